// round 1
// baseline (speedup 1.0000x reference)
#include <cuda_runtime.h>
#include <cuda_bf16.h>
#include <math.h>

// Problem constants
#define B_  4
#define S_  2048
#define E_  512
#define H_  8
#define DK_ 64
#define L_  2
#define NB_ 4
#define FF_ 2048
#define C_  4

// ---------------------------------------------------------------------------
// Scratch (device globals; no allocations anywhere)
// ---------------------------------------------------------------------------
__device__ float g_x  [B_*S_*E_];
__device__ float g_q  [B_*S_*E_];
__device__ float g_k  [B_*S_*E_];
__device__ float g_v  [B_*S_*E_];
__device__ float g_t  [B_*S_*E_];
__device__ float g_ao [B_*S_*E_];
__device__ float g_p  [B_*S_*E_];
__device__ float g_y  [B_*S_*E_];
__device__ float g_ffn[B_*S_*FF_];
__device__ float g_part[16*B_*E_];
__device__ float g_mean[B_*E_];

// ---------------------------------------------------------------------------
// Embedding + sinusoidal positional encoding
// x[b,s,e] = emb[tok[b,s], e] + PE(s, e)
// ---------------------------------------------------------------------------
__global__ void embed_kernel(const int* __restrict__ tok,
                             const float* __restrict__ emb,
                             float* __restrict__ x)
{
    int row = blockIdx.x;              // b*S + s
    int s   = row & (S_-1);
    int t   = tok[row];
    int e   = threadIdx.x * 4;
    float4 ev = *(const float4*)(emb + (long)t*E_ + e);
    float r[4] = {ev.x, ev.y, ev.z, ev.w};
#pragma unroll
    for (int c = 0; c < 4; c++) {
        int ee = e + c;
        int i2 = ee & ~1;  // 2*(ee/2)
        float div = __expf((float)i2 * (-9.210340371976184f / (float)E_));
        float arg = (float)s * div;
        r[c] += (ee & 1) ? cosf(arg) : sinf(arg);
    }
    *(float4*)(x + (long)row*E_ + e) = make_float4(r[0], r[1], r[2], r[3]);
}

// ---------------------------------------------------------------------------
// SGEMM: C[M,N] = A[M,K] @ B[K,N] (+bias)(+relu)
// BM=BN=128, BK=16, 256 threads, 8x8 per thread.
// OUT_HEADT: write C with (b,s,h,d) -> [B,H,S,DK] permutation (QKV proj)
// IN_HEADT : read A from [B,H,S,DK] layout as logical [B*S, E] (Wo proj)
// All shapes here are multiples of the tiles (M=8192, N/K in {512,2048}).
// ---------------------------------------------------------------------------
template<bool OUT_HEADT, bool IN_HEADT, bool BIAS, bool RELU>
__global__ __launch_bounds__(256)
void sgemm_kernel(const float* __restrict__ A, const float* __restrict__ Bm,
                  const float* __restrict__ bias, float* __restrict__ C,
                  int M, int N, int K)
{
    __shared__ float As[16][132];
    __shared__ float Bs[16][128];
    int tid = threadIdx.x;
    int n0 = blockIdx.x * 128;
    int m0 = blockIdx.y * 128;

    int ar = tid >> 2;          // 0..63
    int ak = (tid & 3) * 4;     // 0,4,8,12
    int br = tid >> 5;          // 0..7
    int bn = (tid & 31) * 4;    // 0..124

    int tx = tid & 15;
    int ty = tid >> 4;

    float acc[8][8];
#pragma unroll
    for (int i = 0; i < 8; i++)
#pragma unroll
        for (int j = 0; j < 8; j++) acc[i][j] = 0.f;

    for (int k0 = 0; k0 < K; k0 += 16) {
        // --- load A tile (128x16), store transposed into As[k][m] ---
#pragma unroll
        for (int i = 0; i < 2; i++) {
            int m = m0 + ar + i*64;
            int kk = k0 + ak;
            const float* src;
            if (IN_HEADT) {
                int b = m >> 11;        // /S
                int s = m & (S_-1);
                int h = kk >> 6;        // /DK
                int d = kk & (DK_-1);
                src = A + (((long)(b*H_ + h)*S_ + s)*DK_ + d);
            } else {
                src = A + (long)m*K + kk;
            }
            float4 va = *(const float4*)src;
            As[ak+0][ar + i*64] = va.x;
            As[ak+1][ar + i*64] = va.y;
            As[ak+2][ar + i*64] = va.z;
            As[ak+3][ar + i*64] = va.w;
        }
        // --- load B tile (16x128) ---
#pragma unroll
        for (int i = 0; i < 2; i++) {
            int kk = k0 + br + i*8;
            float4 vb = *(const float4*)(Bm + (long)kk*N + n0 + bn);
            *(float4*)&Bs[br + i*8][bn] = vb;
        }
        __syncthreads();

#pragma unroll
        for (int kk = 0; kk < 16; kk++) {
            float a[8], b[8];
            *(float4*)&a[0] = *(float4*)&As[kk][ty*8];
            *(float4*)&a[4] = *(float4*)&As[kk][ty*8+4];
            *(float4*)&b[0] = *(float4*)&Bs[kk][tx*8];
            *(float4*)&b[4] = *(float4*)&Bs[kk][tx*8+4];
#pragma unroll
            for (int i = 0; i < 8; i++)
#pragma unroll
                for (int j = 0; j < 8; j++)
                    acc[i][j] += a[i]*b[j];
        }
        __syncthreads();
    }

    // --- epilogue ---
#pragma unroll
    for (int i = 0; i < 8; i++) {
        int m = m0 + ty*8 + i;
#pragma unroll
        for (int j = 0; j < 8; j += 4) {
            int n = n0 + tx*8 + j;
            float4 v = make_float4(acc[i][j], acc[i][j+1], acc[i][j+2], acc[i][j+3]);
            if (BIAS) {
                float4 bb = *(const float4*)(bias + n);
                v.x += bb.x; v.y += bb.y; v.z += bb.z; v.w += bb.w;
            }
            if (RELU) {
                v.x = fmaxf(v.x, 0.f); v.y = fmaxf(v.y, 0.f);
                v.z = fmaxf(v.z, 0.f); v.w = fmaxf(v.w, 0.f);
            }
            float* dst;
            if (OUT_HEADT) {
                int b = m >> 11;
                int s = m & (S_-1);
                int h = n >> 6;
                int d = n & (DK_-1);
                dst = C + (((long)(b*H_ + h)*S_ + s)*DK_ + d);
            } else {
                dst = C + (long)m*N + n;
            }
            *(float4*)dst = v;
        }
    }
}

// ---------------------------------------------------------------------------
// Quantum per-head linear: out[b,h,s,:] = in[b,h,s,:] @ W[h] + bias[h]
// W: [H, DK, DK] slice (already offset to (block, layer)); in/out: [B,H,S,DK]
// grid: (S/64, B*H), 256 threads
// ---------------------------------------------------------------------------
__global__ __launch_bounds__(256)
void qapply_kernel(const float* __restrict__ in, const float* __restrict__ W,
                   const float* __restrict__ bias, float* __restrict__ out)
{
    __shared__ float Wsh[64*68];
    __shared__ float Ish[64*68];
    int tid = threadIdx.x;
    int bh = blockIdx.y;
    int h  = bh & (H_-1);
    int s0 = blockIdx.x * 64;

    const float* Wp = W  + h*DK_*DK_;
    const float* Ip = in + ((long)bh*S_ + s0)*DK_;

#pragma unroll
    for (int tt = 0; tt < 4; tt++) {
        int idx = tid + tt*256;       // 0..1023 float4 slots
        int r = idx >> 4;
        int c = (idx & 15) << 2;
        *(float4*)&Wsh[r*68 + c] = *(const float4*)&Wp[r*64 + c];
        *(float4*)&Ish[r*68 + c] = *(const float4*)&Ip[r*64 + c];
    }
    __syncthreads();

    int tx = tid & 15;    // col group (tx*4)
    int ty = tid >> 4;    // row group (ty*4)
    float acc[4][4];
#pragma unroll
    for (int i = 0; i < 4; i++)
#pragma unroll
        for (int j = 0; j < 4; j++) acc[i][j] = 0.f;

#pragma unroll
    for (int d = 0; d < 64; d += 4) {
        float4 aR[4];
#pragma unroll
        for (int r = 0; r < 4; r++)
            aR[r] = *(float4*)&Ish[(ty*4 + r)*68 + d];
#pragma unroll
        for (int dd = 0; dd < 4; dd++) {
            float4 w = *(float4*)&Wsh[(d+dd)*68 + tx*4];
            float av[4] = { dd==0 ? aR[0].x : dd==1 ? aR[0].y : dd==2 ? aR[0].z : aR[0].w,
                            dd==0 ? aR[1].x : dd==1 ? aR[1].y : dd==2 ? aR[1].z : aR[1].w,
                            dd==0 ? aR[2].x : dd==1 ? aR[2].y : dd==2 ? aR[2].z : aR[2].w,
                            dd==0 ? aR[3].x : dd==1 ? aR[3].y : dd==2 ? aR[3].z : aR[3].w };
#pragma unroll
            for (int r = 0; r < 4; r++) {
                acc[r][0] += av[r]*w.x;
                acc[r][1] += av[r]*w.y;
                acc[r][2] += av[r]*w.z;
                acc[r][3] += av[r]*w.w;
            }
        }
    }

    float4 bb = *(const float4*)&bias[h*DK_ + tx*4];
    float* Op = out + ((long)bh*S_ + s0)*DK_;
#pragma unroll
    for (int r = 0; r < 4; r++) {
        float4 v = make_float4(acc[r][0]+bb.x, acc[r][1]+bb.y, acc[r][2]+bb.z, acc[r][3]+bb.w);
        *(float4*)&Op[(ty*4 + r)*64 + tx*4] = v;
    }
}

// ---------------------------------------------------------------------------
// Flash attention (non-causal): O = softmax(Q K^T / 8) V, per (b,h)
// Layouts [B,H,S,DK]. grid (S/128, B*H), 128 threads; each thread = 1 q row.
// Dynamic smem: K tile (64x64) + V tile (64x64) + S scores (128x65)
// ---------------------------------------------------------------------------
#define FLASH_SMEM ((64*64 + 64*64 + 128*65) * 4)

__global__ __launch_bounds__(128)
void flash_attn_kernel(const float* __restrict__ Q, const float* __restrict__ K,
                       const float* __restrict__ V, float* __restrict__ O)
{
    extern __shared__ float sm[];
    float* Ksh = sm;                 // 64*64
    float* Vsh = sm + 4096;          // 64*64
    float* Ssh = sm + 8192;          // 128*65

    int tid = threadIdx.x;
    int bh  = blockIdx.y;
    int q0  = blockIdx.x * 128;

    const float* qp = Q + ((long)bh*S_ + q0 + tid)*DK_;
    float q[64], o[64];
#pragma unroll
    for (int d = 0; d < 64; d += 4) {
        float4 qq = *(const float4*)&qp[d];
        q[d]   = qq.x * 0.125f;
        q[d+1] = qq.y * 0.125f;
        q[d+2] = qq.z * 0.125f;
        q[d+3] = qq.w * 0.125f;
    }
#pragma unroll
    for (int d = 0; d < 64; d++) o[d] = 0.f;

    float m = -1e30f, l = 0.f;

    for (int k0 = 0; k0 < S_; k0 += 64) {
        const float* Kb = K + ((long)bh*S_ + k0)*DK_;
        const float* Vb = V + ((long)bh*S_ + k0)*DK_;
#pragma unroll
        for (int tt = 0; tt < 8; tt++) {
            int idx = tid + tt*128;        // 0..1023 float4 slots
            int r = idx >> 4;
            int c = (idx & 15) << 2;
            *(float4*)&Ksh[r*64 + c] = *(const float4*)&Kb[r*64 + c];
            *(float4*)&Vsh[r*64 + c] = *(const float4*)&Vb[r*64 + c];
        }
        __syncthreads();

        // scores for this tile
        float tmax = -1e30f;
#pragma unroll 2
        for (int j = 0; j < 64; j++) {
            const float* kr = &Ksh[j*64];
            float s = 0.f;
#pragma unroll
            for (int d = 0; d < 64; d += 4) {
                float4 kk = *(const float4*)&kr[d];
                s += q[d]*kk.x + q[d+1]*kk.y + q[d+2]*kk.z + q[d+3]*kk.w;
            }
            Ssh[tid*65 + j] = s;
            tmax = fmaxf(tmax, s);
        }

        float mnew = fmaxf(m, tmax);
        float corr = __expf(m - mnew);
        l *= corr;
#pragma unroll
        for (int d = 0; d < 64; d++) o[d] *= corr;

#pragma unroll 2
        for (int j = 0; j < 64; j++) {
            float p = __expf(Ssh[tid*65 + j] - mnew);
            l += p;
            const float* vr = &Vsh[j*64];
#pragma unroll
            for (int d = 0; d < 64; d += 4) {
                float4 vv = *(const float4*)&vr[d];
                o[d]   += p*vv.x;
                o[d+1] += p*vv.y;
                o[d+2] += p*vv.z;
                o[d+3] += p*vv.w;
            }
        }
        m = mnew;
        __syncthreads();
    }

    float inv = 1.f / l;
    float* op = O + ((long)bh*S_ + q0 + tid)*DK_;
#pragma unroll
    for (int d = 0; d < 64; d += 4) {
        float4 v = make_float4(o[d]*inv, o[d+1]*inv, o[d+2]*inv, o[d+3]*inv);
        *(float4*)&op[d] = v;
    }
}

// ---------------------------------------------------------------------------
// out = LayerNorm(x + r) * g + b   (one block per row of 512)
// ---------------------------------------------------------------------------
__global__ __launch_bounds__(128)
void add_ln_kernel(const float* __restrict__ x, const float* __restrict__ r,
                   const float* __restrict__ g, const float* __restrict__ bta,
                   float* __restrict__ out)
{
    __shared__ float red[4];
    int row = blockIdx.x;
    int tid = threadIdx.x;
    int e = tid * 4;
    const float4 xv = *(const float4*)(x + (long)row*E_ + e);
    const float4 rv = *(const float4*)(r + (long)row*E_ + e);
    float t0 = xv.x + rv.x, t1 = xv.y + rv.y, t2 = xv.z + rv.z, t3 = xv.w + rv.w;

    float s = t0 + t1 + t2 + t3;
#pragma unroll
    for (int off = 16; off; off >>= 1) s += __shfl_xor_sync(0xffffffffu, s, off);
    if ((tid & 31) == 0) red[tid >> 5] = s;
    __syncthreads();
    float mean = (red[0]+red[1]+red[2]+red[3]) * (1.f/E_);
    __syncthreads();

    float d0 = t0-mean, d1 = t1-mean, d2 = t2-mean, d3 = t3-mean;
    float vs = d0*d0 + d1*d1 + d2*d2 + d3*d3;
#pragma unroll
    for (int off = 16; off; off >>= 1) vs += __shfl_xor_sync(0xffffffffu, vs, off);
    if ((tid & 31) == 0) red[tid >> 5] = vs;
    __syncthreads();
    float var = (red[0]+red[1]+red[2]+red[3]) * (1.f/E_);
    float rstd = rsqrtf(var + 1e-5f);

    float4 gg = *(const float4*)(g + e);
    float4 bb = *(const float4*)(bta + e);
    float4 v = make_float4(d0*rstd*gg.x + bb.x, d1*rstd*gg.y + bb.y,
                           d2*rstd*gg.z + bb.z, d3*rstd*gg.w + bb.w);
    *(float4*)(out + (long)row*E_ + e) = v;
}

// ---------------------------------------------------------------------------
// Mean over S (two-stage) + classifier
// ---------------------------------------------------------------------------
__global__ void mean_part_kernel(const float* __restrict__ x, float* __restrict__ part)
{
    int idx = blockIdx.x*256 + threadIdx.x;   // 0..B*E-1
    int b = idx >> 9;
    int e = idx & (E_-1);
    int c = blockIdx.y;                        // 0..15
    const float* p = x + ((long)b*S_ + c*128)*E_ + e;
    float s = 0.f;
#pragma unroll 8
    for (int i = 0; i < 128; i++) s += p[(long)i*E_];
    part[c*(B_*E_) + idx] = s;
}

__global__ void mean_final_kernel(const float* __restrict__ part, float* __restrict__ mean)
{
    int idx = blockIdx.x*256 + threadIdx.x;
    float s = 0.f;
#pragma unroll
    for (int c = 0; c < 16; c++) s += part[c*(B_*E_) + idx];
    mean[idx] = s * (1.f/(float)S_);
}

__global__ __launch_bounds__(128)
void classify_kernel(const float* __restrict__ mean, const float* __restrict__ w,
                     const float* __restrict__ bias, float* __restrict__ out)
{
    __shared__ float red[4];
    int b = blockIdx.x >> 2;
    int c = blockIdx.x & 3;
    int tid = threadIdx.x;
    float s = 0.f;
    for (int e = tid; e < E_; e += 128) s += mean[b*E_ + e] * w[e*C_ + c];
#pragma unroll
    for (int off = 16; off; off >>= 1) s += __shfl_xor_sync(0xffffffffu, s, off);
    if ((tid & 31) == 0) red[tid >> 5] = s;
    __syncthreads();
    if (tid == 0) out[b*C_ + c] = red[0]+red[1]+red[2]+red[3] + bias[c];
}

// ---------------------------------------------------------------------------
// Launch
// ---------------------------------------------------------------------------
extern "C" void kernel_launch(void* const* d_in, const int* in_sizes, int n_in,
                              void* d_out, int out_size)
{
    const int*   tokens = (const int*)  d_in[0];
    const float* emb    = (const float*)d_in[1];
    const float* Wq     = (const float*)d_in[2];
    const float* Wk     = (const float*)d_in[3];
    const float* Wv     = (const float*)d_in[4];
    const float* Wo     = (const float*)d_in[5];
    const float* qh_w   = (const float*)d_in[6];
    const float* qh_b   = (const float*)d_in[7];
    const float* kh_w   = (const float*)d_in[8];
    const float* kh_b   = (const float*)d_in[9];
    const float* vh_w   = (const float*)d_in[10];
    const float* vh_b   = (const float*)d_in[11];
    const float* ln1_g  = (const float*)d_in[12];
    const float* ln1_b  = (const float*)d_in[13];
    const float* ln2_g  = (const float*)d_in[14];
    const float* ln2_b  = (const float*)d_in[15];
    const float* f_w1   = (const float*)d_in[16];
    const float* f_b1   = (const float*)d_in[17];
    const float* f_w2   = (const float*)d_in[18];
    const float* f_b2   = (const float*)d_in[19];
    const float* cls_w  = (const float*)d_in[20];
    const float* cls_b  = (const float*)d_in[21];

    float *x,*q,*k,*v,*t,*ao,*p,*y,*ffn,*part,*mean;
    cudaGetSymbolAddress((void**)&x,    g_x);
    cudaGetSymbolAddress((void**)&q,    g_q);
    cudaGetSymbolAddress((void**)&k,    g_k);
    cudaGetSymbolAddress((void**)&v,    g_v);
    cudaGetSymbolAddress((void**)&t,    g_t);
    cudaGetSymbolAddress((void**)&ao,   g_ao);
    cudaGetSymbolAddress((void**)&p,    g_p);
    cudaGetSymbolAddress((void**)&y,    g_y);
    cudaGetSymbolAddress((void**)&ffn,  g_ffn);
    cudaGetSymbolAddress((void**)&part, g_part);
    cudaGetSymbolAddress((void**)&mean, g_mean);

    cudaFuncSetAttribute((const void*)flash_attn_kernel,
                         cudaFuncAttributeMaxDynamicSharedMemorySize, FLASH_SMEM);

    const int M = B_*S_;               // 8192
    dim3 gProj(E_/128, M/128);         // (4, 64)
    dim3 gFfn1(FF_/128, M/128);        // (16, 64)
    dim3 gQ(S_/64, B_*H_);             // (32, 32)
    dim3 gFlash(S_/128, B_*H_);        // (16, 32)

    embed_kernel<<<M, 128>>>(tokens, emb, x);

    for (int i = 0; i < NB_; i++) {
        const float* Wq_i = Wq + (long)i*E_*E_;
        const float* Wk_i = Wk + (long)i*E_*E_;
        const float* Wv_i = Wv + (long)i*E_*E_;
        const float* Wo_i = Wo + (long)i*E_*E_;

        // Q/K/V projections, fused reshape to [B,H,S,DK]
        sgemm_kernel<true,false,false,false><<<gProj, 256>>>(x, Wq_i, nullptr, q, M, E_, E_);
        sgemm_kernel<true,false,false,false><<<gProj, 256>>>(x, Wk_i, nullptr, k, M, E_, E_);
        sgemm_kernel<true,false,false,false><<<gProj, 256>>>(x, Wv_i, nullptr, v, M, E_, E_);

        // quantum per-head linears, 2 layers each (ping-pong via g_t)
        const int WSZ = H_*DK_*DK_, BSZ = H_*DK_;
        qapply_kernel<<<gQ, 256>>>(q, qh_w + (long)(i*L_+0)*WSZ, qh_b + (long)(i*L_+0)*BSZ, t);
        qapply_kernel<<<gQ, 256>>>(t, qh_w + (long)(i*L_+1)*WSZ, qh_b + (long)(i*L_+1)*BSZ, q);
        qapply_kernel<<<gQ, 256>>>(k, kh_w + (long)(i*L_+0)*WSZ, kh_b + (long)(i*L_+0)*BSZ, t);
        qapply_kernel<<<gQ, 256>>>(t, kh_w + (long)(i*L_+1)*WSZ, kh_b + (long)(i*L_+1)*BSZ, k);
        qapply_kernel<<<gQ, 256>>>(v, vh_w + (long)(i*L_+0)*WSZ, vh_b + (long)(i*L_+0)*BSZ, t);
        qapply_kernel<<<gQ, 256>>>(t, vh_w + (long)(i*L_+1)*WSZ, vh_b + (long)(i*L_+1)*BSZ, v);

        // attention
        flash_attn_kernel<<<gFlash, 128, FLASH_SMEM>>>(q, k, v, ao);

        // output projection (fused un-permute) + residual + LN1
        sgemm_kernel<false,true,false,false><<<gProj, 256>>>(ao, Wo_i, nullptr, p, M, E_, E_);
        add_ln_kernel<<<M, 128>>>(x, p, ln1_g + i*E_, ln1_b + i*E_, y);

        // FFN + residual + LN2
        sgemm_kernel<false,false,true,true ><<<gFfn1, 256>>>(y,   f_w1 + (long)i*E_*FF_, f_b1 + i*FF_, ffn, M, FF_, E_);
        sgemm_kernel<false,false,true,false><<<gProj, 256>>>(ffn, f_w2 + (long)i*FF_*E_, f_b2 + i*E_,  p,   M, E_, FF_);
        add_ln_kernel<<<M, 128>>>(y, p, ln2_g + i*E_, ln2_b + i*E_, x);
    }

    mean_part_kernel<<<dim3((B_*E_)/256, 16), 256>>>(x, part);
    mean_final_kernel<<<(B_*E_)/256, 256>>>(part, mean);
    classify_kernel<<<B_*C_, 128>>>(mean, cls_w, cls_b, (float*)d_out);
}

// round 2
// speedup vs baseline: 3.3650x; 3.3650x over previous
#include <cuda_runtime.h>
#include <cuda_bf16.h>
#include <math.h>

// Problem constants
#define B_  4
#define S_  2048
#define E_  512
#define H_  8
#define DK_ 64
#define L_  2
#define NB_ 4
#define FF_ 2048
#define C_  4

// ---------------------------------------------------------------------------
// Scratch (device globals; no allocations anywhere)
// ---------------------------------------------------------------------------
__device__ float g_x  [B_*S_*E_];
__device__ float g_q  [B_*S_*E_];
__device__ float g_k  [B_*S_*E_];
__device__ float g_v  [B_*S_*E_];
__device__ float g_t  [B_*S_*E_];
__device__ float g_ao [B_*S_*E_];
__device__ float g_p  [B_*S_*E_];
__device__ float g_y  [B_*S_*E_];
__device__ float g_ffn[B_*S_*FF_];
__device__ float g_part[16*B_*E_];
__device__ float g_mean[B_*E_];

// ---------------------------------------------------------------------------
// TF32 helpers
// ---------------------------------------------------------------------------
__device__ __forceinline__ unsigned f2tf(float x) {
    unsigned r;
    asm("cvt.rna.tf32.f32 %0, %1;" : "=r"(r) : "f"(x));
    return r;
}
__device__ __forceinline__ float f2tff(float x) { return __uint_as_float(f2tf(x)); }

// D = A(16x8) * B(8x8) + D, tf32 inputs, f32 accum
__device__ __forceinline__ void mma1688(float* c, const unsigned* a, unsigned b0, unsigned b1) {
    asm volatile(
        "mma.sync.aligned.m16n8k8.row.col.f32.tf32.tf32.f32 "
        "{%0,%1,%2,%3}, {%4,%5,%6,%7}, {%8,%9}, {%0,%1,%2,%3};"
        : "+f"(c[0]), "+f"(c[1]), "+f"(c[2]), "+f"(c[3])
        : "r"(a[0]), "r"(a[1]), "r"(a[2]), "r"(a[3]), "r"(b0), "r"(b1));
}

// ---------------------------------------------------------------------------
// Embedding + sinusoidal positional encoding
// ---------------------------------------------------------------------------
__global__ void embed_kernel(const int* __restrict__ tok,
                             const float* __restrict__ emb,
                             float* __restrict__ x)
{
    int row = blockIdx.x;              // b*S + s
    int s   = row & (S_-1);
    int t   = tok[row];
    int e   = threadIdx.x * 4;
    float4 ev = *(const float4*)(emb + (long)t*E_ + e);
    float r[4] = {ev.x, ev.y, ev.z, ev.w};
#pragma unroll
    for (int c = 0; c < 4; c++) {
        int ee = e + c;
        int i2 = ee & ~1;
        float div = __expf((float)i2 * (-9.210340371976184f / (float)E_));
        float arg = (float)s * div;
        r[c] += (ee & 1) ? cosf(arg) : sinf(arg);
    }
    *(float4*)(x + (long)row*E_ + e) = make_float4(r[0], r[1], r[2], r[3]);
}

// ---------------------------------------------------------------------------
// TF32 tensor-core GEMM: C[M,N] = A[M,K] @ B[K,N] (+bias)(+relu)
// 128x128 tile, BK=32, 256 threads = 8 warps (2x4), warp tile 64x32.
// OUT_HEADT: write C with (b,s,h,d) -> [B,H,S,DK] permutation (QKV proj)
// IN_HEADT : read A from [B,H,S,DK] layout as logical [B*S, E] (Wo proj)
// ---------------------------------------------------------------------------
template<bool OUT_HEADT, bool IN_HEADT, bool BIAS, bool RELU>
__global__ __launch_bounds__(256)
void sgemm_tc(const float* __restrict__ A, const float* __restrict__ Bm,
              const float* __restrict__ bias, float* __restrict__ C,
              int M, int N, int K)
{
    __shared__ float As[32][136];   // [k][m], tf32 bits
    __shared__ float Bs[32][136];   // [k][n], tf32 bits
    int tid  = threadIdx.x;
    int lane = tid & 31;
    int w    = tid >> 5;
    int wm   = w & 1;               // 2 m-groups of 64
    int wn   = w >> 1;              // 4 n-groups of 32
    int n0 = blockIdx.x * 128;
    int m0 = blockIdx.y * 128;
    int r0 = lane >> 2;             // 0..7
    int kc = lane & 3;              // 0..3

    float acc[4][4][4];
#pragma unroll
    for (int i = 0; i < 4; i++)
#pragma unroll
        for (int j = 0; j < 4; j++)
#pragma unroll
            for (int q = 0; q < 4; q++) acc[i][j][q] = 0.f;

    for (int k0 = 0; k0 < K; k0 += 32) {
        // A tile 128x32 -> As[k][m] (transposed), tf32-converted
#pragma unroll
        for (int t = 0; t < 4; t++) {
            int idx = tid + t*256;
            int r = idx >> 3;            // m 0..127
            int k = (idx & 7) * 4;       // k 0,4,..28
            int mg = m0 + r, kk = k0 + k;
            const float* src;
            if (IN_HEADT) {
                int b = mg >> 11, s = mg & (S_-1);
                int h = kk >> 6,  d = kk & (DK_-1);
                src = A + (((long)(b*H_ + h)*S_ + s)*DK_ + d);
            } else {
                src = A + (long)mg*K + kk;
            }
            float4 v = *(const float4*)src;
            As[k+0][r] = f2tff(v.x);
            As[k+1][r] = f2tff(v.y);
            As[k+2][r] = f2tff(v.z);
            As[k+3][r] = f2tff(v.w);
        }
        // B tile 32x128 -> Bs[k][n]
#pragma unroll
        for (int t = 0; t < 4; t++) {
            int idx = tid + t*256;
            int r = idx >> 5;            // k 0..31
            int c = (idx & 31) * 4;      // n
            float4 v = *(const float4*)&Bm[(long)(k0+r)*N + n0 + c];
            float4 cv = make_float4(f2tff(v.x), f2tff(v.y), f2tff(v.z), f2tff(v.w));
            *(float4*)&Bs[r][c] = cv;
        }
        __syncthreads();

#pragma unroll
        for (int ks = 0; ks < 4; ks++) {
            unsigned af[4][4], bf[4][2];
#pragma unroll
            for (int mt = 0; mt < 4; mt++) {
                int mb = wm*64 + mt*16;
                af[mt][0] = __float_as_uint(As[ks*8 + kc    ][mb + r0    ]);
                af[mt][1] = __float_as_uint(As[ks*8 + kc    ][mb + r0 + 8]);
                af[mt][2] = __float_as_uint(As[ks*8 + kc + 4][mb + r0    ]);
                af[mt][3] = __float_as_uint(As[ks*8 + kc + 4][mb + r0 + 8]);
            }
#pragma unroll
            for (int nt = 0; nt < 4; nt++) {
                int nb = wn*32 + nt*8;
                bf[nt][0] = __float_as_uint(Bs[ks*8 + kc    ][nb + r0]);
                bf[nt][1] = __float_as_uint(Bs[ks*8 + kc + 4][nb + r0]);
            }
#pragma unroll
            for (int mt = 0; mt < 4; mt++)
#pragma unroll
                for (int nt = 0; nt < 4; nt++)
                    mma1688(acc[mt][nt], af[mt], bf[nt][0], bf[nt][1]);
        }
        __syncthreads();
    }

    // epilogue
#pragma unroll
    for (int mt = 0; mt < 4; mt++) {
#pragma unroll
        for (int nt = 0; nt < 4; nt++) {
            int c = n0 + wn*32 + nt*8 + kc*2;
            float bx = 0.f, by = 0.f;
            if (BIAS) { bx = bias[c]; by = bias[c+1]; }
#pragma unroll
            for (int half = 0; half < 2; half++) {
                int r = m0 + wm*64 + mt*16 + r0 + half*8;
                float vx = acc[mt][nt][half*2]   + bx;
                float vy = acc[mt][nt][half*2+1] + by;
                if (RELU) { vx = fmaxf(vx, 0.f); vy = fmaxf(vy, 0.f); }
                float* dst;
                if (OUT_HEADT) {
                    int b = r >> 11, s = r & (S_-1);
                    int h = c >> 6,  d = c & (DK_-1);
                    dst = C + (((long)(b*H_ + h)*S_ + s)*DK_ + d);
                } else {
                    dst = C + (long)r*N + c;
                }
                *(float2*)dst = make_float2(vx, vy);
            }
        }
    }
}

// ---------------------------------------------------------------------------
// Quantum per-head linear (fp32 SIMT; tiny fraction of runtime)
// out[b,h,s,:] = in[b,h,s,:] @ W[h] + bias[h]
// ---------------------------------------------------------------------------
__global__ __launch_bounds__(256)
void qapply_kernel(const float* __restrict__ in, const float* __restrict__ W,
                   const float* __restrict__ bias, float* __restrict__ out)
{
    __shared__ float Wsh[64*68];
    __shared__ float Ish[64*68];
    int tid = threadIdx.x;
    int bh = blockIdx.y;
    int h  = bh & (H_-1);
    int s0 = blockIdx.x * 64;

    const float* Wp = W  + h*DK_*DK_;
    const float* Ip = in + ((long)bh*S_ + s0)*DK_;

#pragma unroll
    for (int tt = 0; tt < 4; tt++) {
        int idx = tid + tt*256;
        int r = idx >> 4;
        int c = (idx & 15) << 2;
        *(float4*)&Wsh[r*68 + c] = *(const float4*)&Wp[r*64 + c];
        *(float4*)&Ish[r*68 + c] = *(const float4*)&Ip[r*64 + c];
    }
    __syncthreads();

    int tx = tid & 15;
    int ty = tid >> 4;
    float acc[4][4];
#pragma unroll
    for (int i = 0; i < 4; i++)
#pragma unroll
        for (int j = 0; j < 4; j++) acc[i][j] = 0.f;

#pragma unroll
    for (int d = 0; d < 64; d += 4) {
        float4 aR[4];
#pragma unroll
        for (int r = 0; r < 4; r++)
            aR[r] = *(float4*)&Ish[(ty*4 + r)*68 + d];
#pragma unroll
        for (int dd = 0; dd < 4; dd++) {
            float4 w = *(float4*)&Wsh[(d+dd)*68 + tx*4];
            float av[4] = { dd==0 ? aR[0].x : dd==1 ? aR[0].y : dd==2 ? aR[0].z : aR[0].w,
                            dd==0 ? aR[1].x : dd==1 ? aR[1].y : dd==2 ? aR[1].z : aR[1].w,
                            dd==0 ? aR[2].x : dd==1 ? aR[2].y : dd==2 ? aR[2].z : aR[2].w,
                            dd==0 ? aR[3].x : dd==1 ? aR[3].y : dd==2 ? aR[3].z : aR[3].w };
#pragma unroll
            for (int r = 0; r < 4; r++) {
                acc[r][0] += av[r]*w.x;
                acc[r][1] += av[r]*w.y;
                acc[r][2] += av[r]*w.z;
                acc[r][3] += av[r]*w.w;
            }
        }
    }

    float4 bb = *(const float4*)&bias[h*DK_ + tx*4];
    float* Op = out + ((long)bh*S_ + s0)*DK_;
#pragma unroll
    for (int r = 0; r < 4; r++) {
        float4 v = make_float4(acc[r][0]+bb.x, acc[r][1]+bb.y, acc[r][2]+bb.z, acc[r][3]+bb.w);
        *(float4*)&Op[(ty*4 + r)*64 + tx*4] = v;
    }
}

// ---------------------------------------------------------------------------
// Tensor-core flash attention (non-causal): O = softmax(Q K^T / 8) V
// Layouts [B,H,S,DK]. Block = 128 threads (4 warps), 64 q rows.
// Q held as persistent tf32 A-fragments in registers. K/V/P staged in smem.
// ---------------------------------------------------------------------------
#define KS_ 68
#define VS_ 72
#define PS_ 68
#define FLASH_SMEM ((64*KS_ + 64*VS_ + 64*PS_) * 4)

__global__ __launch_bounds__(128)
void flash_tc_kernel(const float* __restrict__ Q, const float* __restrict__ K,
                     const float* __restrict__ V, float* __restrict__ O)
{
    extern __shared__ float sm[];
    float* Ksh = sm;                     // [64][KS_]
    float* Vsh = sm + 64*KS_;            // [64][VS_]
    float* Psh = sm + 64*KS_ + 64*VS_;   // [64][PS_]

    int tid  = threadIdx.x;
    int lane = tid & 31;
    int w    = tid >> 5;
    int bh = blockIdx.y;
    int q0 = blockIdx.x * 64;
    int r0 = lane >> 2;   // 0..7
    int kc = lane & 3;    // 0..3

    // Q fragments (persistent): warp covers q rows [w*16, w*16+16)
    unsigned qa[8][4];
    const float* qbase = Q + ((long)bh*S_ + q0 + w*16)*DK_;
#pragma unroll
    for (int kt = 0; kt < 8; kt++) {
        qa[kt][0] = f2tf(qbase[(r0    )*DK_ + kt*8 + kc    ] * 0.125f);
        qa[kt][1] = f2tf(qbase[(r0 + 8)*DK_ + kt*8 + kc    ] * 0.125f);
        qa[kt][2] = f2tf(qbase[(r0    )*DK_ + kt*8 + kc + 4] * 0.125f);
        qa[kt][3] = f2tf(qbase[(r0 + 8)*DK_ + kt*8 + kc + 4] * 0.125f);
    }

    float o[8][4];
#pragma unroll
    for (int nt = 0; nt < 8; nt++)
#pragma unroll
        for (int q = 0; q < 4; q++) o[nt][q] = 0.f;
    float m0 = -1e30f, m1 = -1e30f, l0 = 0.f, l1 = 0.f;

    for (int k0 = 0; k0 < S_; k0 += 64) {
        __syncthreads();   // previous iteration's K/V/P consumption done
        const float* Kb = K + ((long)bh*S_ + k0)*DK_;
        const float* Vb = V + ((long)bh*S_ + k0)*DK_;
#pragma unroll
        for (int t = 0; t < 8; t++) {
            int idx = tid + t*128;
            int r = idx >> 4;
            int c = (idx & 15) * 4;
            float4 kv = *(const float4*)&Kb[r*DK_ + c];
            Ksh[r*KS_ + c + 0] = f2tff(kv.x);
            Ksh[r*KS_ + c + 1] = f2tff(kv.y);
            Ksh[r*KS_ + c + 2] = f2tff(kv.z);
            Ksh[r*KS_ + c + 3] = f2tff(kv.w);
            float4 vv = *(const float4*)&Vb[r*DK_ + c];
            Vsh[r*VS_ + c + 0] = f2tff(vv.x);
            Vsh[r*VS_ + c + 1] = f2tff(vv.y);
            Vsh[r*VS_ + c + 2] = f2tff(vv.z);
            Vsh[r*VS_ + c + 3] = f2tff(vv.w);
        }
        __syncthreads();

        // S = Q K^T for this tile: warp computes 16x64
        float sc[8][4];
#pragma unroll
        for (int nt = 0; nt < 8; nt++)
#pragma unroll
            for (int q = 0; q < 4; q++) sc[nt][q] = 0.f;

#pragma unroll
        for (int kt = 0; kt < 8; kt++) {
            unsigned b0[8], b1[8];
#pragma unroll
            for (int nt = 0; nt < 8; nt++) {
                b0[nt] = __float_as_uint(Ksh[(nt*8 + r0)*KS_ + kt*8 + kc    ]);
                b1[nt] = __float_as_uint(Ksh[(nt*8 + r0)*KS_ + kt*8 + kc + 4]);
            }
#pragma unroll
            for (int nt = 0; nt < 8; nt++)
                mma1688(sc[nt], qa[kt], b0[nt], b1[nt]);
        }

        // online softmax on fragments (rows r0 and r0+8)
        float tm0 = -1e30f, tm1 = -1e30f;
#pragma unroll
        for (int nt = 0; nt < 8; nt++) {
            tm0 = fmaxf(tm0, fmaxf(sc[nt][0], sc[nt][1]));
            tm1 = fmaxf(tm1, fmaxf(sc[nt][2], sc[nt][3]));
        }
        tm0 = fmaxf(tm0, __shfl_xor_sync(0xffffffffu, tm0, 1));
        tm0 = fmaxf(tm0, __shfl_xor_sync(0xffffffffu, tm0, 2));
        tm1 = fmaxf(tm1, __shfl_xor_sync(0xffffffffu, tm1, 1));
        tm1 = fmaxf(tm1, __shfl_xor_sync(0xffffffffu, tm1, 2));

        float mn0 = fmaxf(m0, tm0), mn1 = fmaxf(m1, tm1);
        float c0 = __expf(m0 - mn0), c1 = __expf(m1 - mn1);
        l0 *= c0; l1 *= c1;

        float s0 = 0.f, s1 = 0.f;
#pragma unroll
        for (int nt = 0; nt < 8; nt++) {
            float p0 = __expf(sc[nt][0] - mn0);
            float p1 = __expf(sc[nt][1] - mn0);
            float p2 = __expf(sc[nt][2] - mn1);
            float p3 = __expf(sc[nt][3] - mn1);
            s0 += p0 + p1; s1 += p2 + p3;
            o[nt][0] *= c0; o[nt][1] *= c0; o[nt][2] *= c1; o[nt][3] *= c1;
            *(float2*)&Psh[(w*16 + r0    )*PS_ + nt*8 + kc*2] =
                make_float2(f2tff(p0), f2tff(p1));
            *(float2*)&Psh[(w*16 + r0 + 8)*PS_ + nt*8 + kc*2] =
                make_float2(f2tff(p2), f2tff(p3));
        }
        s0 += __shfl_xor_sync(0xffffffffu, s0, 1);
        s0 += __shfl_xor_sync(0xffffffffu, s0, 2);
        s1 += __shfl_xor_sync(0xffffffffu, s1, 1);
        s1 += __shfl_xor_sync(0xffffffffu, s1, 2);
        l0 += s0; l1 += s1;
        m0 = mn0; m1 = mn1;

        __syncwarp();   // P stripe written by this warp, read by this warp

        // O += P V
#pragma unroll
        for (int kt = 0; kt < 8; kt++) {
            unsigned pa[4];
            pa[0] = __float_as_uint(Psh[(w*16 + r0    )*PS_ + kt*8 + kc    ]);
            pa[1] = __float_as_uint(Psh[(w*16 + r0 + 8)*PS_ + kt*8 + kc    ]);
            pa[2] = __float_as_uint(Psh[(w*16 + r0    )*PS_ + kt*8 + kc + 4]);
            pa[3] = __float_as_uint(Psh[(w*16 + r0 + 8)*PS_ + kt*8 + kc + 4]);
            unsigned vb0[8], vb1[8];
#pragma unroll
            for (int nt = 0; nt < 8; nt++) {
                vb0[nt] = __float_as_uint(Vsh[(kt*8 + kc    )*VS_ + nt*8 + r0]);
                vb1[nt] = __float_as_uint(Vsh[(kt*8 + kc + 4)*VS_ + nt*8 + r0]);
            }
#pragma unroll
            for (int nt = 0; nt < 8; nt++)
                mma1688(o[nt], pa, vb0[nt], vb1[nt]);
        }
    }

    float i0 = 1.f / l0, i1 = 1.f / l1;
    float* ob = O + ((long)bh*S_ + q0 + w*16)*DK_;
#pragma unroll
    for (int nt = 0; nt < 8; nt++) {
        *(float2*)&ob[(r0    )*DK_ + nt*8 + kc*2] = make_float2(o[nt][0]*i0, o[nt][1]*i0);
        *(float2*)&ob[(r0 + 8)*DK_ + nt*8 + kc*2] = make_float2(o[nt][2]*i1, o[nt][3]*i1);
    }
}

// ---------------------------------------------------------------------------
// out = LayerNorm(x + r) * g + b
// ---------------------------------------------------------------------------
__global__ __launch_bounds__(128)
void add_ln_kernel(const float* __restrict__ x, const float* __restrict__ r,
                   const float* __restrict__ g, const float* __restrict__ bta,
                   float* __restrict__ out)
{
    __shared__ float red[4];
    int row = blockIdx.x;
    int tid = threadIdx.x;
    int e = tid * 4;
    const float4 xv = *(const float4*)(x + (long)row*E_ + e);
    const float4 rv = *(const float4*)(r + (long)row*E_ + e);
    float t0 = xv.x + rv.x, t1 = xv.y + rv.y, t2 = xv.z + rv.z, t3 = xv.w + rv.w;

    float s = t0 + t1 + t2 + t3;
#pragma unroll
    for (int off = 16; off; off >>= 1) s += __shfl_xor_sync(0xffffffffu, s, off);
    if ((tid & 31) == 0) red[tid >> 5] = s;
    __syncthreads();
    float mean = (red[0]+red[1]+red[2]+red[3]) * (1.f/E_);
    __syncthreads();

    float d0 = t0-mean, d1 = t1-mean, d2 = t2-mean, d3 = t3-mean;
    float vs = d0*d0 + d1*d1 + d2*d2 + d3*d3;
#pragma unroll
    for (int off = 16; off; off >>= 1) vs += __shfl_xor_sync(0xffffffffu, vs, off);
    if ((tid & 31) == 0) red[tid >> 5] = vs;
    __syncthreads();
    float var = (red[0]+red[1]+red[2]+red[3]) * (1.f/E_);
    float rstd = rsqrtf(var + 1e-5f);

    float4 gg = *(const float4*)(g + e);
    float4 bb = *(const float4*)(bta + e);
    float4 v = make_float4(d0*rstd*gg.x + bb.x, d1*rstd*gg.y + bb.y,
                           d2*rstd*gg.z + bb.z, d3*rstd*gg.w + bb.w);
    *(float4*)(out + (long)row*E_ + e) = v;
}

// ---------------------------------------------------------------------------
// Mean over S (two-stage) + classifier
// ---------------------------------------------------------------------------
__global__ void mean_part_kernel(const float* __restrict__ x, float* __restrict__ part)
{
    int idx = blockIdx.x*256 + threadIdx.x;
    int b = idx >> 9;
    int e = idx & (E_-1);
    int c = blockIdx.y;
    const float* p = x + ((long)b*S_ + c*128)*E_ + e;
    float s = 0.f;
#pragma unroll 8
    for (int i = 0; i < 128; i++) s += p[(long)i*E_];
    part[c*(B_*E_) + idx] = s;
}

__global__ void mean_final_kernel(const float* __restrict__ part, float* __restrict__ mean)
{
    int idx = blockIdx.x*256 + threadIdx.x;
    float s = 0.f;
#pragma unroll
    for (int c = 0; c < 16; c++) s += part[c*(B_*E_) + idx];
    mean[idx] = s * (1.f/(float)S_);
}

__global__ __launch_bounds__(128)
void classify_kernel(const float* __restrict__ mean, const float* __restrict__ w,
                     const float* __restrict__ bias, float* __restrict__ out)
{
    __shared__ float red[4];
    int b = blockIdx.x >> 2;
    int c = blockIdx.x & 3;
    int tid = threadIdx.x;
    float s = 0.f;
    for (int e = tid; e < E_; e += 128) s += mean[b*E_ + e] * w[e*C_ + c];
#pragma unroll
    for (int off = 16; off; off >>= 1) s += __shfl_xor_sync(0xffffffffu, s, off);
    if ((tid & 31) == 0) red[tid >> 5] = s;
    __syncthreads();
    if (tid == 0) out[b*C_ + c] = red[0]+red[1]+red[2]+red[3] + bias[c];
}

// ---------------------------------------------------------------------------
// Launch
// ---------------------------------------------------------------------------
extern "C" void kernel_launch(void* const* d_in, const int* in_sizes, int n_in,
                              void* d_out, int out_size)
{
    const int*   tokens = (const int*)  d_in[0];
    const float* emb    = (const float*)d_in[1];
    const float* Wq     = (const float*)d_in[2];
    const float* Wk     = (const float*)d_in[3];
    const float* Wv     = (const float*)d_in[4];
    const float* Wo     = (const float*)d_in[5];
    const float* qh_w   = (const float*)d_in[6];
    const float* qh_b   = (const float*)d_in[7];
    const float* kh_w   = (const float*)d_in[8];
    const float* kh_b   = (const float*)d_in[9];
    const float* vh_w   = (const float*)d_in[10];
    const float* vh_b   = (const float*)d_in[11];
    const float* ln1_g  = (const float*)d_in[12];
    const float* ln1_b  = (const float*)d_in[13];
    const float* ln2_g  = (const float*)d_in[14];
    const float* ln2_b  = (const float*)d_in[15];
    const float* f_w1   = (const float*)d_in[16];
    const float* f_b1   = (const float*)d_in[17];
    const float* f_w2   = (const float*)d_in[18];
    const float* f_b2   = (const float*)d_in[19];
    const float* cls_w  = (const float*)d_in[20];
    const float* cls_b  = (const float*)d_in[21];

    float *x,*q,*k,*v,*t,*ao,*p,*y,*ffn,*part,*mean;
    cudaGetSymbolAddress((void**)&x,    g_x);
    cudaGetSymbolAddress((void**)&q,    g_q);
    cudaGetSymbolAddress((void**)&k,    g_k);
    cudaGetSymbolAddress((void**)&v,    g_v);
    cudaGetSymbolAddress((void**)&t,    g_t);
    cudaGetSymbolAddress((void**)&ao,   g_ao);
    cudaGetSymbolAddress((void**)&p,    g_p);
    cudaGetSymbolAddress((void**)&y,    g_y);
    cudaGetSymbolAddress((void**)&ffn,  g_ffn);
    cudaGetSymbolAddress((void**)&part, g_part);
    cudaGetSymbolAddress((void**)&mean, g_mean);

    cudaFuncSetAttribute((const void*)flash_tc_kernel,
                         cudaFuncAttributeMaxDynamicSharedMemorySize, FLASH_SMEM);

    const int M = B_*S_;               // 8192
    dim3 gProj(E_/128, M/128);         // (4, 64)
    dim3 gFfn1(FF_/128, M/128);        // (16, 64)
    dim3 gQ(S_/64, B_*H_);             // (32, 32)
    dim3 gFlash(S_/64, B_*H_);         // (32, 32)

    embed_kernel<<<M, 128>>>(tokens, emb, x);

    for (int i = 0; i < NB_; i++) {
        const float* Wq_i = Wq + (long)i*E_*E_;
        const float* Wk_i = Wk + (long)i*E_*E_;
        const float* Wv_i = Wv + (long)i*E_*E_;
        const float* Wo_i = Wo + (long)i*E_*E_;

        // Q/K/V projections, fused reshape to [B,H,S,DK]
        sgemm_tc<true,false,false,false><<<gProj, 256>>>(x, Wq_i, nullptr, q, M, E_, E_);
        sgemm_tc<true,false,false,false><<<gProj, 256>>>(x, Wk_i, nullptr, k, M, E_, E_);
        sgemm_tc<true,false,false,false><<<gProj, 256>>>(x, Wv_i, nullptr, v, M, E_, E_);

        // quantum per-head linears, 2 layers each (ping-pong via g_t)
        const int WSZ = H_*DK_*DK_, BSZ = H_*DK_;
        qapply_kernel<<<gQ, 256>>>(q, qh_w + (long)(i*L_+0)*WSZ, qh_b + (long)(i*L_+0)*BSZ, t);
        qapply_kernel<<<gQ, 256>>>(t, qh_w + (long)(i*L_+1)*WSZ, qh_b + (long)(i*L_+1)*BSZ, q);
        qapply_kernel<<<gQ, 256>>>(k, kh_w + (long)(i*L_+0)*WSZ, kh_b + (long)(i*L_+0)*BSZ, t);
        qapply_kernel<<<gQ, 256>>>(t, kh_w + (long)(i*L_+1)*WSZ, kh_b + (long)(i*L_+1)*BSZ, k);
        qapply_kernel<<<gQ, 256>>>(v, vh_w + (long)(i*L_+0)*WSZ, vh_b + (long)(i*L_+0)*BSZ, t);
        qapply_kernel<<<gQ, 256>>>(t, vh_w + (long)(i*L_+1)*WSZ, vh_b + (long)(i*L_+1)*BSZ, v);

        // attention (tensor cores)
        flash_tc_kernel<<<gFlash, 128, FLASH_SMEM>>>(q, k, v, ao);

        // output projection (fused un-permute) + residual + LN1
        sgemm_tc<false,true,false,false><<<gProj, 256>>>(ao, Wo_i, nullptr, p, M, E_, E_);
        add_ln_kernel<<<M, 128>>>(x, p, ln1_g + i*E_, ln1_b + i*E_, y);

        // FFN + residual + LN2
        sgemm_tc<false,false,true,true ><<<gFfn1, 256>>>(y,   f_w1 + (long)i*E_*FF_, f_b1 + i*FF_, ffn, M, FF_, E_);
        sgemm_tc<false,false,true,false><<<gProj, 256>>>(ffn, f_w2 + (long)i*FF_*E_, f_b2 + i*E_,  p,   M, E_, FF_);
        add_ln_kernel<<<M, 128>>>(y, p, ln2_g + i*E_, ln2_b + i*E_, x);
    }

    mean_part_kernel<<<dim3((B_*E_)/256, 16), 256>>>(x, part);
    mean_final_kernel<<<(B_*E_)/256, 256>>>(part, mean);
    classify_kernel<<<B_*C_, 128>>>(mean, cls_w, cls_b, (float*)d_out);
}

// round 4
// speedup vs baseline: 3.4110x; 1.0137x over previous
#include <cuda_runtime.h>
#include <cuda_bf16.h>
#include <math.h>

// Problem constants
#define B_  4
#define S_  2048
#define E_  512
#define H_  8
#define DK_ 64
#define L_  2
#define NB_ 4
#define FF_ 2048
#define C_  4

// ---------------------------------------------------------------------------
// Scratch (device globals; no allocations anywhere)
// ---------------------------------------------------------------------------
__device__ float g_x  [B_*S_*E_];
__device__ float g_q  [B_*S_*E_];
__device__ float g_k  [B_*S_*E_];
__device__ float g_v  [B_*S_*E_];
__device__ float g_ao [B_*S_*E_];
__device__ float g_p  [B_*S_*E_];
__device__ float g_y  [B_*S_*E_];
__device__ float g_ffn[B_*S_*FF_];
__device__ float g_part[16*B_*E_];
__device__ float g_mean[B_*E_];
// folded quantum weights
__device__ float g_wc  [3*NB_*H_*DK_*DK_];   // per-head W1@W2
__device__ float g_weff[3*NB_*E_*E_];        // effective QKV projection weights
__device__ float g_beff[3*NB_*E_];           // effective biases

// ---------------------------------------------------------------------------
// Async-copy helpers
// ---------------------------------------------------------------------------
__device__ __forceinline__ void cpa16(void* dst, const void* src) {
    unsigned d = (unsigned)__cvta_generic_to_shared(dst);
    asm volatile("cp.async.cg.shared.global [%0], [%1], 16;" :: "r"(d), "l"(src));
}
__device__ __forceinline__ void cp_commit() { asm volatile("cp.async.commit_group;"); }
__device__ __forceinline__ void cp_wait0()  { asm volatile("cp.async.wait_group 0;"); }
__device__ __forceinline__ void cp_wait1()  { asm volatile("cp.async.wait_group 1;"); }

// round-to-nearest tf32 conversion (critical: HW mma truncates raw fp32 bits,
// which biases the K-sum; rna keeps error ~1e-4)
__device__ __forceinline__ unsigned f2tf(float x) {
    unsigned r;
    asm("cvt.rna.tf32.f32 %0, %1;" : "=r"(r) : "f"(x));
    return r;
}

// D = A(16x8) * B(8x8) + D, tf32 inputs, f32 accum
__device__ __forceinline__ void mma1688(float* c, const unsigned* a, unsigned b0, unsigned b1) {
    asm volatile(
        "mma.sync.aligned.m16n8k8.row.col.f32.tf32.tf32.f32 "
        "{%0,%1,%2,%3}, {%4,%5,%6,%7}, {%8,%9}, {%0,%1,%2,%3};"
        : "+f"(c[0]), "+f"(c[1]), "+f"(c[2]), "+f"(c[3])
        : "r"(a[0]), "r"(a[1]), "r"(a[2]), "r"(a[3]), "r"(b0), "r"(b1));
}

// ---------------------------------------------------------------------------
// Embedding + sinusoidal positional encoding
// ---------------------------------------------------------------------------
__global__ void embed_kernel(const int* __restrict__ tok,
                             const float* __restrict__ emb,
                             float* __restrict__ x)
{
    int row = blockIdx.x;              // b*S + s
    int s   = row & (S_-1);
    int t   = tok[row];
    int e   = threadIdx.x * 4;
    float4 ev = *(const float4*)(emb + (long)t*E_ + e);
    float r[4] = {ev.x, ev.y, ev.z, ev.w};
#pragma unroll
    for (int c = 0; c < 4; c++) {
        int ee = e + c;
        int i2 = ee & ~1;
        float div = __expf((float)i2 * (-9.210340371976184f / (float)E_));
        float arg = (float)s * div;
        r[c] += (ee & 1) ? cosf(arg) : sinf(arg);
    }
    *(float4*)(x + (long)row*E_ + e) = make_float4(r[0], r[1], r[2], r[3]);
}

// ---------------------------------------------------------------------------
// Fold quantum linears: Wc[h] = W1[h]@W2[h], beff = b1@W2 + b2   (fp32)
// ---------------------------------------------------------------------------
__global__ __launch_bounds__(256)
void qcombine_kernel(const float* __restrict__ qw, const float* __restrict__ qb,
                     const float* __restrict__ kw, const float* __restrict__ kb,
                     const float* __restrict__ vw, const float* __restrict__ vb,
                     float* __restrict__ wc, float* __restrict__ beff)
{
    __shared__ float s1[64*65], s2[64*65];
    int blk = blockIdx.x;
    int t  = blk / (NB_*H_);
    int ih = blk % (NB_*H_);
    int i  = ih / H_, h = ih % H_;
    const float* w = t==0 ? qw : (t==1 ? kw : vw);
    const float* b = t==0 ? qb : (t==1 ? kb : vb);
    const float* W1 = w + ((long)(i*L_+0)*H_ + h)*DK_*DK_;
    const float* W2 = w + ((long)(i*L_+1)*H_ + h)*DK_*DK_;
    const float* b1 = b + ((long)(i*L_+0)*H_ + h)*DK_;
    const float* b2 = b + ((long)(i*L_+1)*H_ + h)*DK_;
    int tid = threadIdx.x;
    for (int idx = tid; idx < 4096; idx += 256) {
        int r = idx >> 6, c = idx & 63;
        s1[r*65+c] = W1[idx];
        s2[r*65+c] = W2[idx];
    }
    __syncthreads();
    float* wcp = wc + (long)blk*DK_*DK_;
    for (int idx = tid; idx < 4096; idx += 256) {
        int r = idx >> 6, c = idx & 63;
        float sum = 0.f;
#pragma unroll 8
        for (int d = 0; d < 64; d++) sum += s1[r*65+d]*s2[d*65+c];
        wcp[idx] = sum;
    }
    if (tid < 64) {
        float sum = b2[tid];
#pragma unroll 8
        for (int d = 0; d < 64; d++) sum += b1[d]*s2[d*65+tid];
        beff[((long)t*NB_ + i)*E_ + h*DK_ + tid] = sum;
    }
}

// ---------------------------------------------------------------------------
// Effective projection weights: Weff[:, h*64+c] = Wq[:, h*64+:] @ Wc[h]  (fp32)
// ---------------------------------------------------------------------------
__global__ __launch_bounds__(256)
void qweff_kernel(const float* __restrict__ Wq, const float* __restrict__ Wk,
                  const float* __restrict__ Wv,
                  const float* __restrict__ wc, float* __restrict__ weff)
{
    __shared__ float wq_s[64*64];
    __shared__ float wc_s[64*64];
    int t = blockIdx.z / NB_, i = blockIdx.z % NB_;
    int h = blockIdx.y;
    int rb = blockIdx.x;
    const float* Wsrc = (t==0 ? Wq : (t==1 ? Wk : Wv)) + (long)i*E_*E_;
    const float* Wcp  = wc + (long)((t*NB_ + i)*H_ + h)*DK_*DK_;
    float* out = weff + (long)(t*NB_ + i)*E_*E_;
    int tid = threadIdx.x;
    for (int idx = tid; idx < 64*64; idx += 256) {
        int r = idx >> 6, c = idx & 63;
        wq_s[idx] = Wsrc[(long)(rb*64 + r)*E_ + h*64 + c];
        wc_s[idx] = Wcp[idx];
    }
    __syncthreads();
    int c = tid & 63, rg = tid >> 6;
    for (int r = rg*16; r < rg*16 + 16; r++) {
        float sum = 0.f;
#pragma unroll 8
        for (int d = 0; d < 64; d++) sum += wq_s[r*64+d]*wc_s[d*64+c];
        out[(long)(rb*64 + r)*E_ + h*64 + c] = sum;
    }
}

// ---------------------------------------------------------------------------
// TF32 tensor-core GEMM with cp.async double buffering.
// C[M,N] = A[M,K] @ B[K,N] (+bias)(+relu)
// 128x128 tile, BK=32, 256 threads = 8 warps (2x4), warp tile 64x32.
// As: [m][k] pad 36; Bs: [k][n] pad 136. rna-tf32 applied at fragment read.
// gridDim.z selects (B,bias,C) triple (fused QKV).
// ---------------------------------------------------------------------------
#define ASTR 36
#define BSTR 136
#define ABUF (128*ASTR)
#define BBUF (32*BSTR)
#define GEMM_SMEM ((ABUF+BBUF)*2*4)           // 71680 bytes

template<bool OUT_HEADT, bool IN_HEADT, bool BIAS, bool RELU>
__global__ __launch_bounds__(256)
void sgemm_cp(const float* __restrict__ A,
              const float* __restrict__ Bp0, const float* __restrict__ Bp1,
              const float* __restrict__ Bp2,
              const float* __restrict__ bi0, const float* __restrict__ bi1,
              const float* __restrict__ bi2,
              float* __restrict__ Cp0, float* __restrict__ Cp1,
              float* __restrict__ Cp2,
              int M, int N, int K)
{
    extern __shared__ float sm[];
    int z = blockIdx.z;
    const float* Bm   = z==0 ? Bp0 : (z==1 ? Bp1 : Bp2);
    const float* bias = z==0 ? bi0 : (z==1 ? bi1 : bi2);
    float*       C    = z==0 ? Cp0 : (z==1 ? Cp1 : Cp2);

    float* Asb[2] = { sm,            sm + ABUF + BBUF };
    float* Bsb[2] = { sm + ABUF,     sm + 2*ABUF + BBUF };

    int tid  = threadIdx.x;
    int lane = tid & 31;
    int w    = tid >> 5;
    int wm   = w & 1;
    int wn   = w >> 1;
    int n0 = blockIdx.x * 128;
    int m0 = blockIdx.y * 128;
    int r0 = lane >> 2;
    int kc = lane & 3;

    int arow = tid >> 3;
    int acol = (tid & 7) * 4;
    int brow = tid >> 5;
    int bcol = (tid & 31) * 4;

    auto copyA = [&](int k0, float* as) {
#pragma unroll
        for (int t = 0; t < 4; t++) {
            int r = arow + t*32;
            int kk = k0 + acol;
            const float* src;
            if (IN_HEADT) {
                int mg = m0 + r;
                int b = mg >> 11, s = mg & (S_-1);
                int h = kk >> 6,  d = kk & (DK_-1);
                src = A + (((long)(b*H_ + h)*S_ + s)*DK_ + d);
            } else {
                src = A + (long)(m0 + r)*K + kk;
            }
            cpa16(as + r*ASTR + acol, src);
        }
    };
    auto copyB = [&](int k0, float* bs) {
#pragma unroll
        for (int t = 0; t < 4; t++) {
            int r = brow + t*8;
            cpa16(bs + r*BSTR + bcol, Bm + (long)(k0 + r)*N + n0 + bcol);
        }
    };

    float acc[4][4][4];
#pragma unroll
    for (int i = 0; i < 4; i++)
#pragma unroll
        for (int j = 0; j < 4; j++)
#pragma unroll
            for (int q = 0; q < 4; q++) acc[i][j][q] = 0.f;

    int niter = K >> 5;
    copyA(0, Asb[0]); copyB(0, Bsb[0]); cp_commit();

    for (int it = 0; it < niter; it++) {
        if (it + 1 < niter) {
            copyA((it+1) << 5, Asb[(it+1)&1]);
            copyB((it+1) << 5, Bsb[(it+1)&1]);
            cp_commit();
            cp_wait1();
        } else {
            cp_wait0();
        }
        __syncthreads();
        const float* as = Asb[it&1];
        const float* bs = Bsb[it&1];
#pragma unroll
        for (int ks = 0; ks < 4; ks++) {
            unsigned af[4][4], bf[4][2];
#pragma unroll
            for (int mt = 0; mt < 4; mt++) {
                int row = wm*64 + mt*16;
                af[mt][0] = f2tf(as[(row + r0    )*ASTR + ks*8 + kc    ]);
                af[mt][1] = f2tf(as[(row + r0 + 8)*ASTR + ks*8 + kc    ]);
                af[mt][2] = f2tf(as[(row + r0    )*ASTR + ks*8 + kc + 4]);
                af[mt][3] = f2tf(as[(row + r0 + 8)*ASTR + ks*8 + kc + 4]);
            }
#pragma unroll
            for (int nt = 0; nt < 4; nt++) {
                int nb = wn*32 + nt*8;
                bf[nt][0] = f2tf(bs[(ks*8 + kc    )*BSTR + nb + r0]);
                bf[nt][1] = f2tf(bs[(ks*8 + kc + 4)*BSTR + nb + r0]);
            }
#pragma unroll
            for (int mt = 0; mt < 4; mt++)
#pragma unroll
                for (int nt = 0; nt < 4; nt++)
                    mma1688(acc[mt][nt], af[mt], bf[nt][0], bf[nt][1]);
        }
        __syncthreads();
    }

    // epilogue
#pragma unroll
    for (int mt = 0; mt < 4; mt++) {
#pragma unroll
        for (int nt = 0; nt < 4; nt++) {
            int c = n0 + wn*32 + nt*8 + kc*2;
            float bx = 0.f, by = 0.f;
            if (BIAS) { bx = bias[c]; by = bias[c+1]; }
#pragma unroll
            for (int half = 0; half < 2; half++) {
                int r = m0 + wm*64 + mt*16 + r0 + half*8;
                float vx = acc[mt][nt][half*2]   + bx;
                float vy = acc[mt][nt][half*2+1] + by;
                if (RELU) { vx = fmaxf(vx, 0.f); vy = fmaxf(vy, 0.f); }
                float* dst;
                if (OUT_HEADT) {
                    int b = r >> 11, s = r & (S_-1);
                    int h = c >> 6,  d = c & (DK_-1);
                    dst = C + (((long)(b*H_ + h)*S_ + s)*DK_ + d);
                } else {
                    dst = C + (long)r*N + c;
                }
                *(float2*)dst = make_float2(vx, vy);
            }
        }
    }
}

// ---------------------------------------------------------------------------
// Tensor-core flash attention with cp.async double-buffered K/V.
// Block = 256 threads (8 warps), 128 q rows; warp = 16 q rows.
// ---------------------------------------------------------------------------
#define KSTR 68
#define VSTR 72
#define PSTR 68
#define KBUF (64*KSTR)
#define VBUF (64*VSTR)
#define FLASH_SMEM (((KBUF+VBUF)*2 + 128*PSTR) * 4)   // 106496 bytes

__global__ __launch_bounds__(256)
void flash_cp(const float* __restrict__ Q, const float* __restrict__ K,
              const float* __restrict__ V, float* __restrict__ O)
{
    extern __shared__ float sm[];
    float* Ksb[2] = { sm,                      sm + KBUF + VBUF };
    float* Vsb[2] = { sm + KBUF,               sm + 2*KBUF + VBUF };
    float* Psh    = sm + 2*(KBUF + VBUF);      // [128][PSTR]

    int tid  = threadIdx.x;
    int lane = tid & 31;
    int w    = tid >> 5;
    int bh = blockIdx.y;
    int q0 = blockIdx.x * 128;
    int r0 = lane >> 2;
    int kc = lane & 3;

    auto copyKV = [&](int k0, float* ks, float* vs) {
        const float* Kb = K + ((long)bh*S_ + k0)*DK_;
        const float* Vb = V + ((long)bh*S_ + k0)*DK_;
#pragma unroll
        for (int t = 0; t < 4; t++) {
            int idx = tid + t*256;
            int r = idx >> 4;
            int c = (idx & 15) * 4;
            cpa16(ks + r*KSTR + c, Kb + r*DK_ + c);
            cpa16(vs + r*VSTR + c, Vb + r*DK_ + c);
        }
    };

    // persistent Q fragments (scaled by 1/8), rna-tf32
    unsigned qa[8][4];
    const float* qbase = Q + ((long)bh*S_ + q0 + w*16)*DK_;
#pragma unroll
    for (int kt = 0; kt < 8; kt++) {
        qa[kt][0] = f2tf(qbase[(r0    )*DK_ + kt*8 + kc    ] * 0.125f);
        qa[kt][1] = f2tf(qbase[(r0 + 8)*DK_ + kt*8 + kc    ] * 0.125f);
        qa[kt][2] = f2tf(qbase[(r0    )*DK_ + kt*8 + kc + 4] * 0.125f);
        qa[kt][3] = f2tf(qbase[(r0 + 8)*DK_ + kt*8 + kc + 4] * 0.125f);
    }

    float o[8][4];
#pragma unroll
    for (int nt = 0; nt < 8; nt++)
#pragma unroll
        for (int q = 0; q < 4; q++) o[nt][q] = 0.f;
    float m0 = -1e30f, m1 = -1e30f, l0 = 0.f, l1 = 0.f;

    const int niter = S_ / 64;
    copyKV(0, Ksb[0], Vsb[0]); cp_commit();

    for (int it = 0; it < niter; it++) {
        if (it + 1 < niter) {
            copyKV((it+1)*64, Ksb[(it+1)&1], Vsb[(it+1)&1]);
            cp_commit();
            cp_wait1();
        } else {
            cp_wait0();
        }
        __syncthreads();
        const float* ks = Ksb[it&1];
        const float* vs = Vsb[it&1];

        // S = Q K^T for this 128x64 tile (warp: 16x64)
        float sc[8][4];
#pragma unroll
        for (int nt = 0; nt < 8; nt++)
#pragma unroll
            for (int q = 0; q < 4; q++) sc[nt][q] = 0.f;

#pragma unroll
        for (int kt = 0; kt < 8; kt++) {
            unsigned b0[8], b1[8];
#pragma unroll
            for (int nt = 0; nt < 8; nt++) {
                b0[nt] = f2tf(ks[(nt*8 + r0)*KSTR + kt*8 + kc    ]);
                b1[nt] = f2tf(ks[(nt*8 + r0)*KSTR + kt*8 + kc + 4]);
            }
#pragma unroll
            for (int nt = 0; nt < 8; nt++)
                mma1688(sc[nt], qa[kt], b0[nt], b1[nt]);
        }

        // online softmax (rows r0 and r0+8)
        float tm0 = -1e30f, tm1 = -1e30f;
#pragma unroll
        for (int nt = 0; nt < 8; nt++) {
            tm0 = fmaxf(tm0, fmaxf(sc[nt][0], sc[nt][1]));
            tm1 = fmaxf(tm1, fmaxf(sc[nt][2], sc[nt][3]));
        }
        tm0 = fmaxf(tm0, __shfl_xor_sync(0xffffffffu, tm0, 1));
        tm0 = fmaxf(tm0, __shfl_xor_sync(0xffffffffu, tm0, 2));
        tm1 = fmaxf(tm1, __shfl_xor_sync(0xffffffffu, tm1, 1));
        tm1 = fmaxf(tm1, __shfl_xor_sync(0xffffffffu, tm1, 2));

        float mn0 = fmaxf(m0, tm0), mn1 = fmaxf(m1, tm1);
        float c0 = __expf(m0 - mn0), c1 = __expf(m1 - mn1);
        l0 *= c0; l1 *= c1;

        float s0 = 0.f, s1 = 0.f;
#pragma unroll
        for (int nt = 0; nt < 8; nt++) {
            float p0 = __expf(sc[nt][0] - mn0);
            float p1 = __expf(sc[nt][1] - mn0);
            float p2 = __expf(sc[nt][2] - mn1);
            float p3 = __expf(sc[nt][3] - mn1);
            s0 += p0 + p1; s1 += p2 + p3;
            o[nt][0] *= c0; o[nt][1] *= c0; o[nt][2] *= c1; o[nt][3] *= c1;
            *(float2*)&Psh[(w*16 + r0    )*PSTR + nt*8 + kc*2] =
                make_float2(__uint_as_float(f2tf(p0)), __uint_as_float(f2tf(p1)));
            *(float2*)&Psh[(w*16 + r0 + 8)*PSTR + nt*8 + kc*2] =
                make_float2(__uint_as_float(f2tf(p2)), __uint_as_float(f2tf(p3)));
        }
        s0 += __shfl_xor_sync(0xffffffffu, s0, 1);
        s0 += __shfl_xor_sync(0xffffffffu, s0, 2);
        s1 += __shfl_xor_sync(0xffffffffu, s1, 1);
        s1 += __shfl_xor_sync(0xffffffffu, s1, 2);
        l0 += s0; l1 += s1;
        m0 = mn0; m1 = mn1;

        __syncwarp();   // P stripe is warp-private

        // O += P V
#pragma unroll
        for (int kt = 0; kt < 8; kt++) {
            unsigned pa[4];
            pa[0] = __float_as_uint(Psh[(w*16 + r0    )*PSTR + kt*8 + kc    ]);
            pa[1] = __float_as_uint(Psh[(w*16 + r0 + 8)*PSTR + kt*8 + kc    ]);
            pa[2] = __float_as_uint(Psh[(w*16 + r0    )*PSTR + kt*8 + kc + 4]);
            pa[3] = __float_as_uint(Psh[(w*16 + r0 + 8)*PSTR + kt*8 + kc + 4]);
            unsigned vb0[8], vb1[8];
#pragma unroll
            for (int nt = 0; nt < 8; nt++) {
                vb0[nt] = f2tf(vs[(kt*8 + kc    )*VSTR + nt*8 + r0]);
                vb1[nt] = f2tf(vs[(kt*8 + kc + 4)*VSTR + nt*8 + r0]);
            }
#pragma unroll
            for (int nt = 0; nt < 8; nt++)
                mma1688(o[nt], pa, vb0[nt], vb1[nt]);
        }
        __syncthreads();
    }

    float i0 = 1.f / l0, i1 = 1.f / l1;
    float* ob = O + ((long)bh*S_ + q0 + w*16)*DK_;
#pragma unroll
    for (int nt = 0; nt < 8; nt++) {
        *(float2*)&ob[(r0    )*DK_ + nt*8 + kc*2] = make_float2(o[nt][0]*i0, o[nt][1]*i0);
        *(float2*)&ob[(r0 + 8)*DK_ + nt*8 + kc*2] = make_float2(o[nt][2]*i1, o[nt][3]*i1);
    }
}

// ---------------------------------------------------------------------------
// out = LayerNorm(x + r) * g + b
// ---------------------------------------------------------------------------
__global__ __launch_bounds__(128)
void add_ln_kernel(const float* __restrict__ x, const float* __restrict__ r,
                   const float* __restrict__ g, const float* __restrict__ bta,
                   float* __restrict__ out)
{
    __shared__ float red[4];
    int row = blockIdx.x;
    int tid = threadIdx.x;
    int e = tid * 4;
    const float4 xv = *(const float4*)(x + (long)row*E_ + e);
    const float4 rv = *(const float4*)(r + (long)row*E_ + e);
    float t0 = xv.x + rv.x, t1 = xv.y + rv.y, t2 = xv.z + rv.z, t3 = xv.w + rv.w;

    float s = t0 + t1 + t2 + t3;
#pragma unroll
    for (int off = 16; off; off >>= 1) s += __shfl_xor_sync(0xffffffffu, s, off);
    if ((tid & 31) == 0) red[tid >> 5] = s;
    __syncthreads();
    float mean = (red[0]+red[1]+red[2]+red[3]) * (1.f/E_);
    __syncthreads();

    float d0 = t0-mean, d1 = t1-mean, d2 = t2-mean, d3 = t3-mean;
    float vs = d0*d0 + d1*d1 + d2*d2 + d3*d3;
#pragma unroll
    for (int off = 16; off; off >>= 1) vs += __shfl_xor_sync(0xffffffffu, vs, off);
    if ((tid & 31) == 0) red[tid >> 5] = vs;
    __syncthreads();
    float var = (red[0]+red[1]+red[2]+red[3]) * (1.f/E_);
    float rstd = rsqrtf(var + 1e-5f);

    float4 gg = *(const float4*)(g + e);
    float4 bb = *(const float4*)(bta + e);
    float4 v = make_float4(d0*rstd*gg.x + bb.x, d1*rstd*gg.y + bb.y,
                           d2*rstd*gg.z + bb.z, d3*rstd*gg.w + bb.w);
    *(float4*)(out + (long)row*E_ + e) = v;
}

// ---------------------------------------------------------------------------
// Mean over S (two-stage) + classifier
// ---------------------------------------------------------------------------
__global__ void mean_part_kernel(const float* __restrict__ x, float* __restrict__ part)
{
    int idx = blockIdx.x*256 + threadIdx.x;
    int b = idx >> 9;
    int e = idx & (E_-1);
    int c = blockIdx.y;
    const float* p = x + ((long)b*S_ + c*128)*E_ + e;
    float s = 0.f;
#pragma unroll 8
    for (int i = 0; i < 128; i++) s += p[(long)i*E_];
    part[c*(B_*E_) + idx] = s;
}

__global__ void mean_final_kernel(const float* __restrict__ part, float* __restrict__ mean)
{
    int idx = blockIdx.x*256 + threadIdx.x;
    float s = 0.f;
#pragma unroll
    for (int c = 0; c < 16; c++) s += part[c*(B_*E_) + idx];
    mean[idx] = s * (1.f/(float)S_);
}

__global__ __launch_bounds__(128)
void classify_kernel(const float* __restrict__ mean, const float* __restrict__ w,
                     const float* __restrict__ bias, float* __restrict__ out)
{
    __shared__ float red[4];
    int b = blockIdx.x >> 2;
    int c = blockIdx.x & 3;
    int tid = threadIdx.x;
    float s = 0.f;
    for (int e = tid; e < E_; e += 128) s += mean[b*E_ + e] * w[e*C_ + c];
#pragma unroll
    for (int off = 16; off; off >>= 1) s += __shfl_xor_sync(0xffffffffu, s, off);
    if ((tid & 31) == 0) red[tid >> 5] = s;
    __syncthreads();
    if (tid == 0) out[b*C_ + c] = red[0]+red[1]+red[2]+red[3] + bias[c];
}

// ---------------------------------------------------------------------------
// Launch
// ---------------------------------------------------------------------------
extern "C" void kernel_launch(void* const* d_in, const int* in_sizes, int n_in,
                              void* d_out, int out_size)
{
    const int*   tokens = (const int*)  d_in[0];
    const float* emb    = (const float*)d_in[1];
    const float* Wq     = (const float*)d_in[2];
    const float* Wk     = (const float*)d_in[3];
    const float* Wv     = (const float*)d_in[4];
    const float* Wo     = (const float*)d_in[5];
    const float* qh_w   = (const float*)d_in[6];
    const float* qh_b   = (const float*)d_in[7];
    const float* kh_w   = (const float*)d_in[8];
    const float* kh_b   = (const float*)d_in[9];
    const float* vh_w   = (const float*)d_in[10];
    const float* vh_b   = (const float*)d_in[11];
    const float* ln1_g  = (const float*)d_in[12];
    const float* ln1_b  = (const float*)d_in[13];
    const float* ln2_g  = (const float*)d_in[14];
    const float* ln2_b  = (const float*)d_in[15];
    const float* f_w1   = (const float*)d_in[16];
    const float* f_b1   = (const float*)d_in[17];
    const float* f_w2   = (const float*)d_in[18];
    const float* f_b2   = (const float*)d_in[19];
    const float* cls_w  = (const float*)d_in[20];
    const float* cls_b  = (const float*)d_in[21];

    float *x,*q,*k,*v,*ao,*p,*y,*ffn,*part,*mean,*wc,*weff,*beff;
    cudaGetSymbolAddress((void**)&x,    g_x);
    cudaGetSymbolAddress((void**)&q,    g_q);
    cudaGetSymbolAddress((void**)&k,    g_k);
    cudaGetSymbolAddress((void**)&v,    g_v);
    cudaGetSymbolAddress((void**)&ao,   g_ao);
    cudaGetSymbolAddress((void**)&p,    g_p);
    cudaGetSymbolAddress((void**)&y,    g_y);
    cudaGetSymbolAddress((void**)&ffn,  g_ffn);
    cudaGetSymbolAddress((void**)&part, g_part);
    cudaGetSymbolAddress((void**)&mean, g_mean);
    cudaGetSymbolAddress((void**)&wc,   g_wc);
    cudaGetSymbolAddress((void**)&weff, g_weff);
    cudaGetSymbolAddress((void**)&beff, g_beff);

    cudaFuncSetAttribute((const void*)flash_cp,
                         cudaFuncAttributeMaxDynamicSharedMemorySize, FLASH_SMEM);
    cudaFuncSetAttribute((const void*)sgemm_cp<true,false,true,false>,
                         cudaFuncAttributeMaxDynamicSharedMemorySize, GEMM_SMEM);
    cudaFuncSetAttribute((const void*)sgemm_cp<false,true,false,false>,
                         cudaFuncAttributeMaxDynamicSharedMemorySize, GEMM_SMEM);
    cudaFuncSetAttribute((const void*)sgemm_cp<false,false,true,true>,
                         cudaFuncAttributeMaxDynamicSharedMemorySize, GEMM_SMEM);
    cudaFuncSetAttribute((const void*)sgemm_cp<false,false,true,false>,
                         cudaFuncAttributeMaxDynamicSharedMemorySize, GEMM_SMEM);

    const int M = B_*S_;               // 8192
    const long ESQ = (long)E_*E_;
    dim3 gQKV(E_/128, M/128, 3);       // (4, 64, 3)
    dim3 gProj(E_/128, M/128, 1);      // (4, 64)
    dim3 gFfn1(FF_/128, M/128, 1);     // (16, 64)
    dim3 gFlash(S_/128, B_*H_);        // (16, 32)

    embed_kernel<<<M, 128>>>(tokens, emb, x);
    qcombine_kernel<<<3*NB_*H_, 256>>>(qh_w, qh_b, kh_w, kh_b, vh_w, vh_b, wc, beff);
    qweff_kernel<<<dim3(8, H_, 3*NB_), 256>>>(Wq, Wk, Wv, wc, weff);

    for (int i = 0; i < NB_; i++) {
        const float* Wo_i = Wo + (long)i*ESQ;

        // fused QKV projection (quantum layers folded in), reshape to [B,H,S,DK]
        sgemm_cp<true,false,true,false><<<gQKV, 256, GEMM_SMEM>>>(
            x,
            weff + (0*NB_ + i)*ESQ, weff + (1*NB_ + i)*ESQ, weff + (2*NB_ + i)*ESQ,
            beff + (0*NB_ + i)*E_,  beff + (1*NB_ + i)*E_,  beff + (2*NB_ + i)*E_,
            q, k, v, M, E_, E_);

        // attention (tensor cores)
        flash_cp<<<gFlash, 256, FLASH_SMEM>>>(q, k, v, ao);

        // output projection (fused un-permute) + residual + LN1
        sgemm_cp<false,true,false,false><<<gProj, 256, GEMM_SMEM>>>(
            ao, Wo_i, Wo_i, Wo_i, nullptr, nullptr, nullptr, p, p, p, M, E_, E_);
        add_ln_kernel<<<M, 128>>>(x, p, ln1_g + i*E_, ln1_b + i*E_, y);

        // FFN + residual + LN2
        sgemm_cp<false,false,true,true><<<gFfn1, 256, GEMM_SMEM>>>(
            y, f_w1 + (long)i*E_*FF_, f_w1 + (long)i*E_*FF_, f_w1 + (long)i*E_*FF_,
            f_b1 + i*FF_, f_b1 + i*FF_, f_b1 + i*FF_,
            ffn, ffn, ffn, M, FF_, E_);
        sgemm_cp<false,false,true,false><<<gProj, 256, GEMM_SMEM>>>(
            ffn, f_w2 + (long)i*FF_*E_, f_w2 + (long)i*FF_*E_, f_w2 + (long)i*FF_*E_,
            f_b2 + i*E_, f_b2 + i*E_, f_b2 + i*E_,
            p, p, p, M, E_, FF_);
        add_ln_kernel<<<M, 128>>>(y, p, ln2_g + i*E_, ln2_b + i*E_, x);
    }

    mean_part_kernel<<<dim3((B_*E_)/256, 16), 256>>>(x, part);
    mean_final_kernel<<<(B_*E_)/256, 256>>>(part, mean);
    classify_kernel<<<B_*C_, 128>>>(mean, cls_w, cls_b, (float*)d_out);
}

// round 5
// speedup vs baseline: 4.1572x; 1.2187x over previous
#include <cuda_runtime.h>
#include <cuda_bf16.h>
#include <math.h>

// Problem constants
#define B_  4
#define S_  2048
#define E_  512
#define H_  8
#define DK_ 64
#define L_  2
#define NB_ 4
#define FF_ 2048
#define C_  4

// ---------------------------------------------------------------------------
// Scratch (device globals; no allocations anywhere)
// ---------------------------------------------------------------------------
__device__ float g_x  [B_*S_*E_];
__device__ float g_q  [B_*S_*E_];
__device__ float g_k  [B_*S_*E_];
__device__ float g_v  [B_*S_*E_];
__device__ float g_ao [B_*S_*E_];
__device__ float g_p  [B_*S_*E_];
__device__ float g_y  [B_*S_*E_];
__device__ float g_ffn[B_*S_*FF_];
__device__ float g_part[16*B_*E_];
__device__ float g_mean[B_*E_];
// folded quantum weights + pre-rounded (tf32) weights
__device__ float g_wc  [3*NB_*H_*DK_*DK_];   // per-head W1@W2
__device__ float g_weff[3*NB_*E_*E_];        // effective QKV weights (tf32-rounded)
__device__ float g_beff[3*NB_*E_];           // effective biases (fp32)
__device__ float g_w1r [NB_*E_*FF_];         // tf32-rounded f_w1
__device__ float g_w2r [NB_*FF_*E_];         // tf32-rounded f_w2
__device__ float g_wor [NB_*E_*E_];          // tf32-rounded Wo

// ---------------------------------------------------------------------------
// Helpers
// ---------------------------------------------------------------------------
__device__ __forceinline__ void cpa16(void* dst, const void* src) {
    unsigned d = (unsigned)__cvta_generic_to_shared(dst);
    asm volatile("cp.async.cg.shared.global [%0], [%1], 16;" :: "r"(d), "l"(src));
}
__device__ __forceinline__ void cp_commit() { asm volatile("cp.async.commit_group;"); }
__device__ __forceinline__ void cp_wait0()  { asm volatile("cp.async.wait_group 0;"); }
__device__ __forceinline__ void cp_wait1()  { asm volatile("cp.async.wait_group 1;"); }

// round-to-nearest tf32 (HW mma truncates raw bits; rna at the PRODUCER keeps
// mainloops cvt-free while matching read-side rna numerics exactly)
__device__ __forceinline__ unsigned f2tf(float x) {
    unsigned r;
    asm("cvt.rna.tf32.f32 %0, %1;" : "=r"(r) : "f"(x));
    return r;
}
__device__ __forceinline__ float f2tff(float x) { return __uint_as_float(f2tf(x)); }

// D = A(16x8) * B(8x8) + D, tf32 inputs, f32 accum
__device__ __forceinline__ void mma1688(float* c, const unsigned* a, unsigned b0, unsigned b1) {
    asm volatile(
        "mma.sync.aligned.m16n8k8.row.col.f32.tf32.tf32.f32 "
        "{%0,%1,%2,%3}, {%4,%5,%6,%7}, {%8,%9}, {%0,%1,%2,%3};"
        : "+f"(c[0]), "+f"(c[1]), "+f"(c[2]), "+f"(c[3])
        : "r"(a[0]), "r"(a[1]), "r"(a[2]), "r"(a[3]), "r"(b0), "r"(b1));
}

// ---------------------------------------------------------------------------
// Elementwise tf32 rounding (weights precompute)
// ---------------------------------------------------------------------------
__global__ void round_tf32_kernel(const float* __restrict__ in, float* __restrict__ out, int n4)
{
    int i = blockIdx.x*256 + threadIdx.x;
    if (i < n4) {
        float4 v = ((const float4*)in)[i];
        ((float4*)out)[i] = make_float4(f2tff(v.x), f2tff(v.y), f2tff(v.z), f2tff(v.w));
    }
}

// ---------------------------------------------------------------------------
// Embedding + sinusoidal positional encoding
// ---------------------------------------------------------------------------
__global__ void embed_kernel(const int* __restrict__ tok,
                             const float* __restrict__ emb,
                             float* __restrict__ x)
{
    int row = blockIdx.x;              // b*S + s
    int s   = row & (S_-1);
    int t   = tok[row];
    int e   = threadIdx.x * 4;
    float4 ev = *(const float4*)(emb + (long)t*E_ + e);
    float r[4] = {ev.x, ev.y, ev.z, ev.w};
#pragma unroll
    for (int c = 0; c < 4; c++) {
        int ee = e + c;
        int i2 = ee & ~1;
        float div = __expf((float)i2 * (-9.210340371976184f / (float)E_));
        float arg = (float)s * div;
        r[c] += (ee & 1) ? cosf(arg) : sinf(arg);
    }
    *(float4*)(x + (long)row*E_ + e) = make_float4(r[0], r[1], r[2], r[3]);
}

// ---------------------------------------------------------------------------
// Fold quantum linears: Wc[h] = W1[h]@W2[h], beff = b1@W2 + b2   (fp32)
// ---------------------------------------------------------------------------
__global__ __launch_bounds__(256)
void qcombine_kernel(const float* __restrict__ qw, const float* __restrict__ qb,
                     const float* __restrict__ kw, const float* __restrict__ kb,
                     const float* __restrict__ vw, const float* __restrict__ vb,
                     float* __restrict__ wc, float* __restrict__ beff)
{
    __shared__ float s1[64*65], s2[64*65];
    int blk = blockIdx.x;
    int t  = blk / (NB_*H_);
    int ih = blk % (NB_*H_);
    int i  = ih / H_, h = ih % H_;
    const float* w = t==0 ? qw : (t==1 ? kw : vw);
    const float* b = t==0 ? qb : (t==1 ? kb : vb);
    const float* W1 = w + ((long)(i*L_+0)*H_ + h)*DK_*DK_;
    const float* W2 = w + ((long)(i*L_+1)*H_ + h)*DK_*DK_;
    const float* b1 = b + ((long)(i*L_+0)*H_ + h)*DK_;
    const float* b2 = b + ((long)(i*L_+1)*H_ + h)*DK_;
    int tid = threadIdx.x;
    for (int idx = tid; idx < 4096; idx += 256) {
        int r = idx >> 6, c = idx & 63;
        s1[r*65+c] = W1[idx];
        s2[r*65+c] = W2[idx];
    }
    __syncthreads();
    float* wcp = wc + (long)blk*DK_*DK_;
    for (int idx = tid; idx < 4096; idx += 256) {
        int r = idx >> 6, c = idx & 63;
        float sum = 0.f;
#pragma unroll 8
        for (int d = 0; d < 64; d++) sum += s1[r*65+d]*s2[d*65+c];
        wcp[idx] = sum;
    }
    if (tid < 64) {
        float sum = b2[tid];
#pragma unroll 8
        for (int d = 0; d < 64; d++) sum += b1[d]*s2[d*65+tid];
        beff[((long)t*NB_ + i)*E_ + h*DK_ + tid] = sum;
    }
}

// ---------------------------------------------------------------------------
// Effective projection weights (tf32-rounded at write):
// Weff[:, h*64+c] = Wq[:, h*64+:] @ Wc[h]
// ---------------------------------------------------------------------------
__global__ __launch_bounds__(256)
void qweff_kernel(const float* __restrict__ Wq, const float* __restrict__ Wk,
                  const float* __restrict__ Wv,
                  const float* __restrict__ wc, float* __restrict__ weff)
{
    __shared__ float wq_s[64*64];
    __shared__ float wc_s[64*64];
    int t = blockIdx.z / NB_, i = blockIdx.z % NB_;
    int h = blockIdx.y;
    int rb = blockIdx.x;
    const float* Wsrc = (t==0 ? Wq : (t==1 ? Wk : Wv)) + (long)i*E_*E_;
    const float* Wcp  = wc + (long)((t*NB_ + i)*H_ + h)*DK_*DK_;
    float* out = weff + (long)(t*NB_ + i)*E_*E_;
    int tid = threadIdx.x;
    for (int idx = tid; idx < 64*64; idx += 256) {
        int r = idx >> 6, c = idx & 63;
        wq_s[idx] = Wsrc[(long)(rb*64 + r)*E_ + h*64 + c];
        wc_s[idx] = Wcp[idx];
    }
    __syncthreads();
    int c = tid & 63, rg = tid >> 6;
    for (int r = rg*16; r < rg*16 + 16; r++) {
        float sum = 0.f;
#pragma unroll 8
        for (int d = 0; d < 64; d++) sum += wq_s[r*64+d]*wc_s[d*64+c];
        out[(long)(rb*64 + r)*E_ + h*64 + c] = f2tff(sum);
    }
}

// ---------------------------------------------------------------------------
// TF32 tensor-core GEMM, cp.async double-buffered, 2 CTAs/SM.
// B (weights) pre-rounded; A rounded at read only when CVT_A (residual-stream
// inputs x/y). Output rounded when CVT_OUT (tensors consumed by later mma).
// ---------------------------------------------------------------------------
#define ASTR 36
#define BSTR 136
#define ABUF (128*ASTR)
#define BBUF (32*BSTR)
#define GEMM_SMEM ((ABUF+BBUF)*2*4)           // 71680 bytes

template<bool OUT_HEADT, bool IN_HEADT, bool BIAS, bool RELU, bool CVT_A, bool CVT_OUT>
__global__ __launch_bounds__(256, 2)
void sgemm_cp(const float* __restrict__ A,
              const float* __restrict__ Bp0, const float* __restrict__ Bp1,
              const float* __restrict__ Bp2,
              const float* __restrict__ bi0, const float* __restrict__ bi1,
              const float* __restrict__ bi2,
              float* __restrict__ Cp0, float* __restrict__ Cp1,
              float* __restrict__ Cp2,
              int M, int N, int K)
{
    extern __shared__ float sm[];
    int z = blockIdx.z;
    const float* Bm   = z==0 ? Bp0 : (z==1 ? Bp1 : Bp2);
    const float* bias = z==0 ? bi0 : (z==1 ? bi1 : bi2);
    float*       C    = z==0 ? Cp0 : (z==1 ? Cp1 : Cp2);

    float* Asb[2] = { sm,            sm + ABUF + BBUF };
    float* Bsb[2] = { sm + ABUF,     sm + 2*ABUF + BBUF };

    int tid  = threadIdx.x;
    int lane = tid & 31;
    int w    = tid >> 5;
    int wm   = w & 1;
    int wn   = w >> 1;
    int n0 = blockIdx.x * 128;
    int m0 = blockIdx.y * 128;
    int r0 = lane >> 2;
    int kc = lane & 3;

    int arow = tid >> 3;
    int acol = (tid & 7) * 4;
    int brow = tid >> 5;
    int bcol = (tid & 31) * 4;

    auto copyA = [&](int k0, float* as) {
#pragma unroll
        for (int t = 0; t < 4; t++) {
            int r = arow + t*32;
            int kk = k0 + acol;
            const float* src;
            if (IN_HEADT) {
                int mg = m0 + r;
                int b = mg >> 11, s = mg & (S_-1);
                int h = kk >> 6,  d = kk & (DK_-1);
                src = A + (((long)(b*H_ + h)*S_ + s)*DK_ + d);
            } else {
                src = A + (long)(m0 + r)*K + kk;
            }
            cpa16(as + r*ASTR + acol, src);
        }
    };
    auto copyB = [&](int k0, float* bs) {
#pragma unroll
        for (int t = 0; t < 4; t++) {
            int r = brow + t*8;
            cpa16(bs + r*BSTR + bcol, Bm + (long)(k0 + r)*N + n0 + bcol);
        }
    };

    float acc[4][4][4];
#pragma unroll
    for (int i = 0; i < 4; i++)
#pragma unroll
        for (int j = 0; j < 4; j++)
#pragma unroll
            for (int q = 0; q < 4; q++) acc[i][j][q] = 0.f;

    int niter = K >> 5;
    copyA(0, Asb[0]); copyB(0, Bsb[0]); cp_commit();

    for (int it = 0; it < niter; it++) {
        if (it + 1 < niter) {
            copyA((it+1) << 5, Asb[(it+1)&1]);
            copyB((it+1) << 5, Bsb[(it+1)&1]);
            cp_commit();
            cp_wait1();
        } else {
            cp_wait0();
        }
        __syncthreads();
        const float* as = Asb[it&1];
        const float* bs = Bsb[it&1];
#pragma unroll
        for (int ks = 0; ks < 4; ks++) {
            unsigned af[4][4], bf[4][2];
#pragma unroll
            for (int mt = 0; mt < 4; mt++) {
                int row = wm*64 + mt*16;
                if (CVT_A) {
                    af[mt][0] = f2tf(as[(row + r0    )*ASTR + ks*8 + kc    ]);
                    af[mt][1] = f2tf(as[(row + r0 + 8)*ASTR + ks*8 + kc    ]);
                    af[mt][2] = f2tf(as[(row + r0    )*ASTR + ks*8 + kc + 4]);
                    af[mt][3] = f2tf(as[(row + r0 + 8)*ASTR + ks*8 + kc + 4]);
                } else {
                    af[mt][0] = __float_as_uint(as[(row + r0    )*ASTR + ks*8 + kc    ]);
                    af[mt][1] = __float_as_uint(as[(row + r0 + 8)*ASTR + ks*8 + kc    ]);
                    af[mt][2] = __float_as_uint(as[(row + r0    )*ASTR + ks*8 + kc + 4]);
                    af[mt][3] = __float_as_uint(as[(row + r0 + 8)*ASTR + ks*8 + kc + 4]);
                }
            }
#pragma unroll
            for (int nt = 0; nt < 4; nt++) {
                int nb = wn*32 + nt*8;
                bf[nt][0] = __float_as_uint(bs[(ks*8 + kc    )*BSTR + nb + r0]);
                bf[nt][1] = __float_as_uint(bs[(ks*8 + kc + 4)*BSTR + nb + r0]);
            }
#pragma unroll
            for (int mt = 0; mt < 4; mt++)
#pragma unroll
                for (int nt = 0; nt < 4; nt++)
                    mma1688(acc[mt][nt], af[mt], bf[nt][0], bf[nt][1]);
        }
        __syncthreads();
    }

    // epilogue
#pragma unroll
    for (int mt = 0; mt < 4; mt++) {
#pragma unroll
        for (int nt = 0; nt < 4; nt++) {
            int c = n0 + wn*32 + nt*8 + kc*2;
            float bx = 0.f, by = 0.f;
            if (BIAS) { bx = bias[c]; by = bias[c+1]; }
#pragma unroll
            for (int half = 0; half < 2; half++) {
                int r = m0 + wm*64 + mt*16 + r0 + half*8;
                float vx = acc[mt][nt][half*2]   + bx;
                float vy = acc[mt][nt][half*2+1] + by;
                if (RELU) { vx = fmaxf(vx, 0.f); vy = fmaxf(vy, 0.f); }
                if (CVT_OUT) { vx = f2tff(vx); vy = f2tff(vy); }
                float* dst;
                if (OUT_HEADT) {
                    int b = r >> 11, s = r & (S_-1);
                    int h = c >> 6,  d = c & (DK_-1);
                    dst = C + (((long)(b*H_ + h)*S_ + s)*DK_ + d);
                } else {
                    dst = C + (long)r*N + c;
                }
                *(float2*)dst = make_float2(vx, vy);
            }
        }
    }
}

// ---------------------------------------------------------------------------
// Tensor-core flash attention, cp.async double-buffered K/V, 2 CTAs/SM.
// Q/K/V pre-rounded (QKV epilogue); only P needs rna at store.
// Output ao rounded (consumed by Wo-proj mma).
// ---------------------------------------------------------------------------
#define KSTR 68
#define VSTR 72
#define PSTR 68
#define KBUF (64*KSTR)
#define VBUF (64*VSTR)
#define FLASH_SMEM (((KBUF+VBUF)*2 + 128*PSTR) * 4)   // 106496 bytes

__global__ __launch_bounds__(256, 2)
void flash_cp(const float* __restrict__ Q, const float* __restrict__ K,
              const float* __restrict__ V, float* __restrict__ O)
{
    extern __shared__ float sm[];
    float* Ksb[2] = { sm,                      sm + KBUF + VBUF };
    float* Vsb[2] = { sm + KBUF,               sm + 2*KBUF + VBUF };
    float* Psh    = sm + 2*(KBUF + VBUF);      // [128][PSTR]

    int tid  = threadIdx.x;
    int lane = tid & 31;
    int w    = tid >> 5;
    int bh = blockIdx.y;
    int q0 = blockIdx.x * 128;
    int r0 = lane >> 2;
    int kc = lane & 3;

    auto copyKV = [&](int k0, float* ks, float* vs) {
        const float* Kb = K + ((long)bh*S_ + k0)*DK_;
        const float* Vb = V + ((long)bh*S_ + k0)*DK_;
#pragma unroll
        for (int t = 0; t < 4; t++) {
            int idx = tid + t*256;
            int r = idx >> 4;
            int c = (idx & 15) * 4;
            cpa16(ks + r*KSTR + c, Kb + r*DK_ + c);
            cpa16(vs + r*VSTR + c, Vb + r*DK_ + c);
        }
    };

    // persistent Q fragments; Q pre-rounded, *0.125 is exact (power of 2)
    unsigned qa[8][4];
    const float* qbase = Q + ((long)bh*S_ + q0 + w*16)*DK_;
#pragma unroll
    for (int kt = 0; kt < 8; kt++) {
        qa[kt][0] = __float_as_uint(qbase[(r0    )*DK_ + kt*8 + kc    ] * 0.125f);
        qa[kt][1] = __float_as_uint(qbase[(r0 + 8)*DK_ + kt*8 + kc    ] * 0.125f);
        qa[kt][2] = __float_as_uint(qbase[(r0    )*DK_ + kt*8 + kc + 4] * 0.125f);
        qa[kt][3] = __float_as_uint(qbase[(r0 + 8)*DK_ + kt*8 + kc + 4] * 0.125f);
    }

    float o[8][4];
#pragma unroll
    for (int nt = 0; nt < 8; nt++)
#pragma unroll
        for (int q = 0; q < 4; q++) o[nt][q] = 0.f;
    float m0 = -1e30f, m1 = -1e30f, l0 = 0.f, l1 = 0.f;

    const int niter = S_ / 64;
    copyKV(0, Ksb[0], Vsb[0]); cp_commit();

    for (int it = 0; it < niter; it++) {
        if (it + 1 < niter) {
            copyKV((it+1)*64, Ksb[(it+1)&1], Vsb[(it+1)&1]);
            cp_commit();
            cp_wait1();
        } else {
            cp_wait0();
        }
        __syncthreads();
        const float* ks = Ksb[it&1];
        const float* vs = Vsb[it&1];

        // S = Q K^T (warp: 16x64)
        float sc[8][4];
#pragma unroll
        for (int nt = 0; nt < 8; nt++)
#pragma unroll
            for (int q = 0; q < 4; q++) sc[nt][q] = 0.f;

#pragma unroll
        for (int kt = 0; kt < 8; kt++) {
            unsigned b0[8], b1[8];
#pragma unroll
            for (int nt = 0; nt < 8; nt++) {
                b0[nt] = __float_as_uint(ks[(nt*8 + r0)*KSTR + kt*8 + kc    ]);
                b1[nt] = __float_as_uint(ks[(nt*8 + r0)*KSTR + kt*8 + kc + 4]);
            }
#pragma unroll
            for (int nt = 0; nt < 8; nt++)
                mma1688(sc[nt], qa[kt], b0[nt], b1[nt]);
        }

        // online softmax (rows r0 and r0+8)
        float tm0 = -1e30f, tm1 = -1e30f;
#pragma unroll
        for (int nt = 0; nt < 8; nt++) {
            tm0 = fmaxf(tm0, fmaxf(sc[nt][0], sc[nt][1]));
            tm1 = fmaxf(tm1, fmaxf(sc[nt][2], sc[nt][3]));
        }
        tm0 = fmaxf(tm0, __shfl_xor_sync(0xffffffffu, tm0, 1));
        tm0 = fmaxf(tm0, __shfl_xor_sync(0xffffffffu, tm0, 2));
        tm1 = fmaxf(tm1, __shfl_xor_sync(0xffffffffu, tm1, 1));
        tm1 = fmaxf(tm1, __shfl_xor_sync(0xffffffffu, tm1, 2));

        float mn0 = fmaxf(m0, tm0), mn1 = fmaxf(m1, tm1);
        float c0 = __expf(m0 - mn0), c1 = __expf(m1 - mn1);
        l0 *= c0; l1 *= c1;

        float s0 = 0.f, s1 = 0.f;
#pragma unroll
        for (int nt = 0; nt < 8; nt++) {
            float p0 = __expf(sc[nt][0] - mn0);
            float p1 = __expf(sc[nt][1] - mn0);
            float p2 = __expf(sc[nt][2] - mn1);
            float p3 = __expf(sc[nt][3] - mn1);
            s0 += p0 + p1; s1 += p2 + p3;
            o[nt][0] *= c0; o[nt][1] *= c0; o[nt][2] *= c1; o[nt][3] *= c1;
            *(float2*)&Psh[(w*16 + r0    )*PSTR + nt*8 + kc*2] =
                make_float2(f2tff(p0), f2tff(p1));
            *(float2*)&Psh[(w*16 + r0 + 8)*PSTR + nt*8 + kc*2] =
                make_float2(f2tff(p2), f2tff(p3));
        }
        s0 += __shfl_xor_sync(0xffffffffu, s0, 1);
        s0 += __shfl_xor_sync(0xffffffffu, s0, 2);
        s1 += __shfl_xor_sync(0xffffffffu, s1, 1);
        s1 += __shfl_xor_sync(0xffffffffu, s1, 2);
        l0 += s0; l1 += s1;
        m0 = mn0; m1 = mn1;

        __syncwarp();   // P stripe is warp-private

        // O += P V
#pragma unroll
        for (int kt = 0; kt < 8; kt++) {
            unsigned pa[4];
            pa[0] = __float_as_uint(Psh[(w*16 + r0    )*PSTR + kt*8 + kc    ]);
            pa[1] = __float_as_uint(Psh[(w*16 + r0 + 8)*PSTR + kt*8 + kc    ]);
            pa[2] = __float_as_uint(Psh[(w*16 + r0    )*PSTR + kt*8 + kc + 4]);
            pa[3] = __float_as_uint(Psh[(w*16 + r0 + 8)*PSTR + kt*8 + kc + 4]);
            unsigned vb0[8], vb1[8];
#pragma unroll
            for (int nt = 0; nt < 8; nt++) {
                vb0[nt] = __float_as_uint(vs[(kt*8 + kc    )*VSTR + nt*8 + r0]);
                vb1[nt] = __float_as_uint(vs[(kt*8 + kc + 4)*VSTR + nt*8 + r0]);
            }
#pragma unroll
            for (int nt = 0; nt < 8; nt++)
                mma1688(o[nt], pa, vb0[nt], vb1[nt]);
        }
        __syncthreads();
    }

    float i0 = 1.f / l0, i1 = 1.f / l1;
    float* ob = O + ((long)bh*S_ + q0 + w*16)*DK_;
#pragma unroll
    for (int nt = 0; nt < 8; nt++) {
        *(float2*)&ob[(r0    )*DK_ + nt*8 + kc*2] =
            make_float2(f2tff(o[nt][0]*i0), f2tff(o[nt][1]*i0));
        *(float2*)&ob[(r0 + 8)*DK_ + nt*8 + kc*2] =
            make_float2(f2tff(o[nt][2]*i1), f2tff(o[nt][3]*i1));
    }
}

// ---------------------------------------------------------------------------
// out = LayerNorm(x + r) * g + b
// ---------------------------------------------------------------------------
__global__ __launch_bounds__(128)
void add_ln_kernel(const float* __restrict__ x, const float* __restrict__ r,
                   const float* __restrict__ g, const float* __restrict__ bta,
                   float* __restrict__ out)
{
    __shared__ float red[4];
    int row = blockIdx.x;
    int tid = threadIdx.x;
    int e = tid * 4;
    const float4 xv = *(const float4*)(x + (long)row*E_ + e);
    const float4 rv = *(const float4*)(r + (long)row*E_ + e);
    float t0 = xv.x + rv.x, t1 = xv.y + rv.y, t2 = xv.z + rv.z, t3 = xv.w + rv.w;

    float s = t0 + t1 + t2 + t3;
#pragma unroll
    for (int off = 16; off; off >>= 1) s += __shfl_xor_sync(0xffffffffu, s, off);
    if ((tid & 31) == 0) red[tid >> 5] = s;
    __syncthreads();
    float mean = (red[0]+red[1]+red[2]+red[3]) * (1.f/E_);
    __syncthreads();

    float d0 = t0-mean, d1 = t1-mean, d2 = t2-mean, d3 = t3-mean;
    float vs = d0*d0 + d1*d1 + d2*d2 + d3*d3;
#pragma unroll
    for (int off = 16; off; off >>= 1) vs += __shfl_xor_sync(0xffffffffu, vs, off);
    if ((tid & 31) == 0) red[tid >> 5] = vs;
    __syncthreads();
    float var = (red[0]+red[1]+red[2]+red[3]) * (1.f/E_);
    float rstd = rsqrtf(var + 1e-5f);

    float4 gg = *(const float4*)(g + e);
    float4 bb = *(const float4*)(bta + e);
    float4 v = make_float4(d0*rstd*gg.x + bb.x, d1*rstd*gg.y + bb.y,
                           d2*rstd*gg.z + bb.z, d3*rstd*gg.w + bb.w);
    *(float4*)(out + (long)row*E_ + e) = v;
}

// ---------------------------------------------------------------------------
// Mean over S (two-stage) + classifier
// ---------------------------------------------------------------------------
__global__ void mean_part_kernel(const float* __restrict__ x, float* __restrict__ part)
{
    int idx = blockIdx.x*256 + threadIdx.x;
    int b = idx >> 9;
    int e = idx & (E_-1);
    int c = blockIdx.y;
    const float* p = x + ((long)b*S_ + c*128)*E_ + e;
    float s = 0.f;
#pragma unroll 8
    for (int i = 0; i < 128; i++) s += p[(long)i*E_];
    part[c*(B_*E_) + idx] = s;
}

__global__ void mean_final_kernel(const float* __restrict__ part, float* __restrict__ mean)
{
    int idx = blockIdx.x*256 + threadIdx.x;
    float s = 0.f;
#pragma unroll
    for (int c = 0; c < 16; c++) s += part[c*(B_*E_) + idx];
    mean[idx] = s * (1.f/(float)S_);
}

__global__ __launch_bounds__(128)
void classify_kernel(const float* __restrict__ mean, const float* __restrict__ w,
                     const float* __restrict__ bias, float* __restrict__ out)
{
    __shared__ float red[4];
    int b = blockIdx.x >> 2;
    int c = blockIdx.x & 3;
    int tid = threadIdx.x;
    float s = 0.f;
    for (int e = tid; e < E_; e += 128) s += mean[b*E_ + e] * w[e*C_ + c];
#pragma unroll
    for (int off = 16; off; off >>= 1) s += __shfl_xor_sync(0xffffffffu, s, off);
    if ((tid & 31) == 0) red[tid >> 5] = s;
    __syncthreads();
    if (tid == 0) out[b*C_ + c] = red[0]+red[1]+red[2]+red[3] + bias[c];
}

// ---------------------------------------------------------------------------
// Launch
// ---------------------------------------------------------------------------
extern "C" void kernel_launch(void* const* d_in, const int* in_sizes, int n_in,
                              void* d_out, int out_size)
{
    const int*   tokens = (const int*)  d_in[0];
    const float* emb    = (const float*)d_in[1];
    const float* Wq     = (const float*)d_in[2];
    const float* Wk     = (const float*)d_in[3];
    const float* Wv     = (const float*)d_in[4];
    const float* Wo     = (const float*)d_in[5];
    const float* qh_w   = (const float*)d_in[6];
    const float* qh_b   = (const float*)d_in[7];
    const float* kh_w   = (const float*)d_in[8];
    const float* kh_b   = (const float*)d_in[9];
    const float* vh_w   = (const float*)d_in[10];
    const float* vh_b   = (const float*)d_in[11];
    const float* ln1_g  = (const float*)d_in[12];
    const float* ln1_b  = (const float*)d_in[13];
    const float* ln2_g  = (const float*)d_in[14];
    const float* ln2_b  = (const float*)d_in[15];
    const float* f_w1   = (const float*)d_in[16];
    const float* f_b1   = (const float*)d_in[17];
    const float* f_w2   = (const float*)d_in[18];
    const float* f_b2   = (const float*)d_in[19];
    const float* cls_w  = (const float*)d_in[20];
    const float* cls_b  = (const float*)d_in[21];

    float *x,*q,*k,*v,*ao,*p,*y,*ffn,*part,*mean,*wc,*weff,*beff,*w1r,*w2r,*wor;
    cudaGetSymbolAddress((void**)&x,    g_x);
    cudaGetSymbolAddress((void**)&q,    g_q);
    cudaGetSymbolAddress((void**)&k,    g_k);
    cudaGetSymbolAddress((void**)&v,    g_v);
    cudaGetSymbolAddress((void**)&ao,   g_ao);
    cudaGetSymbolAddress((void**)&p,    g_p);
    cudaGetSymbolAddress((void**)&y,    g_y);
    cudaGetSymbolAddress((void**)&ffn,  g_ffn);
    cudaGetSymbolAddress((void**)&part, g_part);
    cudaGetSymbolAddress((void**)&mean, g_mean);
    cudaGetSymbolAddress((void**)&wc,   g_wc);
    cudaGetSymbolAddress((void**)&weff, g_weff);
    cudaGetSymbolAddress((void**)&beff, g_beff);
    cudaGetSymbolAddress((void**)&w1r,  g_w1r);
    cudaGetSymbolAddress((void**)&w2r,  g_w2r);
    cudaGetSymbolAddress((void**)&wor,  g_wor);

    cudaFuncSetAttribute((const void*)flash_cp,
                         cudaFuncAttributeMaxDynamicSharedMemorySize, FLASH_SMEM);
    cudaFuncSetAttribute((const void*)sgemm_cp<true,false,true,false,true,true>,
                         cudaFuncAttributeMaxDynamicSharedMemorySize, GEMM_SMEM);
    cudaFuncSetAttribute((const void*)sgemm_cp<false,true,false,false,false,false>,
                         cudaFuncAttributeMaxDynamicSharedMemorySize, GEMM_SMEM);
    cudaFuncSetAttribute((const void*)sgemm_cp<false,false,true,true,true,true>,
                         cudaFuncAttributeMaxDynamicSharedMemorySize, GEMM_SMEM);
    cudaFuncSetAttribute((const void*)sgemm_cp<false,false,true,false,false,false>,
                         cudaFuncAttributeMaxDynamicSharedMemorySize, GEMM_SMEM);

    const int M = B_*S_;               // 8192
    const long ESQ = (long)E_*E_;
    dim3 gQKV(E_/128, M/128, 3);       // (4, 64, 3)
    dim3 gProj(E_/128, M/128, 1);      // (4, 64)
    dim3 gFfn1(FF_/128, M/128, 1);     // (16, 64)
    dim3 gFlash(S_/128, B_*H_);        // (16, 32)

    // Precompute: embedding, folded quantum weights, tf32-rounded weights
    embed_kernel<<<M, 128>>>(tokens, emb, x);
    qcombine_kernel<<<3*NB_*H_, 256>>>(qh_w, qh_b, kh_w, kh_b, vh_w, vh_b, wc, beff);
    qweff_kernel<<<dim3(8, H_, 3*NB_), 256>>>(Wq, Wk, Wv, wc, weff);
    round_tf32_kernel<<<(NB_*E_*FF_/4 + 255)/256, 256>>>(f_w1, w1r, NB_*E_*FF_/4);
    round_tf32_kernel<<<(NB_*FF_*E_/4 + 255)/256, 256>>>(f_w2, w2r, NB_*FF_*E_/4);
    round_tf32_kernel<<<(NB_*E_*E_/4  + 255)/256, 256>>>(Wo,   wor, NB_*E_*E_/4);

    for (int i = 0; i < NB_; i++) {
        const float* Wo_i = wor + (long)i*ESQ;

        // fused QKV projection (quantum folded), out rounded + [B,H,S,DK]
        sgemm_cp<true,false,true,false,true,true><<<gQKV, 256, GEMM_SMEM>>>(
            x,
            weff + (0*NB_ + i)*ESQ, weff + (1*NB_ + i)*ESQ, weff + (2*NB_ + i)*ESQ,
            beff + (0*NB_ + i)*E_,  beff + (1*NB_ + i)*E_,  beff + (2*NB_ + i)*E_,
            q, k, v, M, E_, E_);

        // attention (tensor cores)
        flash_cp<<<gFlash, 256, FLASH_SMEM>>>(q, k, v, ao);

        // output projection (A=ao pre-rounded) + residual + LN1
        sgemm_cp<false,true,false,false,false,false><<<gProj, 256, GEMM_SMEM>>>(
            ao, Wo_i, Wo_i, Wo_i, nullptr, nullptr, nullptr, p, p, p, M, E_, E_);
        add_ln_kernel<<<M, 128>>>(x, p, ln1_g + i*E_, ln1_b + i*E_, y);

        // FFN + residual + LN2
        sgemm_cp<false,false,true,true,true,true><<<gFfn1, 256, GEMM_SMEM>>>(
            y, w1r + (long)i*E_*FF_, w1r + (long)i*E_*FF_, w1r + (long)i*E_*FF_,
            f_b1 + i*FF_, f_b1 + i*FF_, f_b1 + i*FF_,
            ffn, ffn, ffn, M, FF_, E_);
        sgemm_cp<false,false,true,false,false,false><<<gProj, 256, GEMM_SMEM>>>(
            ffn, w2r + (long)i*FF_*E_, w2r + (long)i*FF_*E_, w2r + (long)i*FF_*E_,
            f_b2 + i*E_, f_b2 + i*E_, f_b2 + i*E_,
            p, p, p, M, E_, FF_);
        add_ln_kernel<<<M, 128>>>(y, p, ln2_g + i*E_, ln2_b + i*E_, x);
    }

    mean_part_kernel<<<dim3((B_*E_)/256, 16), 256>>>(x, part);
    mean_final_kernel<<<(B_*E_)/256, 256>>>(part, mean);
    classify_kernel<<<B_*C_, 128>>>(mean, cls_w, cls_b, (float*)d_out);
}

// round 7
// speedup vs baseline: 4.5586x; 1.0966x over previous
#include <cuda_runtime.h>
#include <cuda_bf16.h>
#include <math.h>

// Problem constants
#define B_  4
#define S_  2048
#define E_  512
#define H_  8
#define DK_ 64
#define L_  2
#define NB_ 4
#define FF_ 2048
#define C_  4

// ---------------------------------------------------------------------------
// Scratch (device globals; no allocations anywhere)
// ---------------------------------------------------------------------------
__device__ float g_x  [B_*S_*E_];
__device__ float g_xr [B_*S_*E_];            // tf32-rounded copy of x
__device__ float g_q  [B_*S_*E_];
__device__ float g_k  [B_*S_*E_];
__device__ float g_v  [B_*S_*E_];            // V stored [B,H,DK,S] (d-major)
__device__ float g_ao [B_*S_*E_];
__device__ float g_p  [B_*S_*E_];
__device__ float g_y  [B_*S_*E_];
__device__ float g_yr [B_*S_*E_];            // tf32-rounded copy of y
__device__ float g_ffn[B_*S_*FF_];
__device__ float g_part[16*B_*E_];
__device__ float g_mean[B_*E_];
// folded quantum weights + transposed/rounded weights [N][K]
__device__ float g_wc  [3*NB_*H_*DK_*DK_];
__device__ float g_weff[3*NB_*E_*E_];        // QKV eff weights, [N][K], tf32
__device__ float g_beff[3*NB_*E_];
__device__ float g_w1t [NB_*FF_*E_];         // f_w1^T  [FF][E], tf32
__device__ float g_w2t [NB_*E_*FF_];         // f_w2^T  [E][FF], tf32
__device__ float g_wot [NB_*E_*E_];          // Wo^T    [E][E],  tf32

// ---------------------------------------------------------------------------
// Helpers
// ---------------------------------------------------------------------------
__device__ __forceinline__ void cpa16(void* dst, const void* src) {
    unsigned d = (unsigned)__cvta_generic_to_shared(dst);
    asm volatile("cp.async.cg.shared.global [%0], [%1], 16;" :: "r"(d), "l"(src));
}
__device__ __forceinline__ void cp_commit() { asm volatile("cp.async.commit_group;"); }
__device__ __forceinline__ void cp_wait0()  { asm volatile("cp.async.wait_group 0;"); }
__device__ __forceinline__ void cp_wait1()  { asm volatile("cp.async.wait_group 1;"); }

__device__ __forceinline__ unsigned f2tf(float x) {
    unsigned r;
    asm("cvt.rna.tf32.f32 %0, %1;" : "=r"(r) : "f"(x));
    return r;
}
__device__ __forceinline__ float f2tff(float x) { return __uint_as_float(f2tf(x)); }

__device__ __forceinline__ void mma1688(float* c, const unsigned* a, unsigned b0, unsigned b1) {
    asm volatile(
        "mma.sync.aligned.m16n8k8.row.col.f32.tf32.tf32.f32 "
        "{%0,%1,%2,%3}, {%4,%5,%6,%7}, {%8,%9}, {%0,%1,%2,%3};"
        : "+f"(c[0]), "+f"(c[1]), "+f"(c[2]), "+f"(c[3])
        : "r"(a[0]), "r"(a[1]), "r"(a[2]), "r"(a[3]), "r"(b0), "r"(b1));
}

// x4 ldmatrix: threads 0-7 feed matrix0 rows, 8-15 m1, 16-23 m2, 24-31 m3.
// For 32-bit data each "matrix" is an 8x4 block; thread i gets elem (i/4, i%4).
__device__ __forceinline__ void ldsm4(unsigned& a, unsigned& b, unsigned& c, unsigned& d,
                                      unsigned addr) {
    asm volatile("ldmatrix.sync.aligned.m8n8.x4.shared.b16 {%0,%1,%2,%3}, [%4];"
        : "=r"(a), "=r"(b), "=r"(c), "=r"(d) : "r"(addr));
}

// ---------------------------------------------------------------------------
// Embedding + positional encoding (dual output: fp32 + tf32-rounded)
// ---------------------------------------------------------------------------
__global__ void embed_kernel(const int* __restrict__ tok,
                             const float* __restrict__ emb,
                             float* __restrict__ x, float* __restrict__ xr)
{
    int row = blockIdx.x;
    int s   = row & (S_-1);
    int t   = tok[row];
    int e   = threadIdx.x * 4;
    float4 ev = *(const float4*)(emb + (long)t*E_ + e);
    float r[4] = {ev.x, ev.y, ev.z, ev.w};
#pragma unroll
    for (int c = 0; c < 4; c++) {
        int ee = e + c;
        int i2 = ee & ~1;
        float div = __expf((float)i2 * (-9.210340371976184f / (float)E_));
        float arg = (float)s * div;
        r[c] += (ee & 1) ? cosf(arg) : sinf(arg);
    }
    *(float4*)(x  + (long)row*E_ + e) = make_float4(r[0], r[1], r[2], r[3]);
    *(float4*)(xr + (long)row*E_ + e) =
        make_float4(f2tff(r[0]), f2tff(r[1]), f2tff(r[2]), f2tff(r[3]));
}

// ---------------------------------------------------------------------------
// Fold quantum linears: Wc[h] = W1[h]@W2[h], beff = b1@W2 + b2   (fp32)
// ---------------------------------------------------------------------------
__global__ __launch_bounds__(256)
void qcombine_kernel(const float* __restrict__ qw, const float* __restrict__ qb,
                     const float* __restrict__ kw, const float* __restrict__ kb,
                     const float* __restrict__ vw, const float* __restrict__ vb,
                     float* __restrict__ wc, float* __restrict__ beff)
{
    __shared__ float s1[64*65], s2[64*65];
    int blk = blockIdx.x;
    int t  = blk / (NB_*H_);
    int ih = blk % (NB_*H_);
    int i  = ih / H_, h = ih % H_;
    const float* w = t==0 ? qw : (t==1 ? kw : vw);
    const float* b = t==0 ? qb : (t==1 ? kb : vb);
    const float* W1 = w + ((long)(i*L_+0)*H_ + h)*DK_*DK_;
    const float* W2 = w + ((long)(i*L_+1)*H_ + h)*DK_*DK_;
    const float* b1 = b + ((long)(i*L_+0)*H_ + h)*DK_;
    const float* b2 = b + ((long)(i*L_+1)*H_ + h)*DK_;
    int tid = threadIdx.x;
    for (int idx = tid; idx < 4096; idx += 256) {
        int r = idx >> 6, c = idx & 63;
        s1[r*65+c] = W1[idx];
        s2[r*65+c] = W2[idx];
    }
    __syncthreads();
    float* wcp = wc + (long)blk*DK_*DK_;
    for (int idx = tid; idx < 4096; idx += 256) {
        int r = idx >> 6, c = idx & 63;
        float sum = 0.f;
#pragma unroll 8
        for (int d = 0; d < 64; d++) sum += s1[r*65+d]*s2[d*65+c];
        wcp[idx] = sum;
    }
    if (tid < 64) {
        float sum = b2[tid];
#pragma unroll 8
        for (int d = 0; d < 64; d++) sum += b1[d]*s2[d*65+tid];
        beff[((long)t*NB_ + i)*E_ + h*DK_ + tid] = sum;
    }
}

// ---------------------------------------------------------------------------
// Effective QKV weights, written TRANSPOSED [N][K] + tf32-rounded:
// WeffT[h*64+n][k] = sum_d Wq[k][h*64+d] * Wc[h][d][n]
// ---------------------------------------------------------------------------
__global__ __launch_bounds__(256)
void qweff_kernel(const float* __restrict__ Wq, const float* __restrict__ Wk,
                  const float* __restrict__ Wv,
                  const float* __restrict__ wc, float* __restrict__ weff)
{
    __shared__ float wq_s[64*65];   // [k_local][d]
    __shared__ float wc_s[64*65];   // [d][n]
    int t = blockIdx.z / NB_, i = blockIdx.z % NB_;
    int h = blockIdx.y;
    int rb = blockIdx.x;            // 64-row block of K
    const float* Wsrc = (t==0 ? Wq : (t==1 ? Wk : Wv)) + (long)i*E_*E_;
    const float* Wcp  = wc + (long)((t*NB_ + i)*H_ + h)*DK_*DK_;
    float* out = weff + (long)(t*NB_ + i)*E_*E_;
    int tid = threadIdx.x;
    for (int idx = tid; idx < 64*64; idx += 256) {
        int r = idx >> 6, c = idx & 63;
        wq_s[r*65+c] = Wsrc[(long)(rb*64 + r)*E_ + h*64 + c];
        wc_s[r*65+c] = Wcp[idx];
    }
    __syncthreads();
    int kl = tid & 63;
    for (int nl = tid >> 6; nl < 64; nl += 4) {
        float sum = 0.f;
#pragma unroll 8
        for (int d = 0; d < 64; d++) sum += wq_s[kl*65+d]*wc_s[d*65+nl];
        out[(long)(h*64 + nl)*E_ + rb*64 + kl] = f2tff(sum);
    }
}

// ---------------------------------------------------------------------------
// Transpose + tf32-round: in [K][N] (per batch z) -> out [N][K]
// ---------------------------------------------------------------------------
__global__ void tr_round_kernel(const float* __restrict__ in, float* __restrict__ out,
                                int K, int N)
{
    __shared__ float t[32][33];
    int kb = blockIdx.x*32, nb = blockIdx.y*32;
    const float* inp = in  + (long)blockIdx.z*K*N;
    float*       oup = out + (long)blockIdx.z*K*N;
    int x = threadIdx.x, y0 = threadIdx.y;   // 32 x 8
#pragma unroll
    for (int dy = 0; dy < 32; dy += 8)
        t[y0+dy][x] = inp[(long)(kb+y0+dy)*N + nb + x];
    __syncthreads();
#pragma unroll
    for (int dy = 0; dy < 32; dy += 8)
        oup[(long)(nb+y0+dy)*K + kb + x] = f2tff(t[x][y0+dy]);
}

// ---------------------------------------------------------------------------
// TF32 GEMM: C[M,N] = A[M,K] @ BT[N,K]^T (+bias)(+relu), ldmatrix operands.
// A pre-rounded; BT pre-rounded+transposed. 128x128 tile, BK=32, 256 thr.
// z==2 with OUT_HEADT stores V transposed ([B,H,DK,S]).
// ---------------------------------------------------------------------------
#define ASTR 36
#define ABUF (128*ASTR)
#define GEMM_SMEM (ABUF*4*2*4)                // A + B, 2 stages: 73728 B

template<bool OUT_HEADT, bool IN_HEADT, bool BIAS, bool RELU, bool CVT_OUT>
__global__ __launch_bounds__(256, 2)
void sgemm_cp(const float* __restrict__ A,
              const float* __restrict__ Bp0, const float* __restrict__ Bp1,
              const float* __restrict__ Bp2,
              const float* __restrict__ bi0, const float* __restrict__ bi1,
              const float* __restrict__ bi2,
              float* __restrict__ Cp0, float* __restrict__ Cp1,
              float* __restrict__ Cp2,
              int M, int N, int K)
{
    extern __shared__ float sm[];
    int z = blockIdx.z;
    const float* Bm   = z==0 ? Bp0 : (z==1 ? Bp1 : Bp2);
    const float* bias = z==0 ? bi0 : (z==1 ? bi1 : bi2);
    float*       C    = z==0 ? Cp0 : (z==1 ? Cp1 : Cp2);

    float* Asb[2] = { sm,           sm + 2*ABUF };
    float* Bsb[2] = { sm + ABUF,    sm + 3*ABUF };

    int tid  = threadIdx.x;
    int lane = tid & 31;
    int w    = tid >> 5;
    int wm   = w & 1;
    int wn   = w >> 1;
    int n0 = blockIdx.x * 128;
    int m0 = blockIdx.y * 128;
    int r0 = lane >> 2;
    int kc = lane & 3;
    int mrow = lane & 7, msel = lane >> 3;

    int grow = tid >> 3;          // 0..31 (+t*32)
    int gcol = (tid & 7) * 4;     // 0..28

    auto copyA = [&](int k0, float* as) {
#pragma unroll
        for (int t = 0; t < 4; t++) {
            int r = grow + t*32;
            int kk = k0 + gcol;
            const float* src;
            if (IN_HEADT) {
                int mg = m0 + r;
                int b = mg >> 11, s = mg & (S_-1);
                int h = kk >> 6,  d = kk & (DK_-1);
                src = A + (((long)(b*H_ + h)*S_ + s)*DK_ + d);
            } else {
                src = A + (long)(m0 + r)*K + kk;
            }
            cpa16(as + r*ASTR + gcol, src);
        }
    };
    auto copyB = [&](int k0, float* bs) {
#pragma unroll
        for (int t = 0; t < 4; t++) {
            int r = grow + t*32;
            cpa16(bs + r*ASTR + gcol, Bm + (long)(n0 + r)*K + k0 + gcol);
        }
    };

    float acc[4][4][4];
#pragma unroll
    for (int i = 0; i < 4; i++)
#pragma unroll
        for (int j = 0; j < 4; j++)
#pragma unroll
            for (int q = 0; q < 4; q++) acc[i][j][q] = 0.f;

    int niter = K >> 5;
    copyA(0, Asb[0]); copyB(0, Bsb[0]); cp_commit();

    for (int it = 0; it < niter; it++) {
        if (it + 1 < niter) {
            copyA((it+1) << 5, Asb[(it+1)&1]);
            copyB((it+1) << 5, Bsb[(it+1)&1]);
            cp_commit();
            cp_wait1();
        } else {
            cp_wait0();
        }
        __syncthreads();
        unsigned as_b = (unsigned)__cvta_generic_to_shared(Asb[it&1]);
        unsigned bs_b = (unsigned)__cvta_generic_to_shared(Bsb[it&1]);
        unsigned aoff = as_b + 4u*((wm*64 + mrow + (msel&1)*8)*ASTR + (msel>>1)*4);
        unsigned boff = bs_b + 4u*((wn*32 + mrow + (msel>>1)*8)*ASTR + (msel&1)*4);
#pragma unroll
        for (int ks = 0; ks < 4; ks++) {
            unsigned af[4][4], bf[4][2];
#pragma unroll
            for (int mt = 0; mt < 4; mt++)
                ldsm4(af[mt][0], af[mt][1], af[mt][2], af[mt][3],
                      aoff + 4u*(mt*16*ASTR + ks*8));
#pragma unroll
            for (int ntp = 0; ntp < 4; ntp += 2)
                ldsm4(bf[ntp][0], bf[ntp][1], bf[ntp+1][0], bf[ntp+1][1],
                      boff + 4u*(ntp*8*ASTR + ks*8));
#pragma unroll
            for (int mt = 0; mt < 4; mt++)
#pragma unroll
                for (int nt = 0; nt < 4; nt++)
                    mma1688(acc[mt][nt], af[mt], bf[nt][0], bf[nt][1]);
        }
        __syncthreads();
    }

    // epilogue
#pragma unroll
    for (int mt = 0; mt < 4; mt++) {
#pragma unroll
        for (int nt = 0; nt < 4; nt++) {
            int c = n0 + wn*32 + nt*8 + kc*2;
            float bx = 0.f, by = 0.f;
            if (BIAS) { bx = bias[c]; by = bias[c+1]; }
#pragma unroll
            for (int half = 0; half < 2; half++) {
                int r = m0 + wm*64 + mt*16 + r0 + half*8;
                float vx = acc[mt][nt][half*2]   + bx;
                float vy = acc[mt][nt][half*2+1] + by;
                if (RELU) { vx = fmaxf(vx, 0.f); vy = fmaxf(vy, 0.f); }
                if (CVT_OUT) { vx = f2tff(vx); vy = f2tff(vy); }
                if (OUT_HEADT) {
                    int b = r >> 11, s = r & (S_-1);
                    int h = c >> 6,  d = c & (DK_-1);
                    if (z == 2) {   // V: store [B,H,DK,S]
                        float* dst = C + (((long)(b*H_ + h)*DK_ + d)*S_ + s);
                        dst[0]  = vx;
                        dst[S_] = vy;
                    } else {
                        *(float2*)(C + (((long)(b*H_ + h)*S_ + s)*DK_ + d)) =
                            make_float2(vx, vy);
                    }
                } else {
                    *(float2*)(C + (long)r*N + c) = make_float2(vx, vy);
                }
            }
        }
    }
}

// ---------------------------------------------------------------------------
// Flash attention, tf32 mma + ldmatrix everywhere, cp.async K/V, 2 CTA/SM.
// Q,K: [B,H,S,DK]; V: [B,H,DK,S] (transposed by QKV epilogue). All rounded.
// ---------------------------------------------------------------------------
#define KSTR 68
#define VTSTR 68
#define PSTR 68
#define KBUF (64*KSTR)
#define VBUF (64*VTSTR)
#define FLASH_SMEM (((KBUF+VBUF)*2 + 128*PSTR) * 4)   // 104448 B

__global__ __launch_bounds__(256, 2)
void flash_cp(const float* __restrict__ Q, const float* __restrict__ K,
              const float* __restrict__ V, float* __restrict__ O)
{
    extern __shared__ float sm[];
    float* Ksb[2] = { sm,                      sm + KBUF + VBUF };
    float* Vsb[2] = { sm + KBUF,               sm + 2*KBUF + VBUF };
    float* Psh    = sm + 2*(KBUF + VBUF);      // [128][PSTR]

    int tid  = threadIdx.x;
    int lane = tid & 31;
    int w    = tid >> 5;
    int bh = blockIdx.y;
    int q0 = blockIdx.x * 128;
    int r0 = lane >> 2;
    int kc = lane & 3;
    int mrow = lane & 7, msel = lane >> 3;

    auto copyKV = [&](int k0, float* ks, float* vs) {
        const float* Kb = K + ((long)bh*S_ + k0)*DK_;
        const float* Vb = V + (long)bh*DK_*S_ + k0;
#pragma unroll
        for (int t = 0; t < 4; t++) {
            int idx = tid + t*256;
            int r = idx >> 4;
            int c = (idx & 15) * 4;
            cpa16(ks + r*KSTR  + c, Kb + r*DK_ + c);
            cpa16(vs + r*VTSTR + c, Vb + (long)r*S_ + c);
        }
    };

    // persistent Q fragments (pre-rounded; *0.125 exact)
    unsigned qa[8][4];
    const float* qbase = Q + ((long)bh*S_ + q0 + w*16)*DK_;
#pragma unroll
    for (int kt = 0; kt < 8; kt++) {
        qa[kt][0] = __float_as_uint(qbase[(r0    )*DK_ + kt*8 + kc    ] * 0.125f);
        qa[kt][1] = __float_as_uint(qbase[(r0 + 8)*DK_ + kt*8 + kc    ] * 0.125f);
        qa[kt][2] = __float_as_uint(qbase[(r0    )*DK_ + kt*8 + kc + 4] * 0.125f);
        qa[kt][3] = __float_as_uint(qbase[(r0 + 8)*DK_ + kt*8 + kc + 4] * 0.125f);
    }

    float o[8][4];
#pragma unroll
    for (int nt = 0; nt < 8; nt++)
#pragma unroll
        for (int q = 0; q < 4; q++) o[nt][q] = 0.f;
    float m0 = -1e30f, m1 = -1e30f, l0 = 0.f, l1 = 0.f;

    unsigned p_base = (unsigned)__cvta_generic_to_shared(Psh);
    unsigned poff = p_base + 4u*((w*16 + mrow + (msel&1)*8)*PSTR + (msel>>1)*4);

    const int niter = S_ / 64;
    copyKV(0, Ksb[0], Vsb[0]); cp_commit();

    for (int it = 0; it < niter; it++) {
        if (it + 1 < niter) {
            copyKV((it+1)*64, Ksb[(it+1)&1], Vsb[(it+1)&1]);
            cp_commit();
            cp_wait1();
        } else {
            cp_wait0();
        }
        __syncthreads();
        unsigned ks_b = (unsigned)__cvta_generic_to_shared(Ksb[it&1]);
        unsigned vs_b = (unsigned)__cvta_generic_to_shared(Vsb[it&1]);
        unsigned koff = ks_b + 4u*((mrow + (msel>>1)*8)*KSTR  + (msel&1)*4);
        unsigned voff = vs_b + 4u*((mrow + (msel>>1)*8)*VTSTR + (msel&1)*4);

        // S = Q K^T (warp: 16x64)
        float sc[8][4];
#pragma unroll
        for (int nt = 0; nt < 8; nt++)
#pragma unroll
            for (int q = 0; q < 4; q++) sc[nt][q] = 0.f;

#pragma unroll
        for (int kt = 0; kt < 8; kt++) {
            unsigned b0[8], b1[8];
#pragma unroll
            for (int ntp = 0; ntp < 8; ntp += 2)
                ldsm4(b0[ntp], b1[ntp], b0[ntp+1], b1[ntp+1],
                      koff + 4u*(ntp*8*KSTR + kt*8));
#pragma unroll
            for (int nt = 0; nt < 8; nt++)
                mma1688(sc[nt], qa[kt], b0[nt], b1[nt]);
        }

        // online softmax (rows r0 and r0+8)
        float tm0 = -1e30f, tm1 = -1e30f;
#pragma unroll
        for (int nt = 0; nt < 8; nt++) {
            tm0 = fmaxf(tm0, fmaxf(sc[nt][0], sc[nt][1]));
            tm1 = fmaxf(tm1, fmaxf(sc[nt][2], sc[nt][3]));
        }
        tm0 = fmaxf(tm0, __shfl_xor_sync(0xffffffffu, tm0, 1));
        tm0 = fmaxf(tm0, __shfl_xor_sync(0xffffffffu, tm0, 2));
        tm1 = fmaxf(tm1, __shfl_xor_sync(0xffffffffu, tm1, 1));
        tm1 = fmaxf(tm1, __shfl_xor_sync(0xffffffffu, tm1, 2));

        float mn0 = fmaxf(m0, tm0), mn1 = fmaxf(m1, tm1);
        float c0 = __expf(m0 - mn0), c1 = __expf(m1 - mn1);
        l0 *= c0; l1 *= c1;

        float s0 = 0.f, s1 = 0.f;
#pragma unroll
        for (int nt = 0; nt < 8; nt++) {
            float p0 = __expf(sc[nt][0] - mn0);
            float p1 = __expf(sc[nt][1] - mn0);
            float p2 = __expf(sc[nt][2] - mn1);
            float p3 = __expf(sc[nt][3] - mn1);
            s0 += p0 + p1; s1 += p2 + p3;
            o[nt][0] *= c0; o[nt][1] *= c0; o[nt][2] *= c1; o[nt][3] *= c1;
            *(float2*)&Psh[(w*16 + r0    )*PSTR + nt*8 + kc*2] =
                make_float2(f2tff(p0), f2tff(p1));
            *(float2*)&Psh[(w*16 + r0 + 8)*PSTR + nt*8 + kc*2] =
                make_float2(f2tff(p2), f2tff(p3));
        }
        s0 += __shfl_xor_sync(0xffffffffu, s0, 1);
        s0 += __shfl_xor_sync(0xffffffffu, s0, 2);
        s1 += __shfl_xor_sync(0xffffffffu, s1, 1);
        s1 += __shfl_xor_sync(0xffffffffu, s1, 2);
        l0 += s0; l1 += s1;
        m0 = mn0; m1 = mn1;

        __syncwarp();   // P stripe is warp-private

        // O += P V   (P via ldmatrix A-pattern, V via ldmatrix B-pattern)
#pragma unroll
        for (int kt = 0; kt < 8; kt++) {
            unsigned pa[4];
            ldsm4(pa[0], pa[1], pa[2], pa[3], poff + 4u*(kt*8));
            unsigned v0[8], v1[8];
#pragma unroll
            for (int ntp = 0; ntp < 8; ntp += 2)
                ldsm4(v0[ntp], v1[ntp], v0[ntp+1], v1[ntp+1],
                      voff + 4u*(ntp*8*VTSTR + kt*8));
#pragma unroll
            for (int nt = 0; nt < 8; nt++)
                mma1688(o[nt], pa, v0[nt], v1[nt]);
        }
        __syncthreads();
    }

    float i0 = 1.f / l0, i1 = 1.f / l1;
    float* ob = O + ((long)bh*S_ + q0 + w*16)*DK_;
#pragma unroll
    for (int nt = 0; nt < 8; nt++) {
        *(float2*)&ob[(r0    )*DK_ + nt*8 + kc*2] =
            make_float2(f2tff(o[nt][0]*i0), f2tff(o[nt][1]*i0));
        *(float2*)&ob[(r0 + 8)*DK_ + nt*8 + kc*2] =
            make_float2(f2tff(o[nt][2]*i1), f2tff(o[nt][3]*i1));
    }
}

// ---------------------------------------------------------------------------
// out = LayerNorm(x + r) * g + b  — dual output (fp32 + tf32-rounded)
// ---------------------------------------------------------------------------
__global__ __launch_bounds__(128)
void add_ln_kernel(const float* __restrict__ x, const float* __restrict__ r,
                   const float* __restrict__ g, const float* __restrict__ bta,
                   float* __restrict__ out, float* __restrict__ outr)
{
    __shared__ float red[4];
    int row = blockIdx.x;
    int tid = threadIdx.x;
    int e = tid * 4;
    const float4 xv = *(const float4*)(x + (long)row*E_ + e);
    const float4 rv = *(const float4*)(r + (long)row*E_ + e);
    float t0 = xv.x + rv.x, t1 = xv.y + rv.y, t2 = xv.z + rv.z, t3 = xv.w + rv.w;

    float s = t0 + t1 + t2 + t3;
#pragma unroll
    for (int off = 16; off; off >>= 1) s += __shfl_xor_sync(0xffffffffu, s, off);
    if ((tid & 31) == 0) red[tid >> 5] = s;
    __syncthreads();
    float mean = (red[0]+red[1]+red[2]+red[3]) * (1.f/E_);
    __syncthreads();

    float d0 = t0-mean, d1 = t1-mean, d2 = t2-mean, d3 = t3-mean;
    float vs = d0*d0 + d1*d1 + d2*d2 + d3*d3;
#pragma unroll
    for (int off = 16; off; off >>= 1) vs += __shfl_xor_sync(0xffffffffu, vs, off);
    if ((tid & 31) == 0) red[tid >> 5] = vs;
    __syncthreads();
    float var = (red[0]+red[1]+red[2]+red[3]) * (1.f/E_);
    float rstd = rsqrtf(var + 1e-5f);

    float4 gg = *(const float4*)(g + e);
    float4 bb = *(const float4*)(bta + e);
    float v0 = d0*rstd*gg.x + bb.x, v1 = d1*rstd*gg.y + bb.y;
    float v2 = d2*rstd*gg.z + bb.z, v3 = d3*rstd*gg.w + bb.w;
    *(float4*)(out  + (long)row*E_ + e) = make_float4(v0, v1, v2, v3);
    *(float4*)(outr + (long)row*E_ + e) =
        make_float4(f2tff(v0), f2tff(v1), f2tff(v2), f2tff(v3));
}

// ---------------------------------------------------------------------------
// Mean over S (two-stage) + classifier
// ---------------------------------------------------------------------------
__global__ void mean_part_kernel(const float* __restrict__ x, float* __restrict__ part)
{
    int idx = blockIdx.x*256 + threadIdx.x;
    int b = idx >> 9;
    int e = idx & (E_-1);
    int c = blockIdx.y;
    const float* p = x + ((long)b*S_ + c*128)*E_ + e;
    float s = 0.f;
#pragma unroll 8
    for (int i = 0; i < 128; i++) s += p[(long)i*E_];
    part[c*(B_*E_) + idx] = s;
}

__global__ void mean_final_kernel(const float* __restrict__ part, float* __restrict__ mean)
{
    int idx = blockIdx.x*256 + threadIdx.x;
    float s = 0.f;
#pragma unroll
    for (int c = 0; c < 16; c++) s += part[c*(B_*E_) + idx];
    mean[idx] = s * (1.f/(float)S_);
}

__global__ __launch_bounds__(128)
void classify_kernel(const float* __restrict__ mean, const float* __restrict__ w,
                     const float* __restrict__ bias, float* __restrict__ out)
{
    __shared__ float red[4];
    int b = blockIdx.x >> 2;
    int c = blockIdx.x & 3;
    int tid = threadIdx.x;
    float s = 0.f;
    for (int e = tid; e < E_; e += 128) s += mean[b*E_ + e] * w[e*C_ + c];
#pragma unroll
    for (int off = 16; off; off >>= 1) s += __shfl_xor_sync(0xffffffffu, s, off);
    if ((tid & 31) == 0) red[tid >> 5] = s;
    __syncthreads();
    if (tid == 0) out[b*C_ + c] = red[0]+red[1]+red[2]+red[3] + bias[c];
}

// ---------------------------------------------------------------------------
// Launch
// ---------------------------------------------------------------------------
extern "C" void kernel_launch(void* const* d_in, const int* in_sizes, int n_in,
                              void* d_out, int out_size)
{
    const int*   tokens = (const int*)  d_in[0];
    const float* emb    = (const float*)d_in[1];
    const float* Wq     = (const float*)d_in[2];
    const float* Wk     = (const float*)d_in[3];
    const float* Wv     = (const float*)d_in[4];
    const float* Wo     = (const float*)d_in[5];
    const float* qh_w   = (const float*)d_in[6];
    const float* qh_b   = (const float*)d_in[7];
    const float* kh_w   = (const float*)d_in[8];
    const float* kh_b   = (const float*)d_in[9];
    const float* vh_w   = (const float*)d_in[10];
    const float* vh_b   = (const float*)d_in[11];
    const float* ln1_g  = (const float*)d_in[12];
    const float* ln1_b  = (const float*)d_in[13];
    const float* ln2_g  = (const float*)d_in[14];
    const float* ln2_b  = (const float*)d_in[15];
    const float* f_w1   = (const float*)d_in[16];
    const float* f_b1   = (const float*)d_in[17];
    const float* f_w2   = (const float*)d_in[18];
    const float* f_b2   = (const float*)d_in[19];
    const float* cls_w  = (const float*)d_in[20];
    const float* cls_b  = (const float*)d_in[21];

    float *x,*xr,*q,*k,*v,*ao,*p,*y,*yr,*ffn,*part,*mean,*wc,*weff,*beff,*w1t,*w2t,*wot;
    cudaGetSymbolAddress((void**)&x,    g_x);
    cudaGetSymbolAddress((void**)&xr,   g_xr);
    cudaGetSymbolAddress((void**)&q,    g_q);
    cudaGetSymbolAddress((void**)&k,    g_k);
    cudaGetSymbolAddress((void**)&v,    g_v);
    cudaGetSymbolAddress((void**)&ao,   g_ao);
    cudaGetSymbolAddress((void**)&p,    g_p);
    cudaGetSymbolAddress((void**)&y,    g_y);
    cudaGetSymbolAddress((void**)&yr,   g_yr);
    cudaGetSymbolAddress((void**)&ffn,  g_ffn);
    cudaGetSymbolAddress((void**)&part, g_part);
    cudaGetSymbolAddress((void**)&mean, g_mean);
    cudaGetSymbolAddress((void**)&wc,   g_wc);
    cudaGetSymbolAddress((void**)&weff, g_weff);
    cudaGetSymbolAddress((void**)&beff, g_beff);
    cudaGetSymbolAddress((void**)&w1t,  g_w1t);
    cudaGetSymbolAddress((void**)&w2t,  g_w2t);
    cudaGetSymbolAddress((void**)&wot,  g_wot);

    cudaFuncSetAttribute((const void*)flash_cp,
                         cudaFuncAttributeMaxDynamicSharedMemorySize, FLASH_SMEM);
    cudaFuncSetAttribute((const void*)sgemm_cp<true,false,true,false,true>,
                         cudaFuncAttributeMaxDynamicSharedMemorySize, GEMM_SMEM);
    cudaFuncSetAttribute((const void*)sgemm_cp<false,true,false,false,false>,
                         cudaFuncAttributeMaxDynamicSharedMemorySize, GEMM_SMEM);
    cudaFuncSetAttribute((const void*)sgemm_cp<false,false,true,true,true>,
                         cudaFuncAttributeMaxDynamicSharedMemorySize, GEMM_SMEM);
    cudaFuncSetAttribute((const void*)sgemm_cp<false,false,true,false,false>,
                         cudaFuncAttributeMaxDynamicSharedMemorySize, GEMM_SMEM);

    const int M = B_*S_;               // 8192
    const long ESQ = (long)E_*E_;
    dim3 gQKV(E_/128, M/128, 3);
    dim3 gProj(E_/128, M/128, 1);
    dim3 gFfn1(FF_/128, M/128, 1);
    dim3 gFlash(S_/128, B_*H_);

    // Precompute
    embed_kernel<<<M, 128>>>(tokens, emb, x, xr);
    qcombine_kernel<<<3*NB_*H_, 256>>>(qh_w, qh_b, kh_w, kh_b, vh_w, vh_b, wc, beff);
    qweff_kernel<<<dim3(8, H_, 3*NB_), 256>>>(Wq, Wk, Wv, wc, weff);
    tr_round_kernel<<<dim3(E_/32,  FF_/32, NB_), dim3(32,8)>>>(f_w1, w1t, E_,  FF_);
    tr_round_kernel<<<dim3(FF_/32, E_/32,  NB_), dim3(32,8)>>>(f_w2, w2t, FF_, E_);
    tr_round_kernel<<<dim3(E_/32,  E_/32,  NB_), dim3(32,8)>>>(Wo,   wot, E_,  E_);

    for (int i = 0; i < NB_; i++) {
        const float* Wo_i = wot + (long)i*ESQ;

        // fused QKV projection (quantum folded); V written [B,H,DK,S]
        sgemm_cp<true,false,true,false,true><<<gQKV, 256, GEMM_SMEM>>>(
            xr,
            weff + (0*NB_ + i)*ESQ, weff + (1*NB_ + i)*ESQ, weff + (2*NB_ + i)*ESQ,
            beff + (0*NB_ + i)*E_,  beff + (1*NB_ + i)*E_,  beff + (2*NB_ + i)*E_,
            q, k, v, M, E_, E_);

        // attention
        flash_cp<<<gFlash, 256, FLASH_SMEM>>>(q, k, v, ao);

        // output projection + residual + LN1
        sgemm_cp<false,true,false,false,false><<<gProj, 256, GEMM_SMEM>>>(
            ao, Wo_i, Wo_i, Wo_i, nullptr, nullptr, nullptr, p, p, p, M, E_, E_);
        add_ln_kernel<<<M, 128>>>(x, p, ln1_g + i*E_, ln1_b + i*E_, y, yr);

        // FFN + residual + LN2
        sgemm_cp<false,false,true,true,true><<<gFfn1, 256, GEMM_SMEM>>>(
            yr, w1t + (long)i*E_*FF_, w1t + (long)i*E_*FF_, w1t + (long)i*E_*FF_,
            f_b1 + i*FF_, f_b1 + i*FF_, f_b1 + i*FF_,
            ffn, ffn, ffn, M, FF_, E_);
        sgemm_cp<false,false,true,false,false><<<gProj, 256, GEMM_SMEM>>>(
            ffn, w2t + (long)i*FF_*E_, w2t + (long)i*FF_*E_, w2t + (long)i*FF_*E_,
            f_b2 + i*E_, f_b2 + i*E_, f_b2 + i*E_,
            p, p, p, M, E_, FF_);
        add_ln_kernel<<<M, 128>>>(y, p, ln2_g + i*E_, ln2_b + i*E_, x, xr);
    }

    mean_part_kernel<<<dim3((B_*E_)/256, 16), 256>>>(x, part);
    mean_final_kernel<<<(B_*E_)/256, 256>>>(part, mean);
    classify_kernel<<<B_*C_, 128>>>(mean, cls_w, cls_b, (float*)d_out);
}

// round 8
// speedup vs baseline: 4.6839x; 1.0275x over previous
#include <cuda_runtime.h>
#include <cuda_bf16.h>
#include <math.h>

// Problem constants
#define B_  4
#define S_  2048
#define E_  512
#define H_  8
#define DK_ 64
#define L_  2
#define NB_ 4
#define FF_ 2048
#define C_  4

// ---------------------------------------------------------------------------
// Scratch (device globals; no allocations anywhere)
// ---------------------------------------------------------------------------
__device__ float g_x  [B_*S_*E_];
__device__ float g_xr [B_*S_*E_];            // tf32-rounded copy of x
__device__ float g_q  [B_*S_*E_];
__device__ float g_k  [B_*S_*E_];
__device__ float g_v  [B_*S_*E_];            // V stored [B,H,DK,S] (d-major)
__device__ float g_ao [B_*S_*E_];
__device__ float g_p  [B_*S_*E_];
__device__ float g_y  [B_*S_*E_];
__device__ float g_yr [B_*S_*E_];            // tf32-rounded copy of y
__device__ float g_ffn[B_*S_*FF_];
__device__ float g_part[16*B_*E_];
__device__ float g_mean[B_*E_];
// folded quantum weights + transposed/rounded weights [N][K]
__device__ float g_wc  [3*NB_*H_*DK_*DK_];
__device__ float g_weff[3*NB_*E_*E_];        // QKV eff weights, [N][K], tf32
__device__ float g_beff[3*NB_*E_];
__device__ float g_w1t [NB_*FF_*E_];         // f_w1^T  [FF][E], tf32
__device__ float g_w2t [NB_*E_*FF_];         // f_w2^T  [E][FF], tf32
__device__ float g_wot [NB_*E_*E_];          // Wo^T    [E][E],  tf32

// ---------------------------------------------------------------------------
// Helpers
// ---------------------------------------------------------------------------
__device__ __forceinline__ void cpa16(void* dst, const void* src) {
    unsigned d = (unsigned)__cvta_generic_to_shared(dst);
    asm volatile("cp.async.cg.shared.global [%0], [%1], 16;" :: "r"(d), "l"(src));
}
__device__ __forceinline__ void cp_commit() { asm volatile("cp.async.commit_group;"); }
__device__ __forceinline__ void cp_wait0()  { asm volatile("cp.async.wait_group 0;"); }

__device__ __forceinline__ unsigned f2tf(float x) {
    unsigned r;
    asm("cvt.rna.tf32.f32 %0, %1;" : "=r"(r) : "f"(x));
    return r;
}
__device__ __forceinline__ float f2tff(float x) { return __uint_as_float(f2tf(x)); }

__device__ __forceinline__ void mma1688(float* c, const unsigned* a, unsigned b0, unsigned b1) {
    asm volatile(
        "mma.sync.aligned.m16n8k8.row.col.f32.tf32.tf32.f32 "
        "{%0,%1,%2,%3}, {%4,%5,%6,%7}, {%8,%9}, {%0,%1,%2,%3};"
        : "+f"(c[0]), "+f"(c[1]), "+f"(c[2]), "+f"(c[3])
        : "r"(a[0]), "r"(a[1]), "r"(a[2]), "r"(a[3]), "r"(b0), "r"(b1));
}

// x4 ldmatrix: for 32-bit data each matrix is an 8x4 block; thread i -> (i/4, i%4).
__device__ __forceinline__ void ldsm4(unsigned& a, unsigned& b, unsigned& c, unsigned& d,
                                      unsigned addr) {
    asm volatile("ldmatrix.sync.aligned.m8n8.x4.shared.b16 {%0,%1,%2,%3}, [%4];"
        : "=r"(a), "=r"(b), "=r"(c), "=r"(d) : "r"(addr));
}

// ---------------------------------------------------------------------------
// Embedding + positional encoding (dual output: fp32 + tf32-rounded)
// ---------------------------------------------------------------------------
__global__ void embed_kernel(const int* __restrict__ tok,
                             const float* __restrict__ emb,
                             float* __restrict__ x, float* __restrict__ xr)
{
    int row = blockIdx.x;
    int s   = row & (S_-1);
    int t   = tok[row];
    int e   = threadIdx.x * 4;
    float4 ev = *(const float4*)(emb + (long)t*E_ + e);
    float r[4] = {ev.x, ev.y, ev.z, ev.w};
#pragma unroll
    for (int c = 0; c < 4; c++) {
        int ee = e + c;
        int i2 = ee & ~1;
        float div = __expf((float)i2 * (-9.210340371976184f / (float)E_));
        float arg = (float)s * div;
        r[c] += (ee & 1) ? cosf(arg) : sinf(arg);
    }
    *(float4*)(x  + (long)row*E_ + e) = make_float4(r[0], r[1], r[2], r[3]);
    *(float4*)(xr + (long)row*E_ + e) =
        make_float4(f2tff(r[0]), f2tff(r[1]), f2tff(r[2]), f2tff(r[3]));
}

// ---------------------------------------------------------------------------
// Fold quantum linears: Wc[h] = W1[h]@W2[h], beff = b1@W2 + b2   (fp32)
// ---------------------------------------------------------------------------
__global__ __launch_bounds__(256)
void qcombine_kernel(const float* __restrict__ qw, const float* __restrict__ qb,
                     const float* __restrict__ kw, const float* __restrict__ kb,
                     const float* __restrict__ vw, const float* __restrict__ vb,
                     float* __restrict__ wc, float* __restrict__ beff)
{
    __shared__ float s1[64*65], s2[64*65];
    int blk = blockIdx.x;
    int t  = blk / (NB_*H_);
    int ih = blk % (NB_*H_);
    int i  = ih / H_, h = ih % H_;
    const float* w = t==0 ? qw : (t==1 ? kw : vw);
    const float* b = t==0 ? qb : (t==1 ? kb : vb);
    const float* W1 = w + ((long)(i*L_+0)*H_ + h)*DK_*DK_;
    const float* W2 = w + ((long)(i*L_+1)*H_ + h)*DK_*DK_;
    const float* b1 = b + ((long)(i*L_+0)*H_ + h)*DK_;
    const float* b2 = b + ((long)(i*L_+1)*H_ + h)*DK_;
    int tid = threadIdx.x;
    for (int idx = tid; idx < 4096; idx += 256) {
        int r = idx >> 6, c = idx & 63;
        s1[r*65+c] = W1[idx];
        s2[r*65+c] = W2[idx];
    }
    __syncthreads();
    float* wcp = wc + (long)blk*DK_*DK_;
    for (int idx = tid; idx < 4096; idx += 256) {
        int r = idx >> 6, c = idx & 63;
        float sum = 0.f;
#pragma unroll 8
        for (int d = 0; d < 64; d++) sum += s1[r*65+d]*s2[d*65+c];
        wcp[idx] = sum;
    }
    if (tid < 64) {
        float sum = b2[tid];
#pragma unroll 8
        for (int d = 0; d < 64; d++) sum += b1[d]*s2[d*65+tid];
        beff[((long)t*NB_ + i)*E_ + h*DK_ + tid] = sum;
    }
}

// ---------------------------------------------------------------------------
// Effective QKV weights, TRANSPOSED [N][K] + tf32-rounded
// ---------------------------------------------------------------------------
__global__ __launch_bounds__(256)
void qweff_kernel(const float* __restrict__ Wq, const float* __restrict__ Wk,
                  const float* __restrict__ Wv,
                  const float* __restrict__ wc, float* __restrict__ weff)
{
    __shared__ float wq_s[64*65];   // [k_local][d]
    __shared__ float wc_s[64*65];   // [d][n]
    int t = blockIdx.z / NB_, i = blockIdx.z % NB_;
    int h = blockIdx.y;
    int rb = blockIdx.x;            // 64-row block of K
    const float* Wsrc = (t==0 ? Wq : (t==1 ? Wk : Wv)) + (long)i*E_*E_;
    const float* Wcp  = wc + (long)((t*NB_ + i)*H_ + h)*DK_*DK_;
    float* out = weff + (long)(t*NB_ + i)*E_*E_;
    int tid = threadIdx.x;
    for (int idx = tid; idx < 64*64; idx += 256) {
        int r = idx >> 6, c = idx & 63;
        wq_s[r*65+c] = Wsrc[(long)(rb*64 + r)*E_ + h*64 + c];
        wc_s[r*65+c] = Wcp[idx];
    }
    __syncthreads();
    int kl = tid & 63;
    for (int nl = tid >> 6; nl < 64; nl += 4) {
        float sum = 0.f;
#pragma unroll 8
        for (int d = 0; d < 64; d++) sum += wq_s[kl*65+d]*wc_s[d*65+nl];
        out[(long)(h*64 + nl)*E_ + rb*64 + kl] = f2tff(sum);
    }
}

// ---------------------------------------------------------------------------
// Transpose + tf32-round: in [K][N] (per batch z) -> out [N][K]
// ---------------------------------------------------------------------------
__global__ void tr_round_kernel(const float* __restrict__ in, float* __restrict__ out,
                                int K, int N)
{
    __shared__ float t[32][33];
    int kb = blockIdx.x*32, nb = blockIdx.y*32;
    const float* inp = in  + (long)blockIdx.z*K*N;
    float*       oup = out + (long)blockIdx.z*K*N;
    int x = threadIdx.x, y0 = threadIdx.y;   // 32 x 8
#pragma unroll
    for (int dy = 0; dy < 32; dy += 8)
        t[y0+dy][x] = inp[(long)(kb+y0+dy)*N + nb + x];
    __syncthreads();
#pragma unroll
    for (int dy = 0; dy < 32; dy += 8)
        oup[(long)(nb+y0+dy)*K + kb + x] = f2tff(t[x][y0+dy]);
}

// ---------------------------------------------------------------------------
// TF32 GEMM: C[M,N] = A[M,K] @ BT[N,K]^T (+bias)(+relu)(+residual)
// ldmatrix operands, single-barrier cp.async pipeline, 2 CTAs/SM.
// z==2 with OUT_HEADT stores V transposed ([B,H,DK,S]).
// ---------------------------------------------------------------------------
#define ASTR 36
#define ABUF (128*ASTR)
#define GEMM_SMEM (ABUF*4*2*4)                // A + B, 2 stages: 73728 B

template<bool OUT_HEADT, bool IN_HEADT, bool BIAS, bool RELU, bool CVT_OUT, bool ADD_RES>
__global__ __launch_bounds__(256, 2)
void sgemm_cp(const float* __restrict__ A,
              const float* __restrict__ Bp0, const float* __restrict__ Bp1,
              const float* __restrict__ Bp2,
              const float* __restrict__ bi0, const float* __restrict__ bi1,
              const float* __restrict__ bi2,
              float* __restrict__ Cp0, float* __restrict__ Cp1,
              float* __restrict__ Cp2,
              const float* __restrict__ Rm,
              int M, int N, int K)
{
    extern __shared__ float sm[];
    int z = blockIdx.z;
    const float* Bm   = z==0 ? Bp0 : (z==1 ? Bp1 : Bp2);
    const float* bias = z==0 ? bi0 : (z==1 ? bi1 : bi2);
    float*       C    = z==0 ? Cp0 : (z==1 ? Cp1 : Cp2);

    float* Asb[2] = { sm,           sm + 2*ABUF };
    float* Bsb[2] = { sm + ABUF,    sm + 3*ABUF };

    int tid  = threadIdx.x;
    int lane = tid & 31;
    int w    = tid >> 5;
    int wm   = w & 1;
    int wn   = w >> 1;
    int n0 = blockIdx.x * 128;
    int m0 = blockIdx.y * 128;
    int r0 = lane >> 2;
    int kc = lane & 3;
    int mrow = lane & 7, msel = lane >> 3;

    int grow = tid >> 3;          // 0..31 (+t*32)
    int gcol = (tid & 7) * 4;     // 0..28

    auto copyA = [&](int k0, float* as) {
#pragma unroll
        for (int t = 0; t < 4; t++) {
            int r = grow + t*32;
            int kk = k0 + gcol;
            const float* src;
            if (IN_HEADT) {
                int mg = m0 + r;
                int b = mg >> 11, s = mg & (S_-1);
                int h = kk >> 6,  d = kk & (DK_-1);
                src = A + (((long)(b*H_ + h)*S_ + s)*DK_ + d);
            } else {
                src = A + (long)(m0 + r)*K + kk;
            }
            cpa16(as + r*ASTR + gcol, src);
        }
    };
    auto copyB = [&](int k0, float* bs) {
#pragma unroll
        for (int t = 0; t < 4; t++) {
            int r = grow + t*32;
            cpa16(bs + r*ASTR + gcol, Bm + (long)(n0 + r)*K + k0 + gcol);
        }
    };

    float acc[4][4][4];
#pragma unroll
    for (int i = 0; i < 4; i++)
#pragma unroll
        for (int j = 0; j < 4; j++)
#pragma unroll
            for (int q = 0; q < 4; q++) acc[i][j][q] = 0.f;

    int niter = K >> 5;
    copyA(0, Asb[0]); copyB(0, Bsb[0]); cp_commit();

    for (int it = 0; it < niter; it++) {
        cp_wait0();               // only the current tile's group is in flight
        __syncthreads();          // smem visible; prior-iter reads complete
        if (it + 1 < niter) {     // prefetch next tile (overlaps compute below)
            copyA((it+1) << 5, Asb[(it+1)&1]);
            copyB((it+1) << 5, Bsb[(it+1)&1]);
            cp_commit();
        }
        unsigned as_b = (unsigned)__cvta_generic_to_shared(Asb[it&1]);
        unsigned bs_b = (unsigned)__cvta_generic_to_shared(Bsb[it&1]);
        unsigned aoff = as_b + 4u*((wm*64 + mrow + (msel&1)*8)*ASTR + (msel>>1)*4);
        unsigned boff = bs_b + 4u*((wn*32 + mrow + (msel>>1)*8)*ASTR + (msel&1)*4);
#pragma unroll
        for (int ks = 0; ks < 4; ks++) {
            unsigned af[4][4], bf[4][2];
#pragma unroll
            for (int mt = 0; mt < 4; mt++)
                ldsm4(af[mt][0], af[mt][1], af[mt][2], af[mt][3],
                      aoff + 4u*(mt*16*ASTR + ks*8));
#pragma unroll
            for (int ntp = 0; ntp < 4; ntp += 2)
                ldsm4(bf[ntp][0], bf[ntp][1], bf[ntp+1][0], bf[ntp+1][1],
                      boff + 4u*(ntp*8*ASTR + ks*8));
#pragma unroll
            for (int mt = 0; mt < 4; mt++)
#pragma unroll
                for (int nt = 0; nt < 4; nt++)
                    mma1688(acc[mt][nt], af[mt], bf[nt][0], bf[nt][1]);
        }
    }

    // epilogue
#pragma unroll
    for (int mt = 0; mt < 4; mt++) {
#pragma unroll
        for (int nt = 0; nt < 4; nt++) {
            int c = n0 + wn*32 + nt*8 + kc*2;
            float bx = 0.f, by = 0.f;
            if (BIAS) { bx = bias[c]; by = bias[c+1]; }
#pragma unroll
            for (int half = 0; half < 2; half++) {
                int r = m0 + wm*64 + mt*16 + r0 + half*8;
                float vx = acc[mt][nt][half*2]   + bx;
                float vy = acc[mt][nt][half*2+1] + by;
                if (RELU) { vx = fmaxf(vx, 0.f); vy = fmaxf(vy, 0.f); }
                if (ADD_RES) {
                    float2 rr = *(const float2*)(Rm + (long)r*N + c);
                    vx += rr.x; vy += rr.y;
                }
                if (CVT_OUT) { vx = f2tff(vx); vy = f2tff(vy); }
                if (OUT_HEADT) {
                    int b = r >> 11, s = r & (S_-1);
                    int h = c >> 6,  d = c & (DK_-1);
                    if (z == 2) {   // V: store [B,H,DK,S]
                        float* dst = C + (((long)(b*H_ + h)*DK_ + d)*S_ + s);
                        dst[0]  = vx;
                        dst[S_] = vy;
                    } else {
                        *(float2*)(C + (((long)(b*H_ + h)*S_ + s)*DK_ + d)) =
                            make_float2(vx, vy);
                    }
                } else {
                    *(float2*)(C + (long)r*N + c) = make_float2(vx, vy);
                }
            }
        }
    }
}

// ---------------------------------------------------------------------------
// Flash attention, tf32 mma + ldmatrix, single-barrier cp.async, 2 CTA/SM.
// Q,K: [B,H,S,DK]; V: [B,H,DK,S]. All pre-rounded.
// ---------------------------------------------------------------------------
#define KSTR 68
#define VTSTR 68
#define PSTR 68
#define KBUF (64*KSTR)
#define VBUF (64*VTSTR)
#define FLASH_SMEM (((KBUF+VBUF)*2 + 128*PSTR) * 4)   // 104448 B

__global__ __launch_bounds__(256, 2)
void flash_cp(const float* __restrict__ Q, const float* __restrict__ K,
              const float* __restrict__ V, float* __restrict__ O)
{
    extern __shared__ float sm[];
    float* Ksb[2] = { sm,                      sm + KBUF + VBUF };
    float* Vsb[2] = { sm + KBUF,               sm + 2*KBUF + VBUF };
    float* Psh    = sm + 2*(KBUF + VBUF);      // [128][PSTR]

    int tid  = threadIdx.x;
    int lane = tid & 31;
    int w    = tid >> 5;
    int bh = blockIdx.y;
    int q0 = blockIdx.x * 128;
    int r0 = lane >> 2;
    int kc = lane & 3;
    int mrow = lane & 7, msel = lane >> 3;

    auto copyKV = [&](int k0, float* ks, float* vs) {
        const float* Kb = K + ((long)bh*S_ + k0)*DK_;
        const float* Vb = V + (long)bh*DK_*S_ + k0;
#pragma unroll
        for (int t = 0; t < 4; t++) {
            int idx = tid + t*256;
            int r = idx >> 4;
            int c = (idx & 15) * 4;
            cpa16(ks + r*KSTR  + c, Kb + r*DK_ + c);
            cpa16(vs + r*VTSTR + c, Vb + (long)r*S_ + c);
        }
    };

    // persistent Q fragments (pre-rounded; *0.125 exact)
    unsigned qa[8][4];
    const float* qbase = Q + ((long)bh*S_ + q0 + w*16)*DK_;
#pragma unroll
    for (int kt = 0; kt < 8; kt++) {
        qa[kt][0] = __float_as_uint(qbase[(r0    )*DK_ + kt*8 + kc    ] * 0.125f);
        qa[kt][1] = __float_as_uint(qbase[(r0 + 8)*DK_ + kt*8 + kc    ] * 0.125f);
        qa[kt][2] = __float_as_uint(qbase[(r0    )*DK_ + kt*8 + kc + 4] * 0.125f);
        qa[kt][3] = __float_as_uint(qbase[(r0 + 8)*DK_ + kt*8 + kc + 4] * 0.125f);
    }

    float o[8][4];
#pragma unroll
    for (int nt = 0; nt < 8; nt++)
#pragma unroll
        for (int q = 0; q < 4; q++) o[nt][q] = 0.f;
    float m0 = -1e30f, m1 = -1e30f, l0 = 0.f, l1 = 0.f;

    unsigned p_base = (unsigned)__cvta_generic_to_shared(Psh);
    unsigned poff = p_base + 4u*((w*16 + mrow + (msel&1)*8)*PSTR + (msel>>1)*4);

    const int niter = S_ / 64;
    copyKV(0, Ksb[0], Vsb[0]); cp_commit();

    for (int it = 0; it < niter; it++) {
        cp_wait0();
        __syncthreads();
        if (it + 1 < niter) {
            copyKV((it+1)*64, Ksb[(it+1)&1], Vsb[(it+1)&1]);
            cp_commit();
        }
        unsigned ks_b = (unsigned)__cvta_generic_to_shared(Ksb[it&1]);
        unsigned vs_b = (unsigned)__cvta_generic_to_shared(Vsb[it&1]);
        unsigned koff = ks_b + 4u*((mrow + (msel>>1)*8)*KSTR  + (msel&1)*4);
        unsigned voff = vs_b + 4u*((mrow + (msel>>1)*8)*VTSTR + (msel&1)*4);

        // S = Q K^T (warp: 16x64)
        float sc[8][4];
#pragma unroll
        for (int nt = 0; nt < 8; nt++)
#pragma unroll
            for (int q = 0; q < 4; q++) sc[nt][q] = 0.f;

#pragma unroll
        for (int kt = 0; kt < 8; kt++) {
            unsigned b0[8], b1[8];
#pragma unroll
            for (int ntp = 0; ntp < 8; ntp += 2)
                ldsm4(b0[ntp], b1[ntp], b0[ntp+1], b1[ntp+1],
                      koff + 4u*(ntp*8*KSTR + kt*8));
#pragma unroll
            for (int nt = 0; nt < 8; nt++)
                mma1688(sc[nt], qa[kt], b0[nt], b1[nt]);
        }

        // online softmax (rows r0 and r0+8)
        float tm0 = -1e30f, tm1 = -1e30f;
#pragma unroll
        for (int nt = 0; nt < 8; nt++) {
            tm0 = fmaxf(tm0, fmaxf(sc[nt][0], sc[nt][1]));
            tm1 = fmaxf(tm1, fmaxf(sc[nt][2], sc[nt][3]));
        }
        tm0 = fmaxf(tm0, __shfl_xor_sync(0xffffffffu, tm0, 1));
        tm0 = fmaxf(tm0, __shfl_xor_sync(0xffffffffu, tm0, 2));
        tm1 = fmaxf(tm1, __shfl_xor_sync(0xffffffffu, tm1, 1));
        tm1 = fmaxf(tm1, __shfl_xor_sync(0xffffffffu, tm1, 2));

        float mn0 = fmaxf(m0, tm0), mn1 = fmaxf(m1, tm1);
        float c0 = __expf(m0 - mn0), c1 = __expf(m1 - mn1);
        l0 *= c0; l1 *= c1;

        float s0 = 0.f, s1 = 0.f;
#pragma unroll
        for (int nt = 0; nt < 8; nt++) {
            float p0 = __expf(sc[nt][0] - mn0);
            float p1 = __expf(sc[nt][1] - mn0);
            float p2 = __expf(sc[nt][2] - mn1);
            float p3 = __expf(sc[nt][3] - mn1);
            s0 += p0 + p1; s1 += p2 + p3;
            o[nt][0] *= c0; o[nt][1] *= c0; o[nt][2] *= c1; o[nt][3] *= c1;
            *(float2*)&Psh[(w*16 + r0    )*PSTR + nt*8 + kc*2] =
                make_float2(f2tff(p0), f2tff(p1));
            *(float2*)&Psh[(w*16 + r0 + 8)*PSTR + nt*8 + kc*2] =
                make_float2(f2tff(p2), f2tff(p3));
        }
        s0 += __shfl_xor_sync(0xffffffffu, s0, 1);
        s0 += __shfl_xor_sync(0xffffffffu, s0, 2);
        s1 += __shfl_xor_sync(0xffffffffu, s1, 1);
        s1 += __shfl_xor_sync(0xffffffffu, s1, 2);
        l0 += s0; l1 += s1;
        m0 = mn0; m1 = mn1;

        __syncwarp();   // P stripe is warp-private

        // O += P V
#pragma unroll
        for (int kt = 0; kt < 8; kt++) {
            unsigned pa[4];
            ldsm4(pa[0], pa[1], pa[2], pa[3], poff + 4u*(kt*8));
            unsigned v0[8], v1[8];
#pragma unroll
            for (int ntp = 0; ntp < 8; ntp += 2)
                ldsm4(v0[ntp], v1[ntp], v0[ntp+1], v1[ntp+1],
                      voff + 4u*(ntp*8*VTSTR + kt*8));
#pragma unroll
            for (int nt = 0; nt < 8; nt++)
                mma1688(o[nt], pa, v0[nt], v1[nt]);
        }
    }

    float i0 = 1.f / l0, i1 = 1.f / l1;
    float* ob = O + ((long)bh*S_ + q0 + w*16)*DK_;
#pragma unroll
    for (int nt = 0; nt < 8; nt++) {
        *(float2*)&ob[(r0    )*DK_ + nt*8 + kc*2] =
            make_float2(f2tff(o[nt][0]*i0), f2tff(o[nt][1]*i0));
        *(float2*)&ob[(r0 + 8)*DK_ + nt*8 + kc*2] =
            make_float2(f2tff(o[nt][2]*i1), f2tff(o[nt][3]*i1));
    }
}

// ---------------------------------------------------------------------------
// out = LayerNorm(in) * g + b  — dual output (fp32 + tf32-rounded)
// (residual add already fused into the producing GEMM's epilogue)
// ---------------------------------------------------------------------------
__global__ __launch_bounds__(128)
void ln_dual_kernel(const float* __restrict__ in,
                    const float* __restrict__ g, const float* __restrict__ bta,
                    float* __restrict__ out, float* __restrict__ outr)
{
    __shared__ float red[4];
    int row = blockIdx.x;
    int tid = threadIdx.x;
    int e = tid * 4;
    const float4 xv = *(const float4*)(in + (long)row*E_ + e);
    float t0 = xv.x, t1 = xv.y, t2 = xv.z, t3 = xv.w;

    float s = t0 + t1 + t2 + t3;
#pragma unroll
    for (int off = 16; off; off >>= 1) s += __shfl_xor_sync(0xffffffffu, s, off);
    if ((tid & 31) == 0) red[tid >> 5] = s;
    __syncthreads();
    float mean = (red[0]+red[1]+red[2]+red[3]) * (1.f/E_);
    __syncthreads();

    float d0 = t0-mean, d1 = t1-mean, d2 = t2-mean, d3 = t3-mean;
    float vs = d0*d0 + d1*d1 + d2*d2 + d3*d3;
#pragma unroll
    for (int off = 16; off; off >>= 1) vs += __shfl_xor_sync(0xffffffffu, vs, off);
    if ((tid & 31) == 0) red[tid >> 5] = vs;
    __syncthreads();
    float var = (red[0]+red[1]+red[2]+red[3]) * (1.f/E_);
    float rstd = rsqrtf(var + 1e-5f);

    float4 gg = *(const float4*)(g + e);
    float4 bb = *(const float4*)(bta + e);
    float v0 = d0*rstd*gg.x + bb.x, v1 = d1*rstd*gg.y + bb.y;
    float v2 = d2*rstd*gg.z + bb.z, v3 = d3*rstd*gg.w + bb.w;
    *(float4*)(out  + (long)row*E_ + e) = make_float4(v0, v1, v2, v3);
    *(float4*)(outr + (long)row*E_ + e) =
        make_float4(f2tff(v0), f2tff(v1), f2tff(v2), f2tff(v3));
}

// ---------------------------------------------------------------------------
// Mean over S (two-stage) + classifier
// ---------------------------------------------------------------------------
__global__ void mean_part_kernel(const float* __restrict__ x, float* __restrict__ part)
{
    int idx = blockIdx.x*256 + threadIdx.x;
    int b = idx >> 9;
    int e = idx & (E_-1);
    int c = blockIdx.y;
    const float* p = x + ((long)b*S_ + c*128)*E_ + e;
    float s = 0.f;
#pragma unroll 8
    for (int i = 0; i < 128; i++) s += p[(long)i*E_];
    part[c*(B_*E_) + idx] = s;
}

__global__ void mean_final_kernel(const float* __restrict__ part, float* __restrict__ mean)
{
    int idx = blockIdx.x*256 + threadIdx.x;
    float s = 0.f;
#pragma unroll
    for (int c = 0; c < 16; c++) s += part[c*(B_*E_) + idx];
    mean[idx] = s * (1.f/(float)S_);
}

__global__ __launch_bounds__(128)
void classify_kernel(const float* __restrict__ mean, const float* __restrict__ w,
                     const float* __restrict__ bias, float* __restrict__ out)
{
    __shared__ float red[4];
    int b = blockIdx.x >> 2;
    int c = blockIdx.x & 3;
    int tid = threadIdx.x;
    float s = 0.f;
    for (int e = tid; e < E_; e += 128) s += mean[b*E_ + e] * w[e*C_ + c];
#pragma unroll
    for (int off = 16; off; off >>= 1) s += __shfl_xor_sync(0xffffffffu, s, off);
    if ((tid & 31) == 0) red[tid >> 5] = s;
    __syncthreads();
    if (tid == 0) out[b*C_ + c] = red[0]+red[1]+red[2]+red[3] + bias[c];
}

// ---------------------------------------------------------------------------
// Launch
// ---------------------------------------------------------------------------
extern "C" void kernel_launch(void* const* d_in, const int* in_sizes, int n_in,
                              void* d_out, int out_size)
{
    const int*   tokens = (const int*)  d_in[0];
    const float* emb    = (const float*)d_in[1];
    const float* Wq     = (const float*)d_in[2];
    const float* Wk     = (const float*)d_in[3];
    const float* Wv     = (const float*)d_in[4];
    const float* Wo     = (const float*)d_in[5];
    const float* qh_w   = (const float*)d_in[6];
    const float* qh_b   = (const float*)d_in[7];
    const float* kh_w   = (const float*)d_in[8];
    const float* kh_b   = (const float*)d_in[9];
    const float* vh_w   = (const float*)d_in[10];
    const float* vh_b   = (const float*)d_in[11];
    const float* ln1_g  = (const float*)d_in[12];
    const float* ln1_b  = (const float*)d_in[13];
    const float* ln2_g  = (const float*)d_in[14];
    const float* ln2_b  = (const float*)d_in[15];
    const float* f_w1   = (const float*)d_in[16];
    const float* f_b1   = (const float*)d_in[17];
    const float* f_w2   = (const float*)d_in[18];
    const float* f_b2   = (const float*)d_in[19];
    const float* cls_w  = (const float*)d_in[20];
    const float* cls_b  = (const float*)d_in[21];

    float *x,*xr,*q,*k,*v,*ao,*p,*y,*yr,*ffn,*part,*mean,*wc,*weff,*beff,*w1t,*w2t,*wot;
    cudaGetSymbolAddress((void**)&x,    g_x);
    cudaGetSymbolAddress((void**)&xr,   g_xr);
    cudaGetSymbolAddress((void**)&q,    g_q);
    cudaGetSymbolAddress((void**)&k,    g_k);
    cudaGetSymbolAddress((void**)&v,    g_v);
    cudaGetSymbolAddress((void**)&ao,   g_ao);
    cudaGetSymbolAddress((void**)&p,    g_p);
    cudaGetSymbolAddress((void**)&y,    g_y);
    cudaGetSymbolAddress((void**)&yr,   g_yr);
    cudaGetSymbolAddress((void**)&ffn,  g_ffn);
    cudaGetSymbolAddress((void**)&part, g_part);
    cudaGetSymbolAddress((void**)&mean, g_mean);
    cudaGetSymbolAddress((void**)&wc,   g_wc);
    cudaGetSymbolAddress((void**)&weff, g_weff);
    cudaGetSymbolAddress((void**)&beff, g_beff);
    cudaGetSymbolAddress((void**)&w1t,  g_w1t);
    cudaGetSymbolAddress((void**)&w2t,  g_w2t);
    cudaGetSymbolAddress((void**)&wot,  g_wot);

    cudaFuncSetAttribute((const void*)flash_cp,
                         cudaFuncAttributeMaxDynamicSharedMemorySize, FLASH_SMEM);
    cudaFuncSetAttribute((const void*)sgemm_cp<true,false,true,false,true,false>,
                         cudaFuncAttributeMaxDynamicSharedMemorySize, GEMM_SMEM);
    cudaFuncSetAttribute((const void*)sgemm_cp<false,true,false,false,false,true>,
                         cudaFuncAttributeMaxDynamicSharedMemorySize, GEMM_SMEM);
    cudaFuncSetAttribute((const void*)sgemm_cp<false,false,true,true,true,false>,
                         cudaFuncAttributeMaxDynamicSharedMemorySize, GEMM_SMEM);
    cudaFuncSetAttribute((const void*)sgemm_cp<false,false,true,false,false,true>,
                         cudaFuncAttributeMaxDynamicSharedMemorySize, GEMM_SMEM);

    const int M = B_*S_;               // 8192
    const long ESQ = (long)E_*E_;
    dim3 gQKV(E_/128, M/128, 3);
    dim3 gProj(E_/128, M/128, 1);
    dim3 gFfn1(FF_/128, M/128, 1);
    dim3 gFlash(S_/128, B_*H_);

    // Precompute
    embed_kernel<<<M, 128>>>(tokens, emb, x, xr);
    qcombine_kernel<<<3*NB_*H_, 256>>>(qh_w, qh_b, kh_w, kh_b, vh_w, vh_b, wc, beff);
    qweff_kernel<<<dim3(8, H_, 3*NB_), 256>>>(Wq, Wk, Wv, wc, weff);
    tr_round_kernel<<<dim3(E_/32,  FF_/32, NB_), dim3(32,8)>>>(f_w1, w1t, E_,  FF_);
    tr_round_kernel<<<dim3(FF_/32, E_/32,  NB_), dim3(32,8)>>>(f_w2, w2t, FF_, E_);
    tr_round_kernel<<<dim3(E_/32,  E_/32,  NB_), dim3(32,8)>>>(Wo,   wot, E_,  E_);

    for (int i = 0; i < NB_; i++) {
        const float* Wo_i = wot + (long)i*ESQ;

        // fused QKV projection (quantum folded); V written [B,H,DK,S]
        sgemm_cp<true,false,true,false,true,false><<<gQKV, 256, GEMM_SMEM>>>(
            xr,
            weff + (0*NB_ + i)*ESQ, weff + (1*NB_ + i)*ESQ, weff + (2*NB_ + i)*ESQ,
            beff + (0*NB_ + i)*E_,  beff + (1*NB_ + i)*E_,  beff + (2*NB_ + i)*E_,
            q, k, v, nullptr, M, E_, E_);

        // attention
        flash_cp<<<gFlash, 256, FLASH_SMEM>>>(q, k, v, ao);

        // output projection + residual(x) fused; then LN1
        sgemm_cp<false,true,false,false,false,true><<<gProj, 256, GEMM_SMEM>>>(
            ao, Wo_i, Wo_i, Wo_i, nullptr, nullptr, nullptr, p, p, p, x, M, E_, E_);
        ln_dual_kernel<<<M, 128>>>(p, ln1_g + i*E_, ln1_b + i*E_, y, yr);

        // FFN + residual(y) fused + LN2
        sgemm_cp<false,false,true,true,true,false><<<gFfn1, 256, GEMM_SMEM>>>(
            yr, w1t + (long)i*E_*FF_, w1t + (long)i*E_*FF_, w1t + (long)i*E_*FF_,
            f_b1 + i*FF_, f_b1 + i*FF_, f_b1 + i*FF_,
            ffn, ffn, ffn, nullptr, M, FF_, E_);
        sgemm_cp<false,false,true,false,false,true><<<gProj, 256, GEMM_SMEM>>>(
            ffn, w2t + (long)i*FF_*E_, w2t + (long)i*FF_*E_, w2t + (long)i*FF_*E_,
            f_b2 + i*E_, f_b2 + i*E_, f_b2 + i*E_,
            p, p, p, y, M, E_, FF_);
        ln_dual_kernel<<<M, 128>>>(p, ln2_g + i*E_, ln2_b + i*E_, x, xr);
    }

    mean_part_kernel<<<dim3((B_*E_)/256, 16), 256>>>(x, part);
    mean_final_kernel<<<(B_*E_)/256, 256>>>(part, mean);
    classify_kernel<<<B_*C_, 128>>>(mean, cls_w, cls_b, (float*)d_out);
}

// round 10
// speedup vs baseline: 6.2727x; 1.3392x over previous
#include <cuda_runtime.h>
#include <cuda_fp16.h>
#include <cuda_bf16.h>
#include <math.h>

// Problem constants
#define B_  4
#define S_  2048
#define E_  512
#define H_  8
#define DK_ 64
#define L_  2
#define NB_ 4
#define FF_ 2048
#define C_  4

typedef __half hf;

// ---------------------------------------------------------------------------
// Scratch (device globals; no allocations anywhere)
// ---------------------------------------------------------------------------
__device__ float g_x  [B_*S_*E_];
__device__ hf    g_xr [B_*S_*E_];            // fp16 copy of x (GEMM A input)
__device__ float g_q  [B_*S_*E_];
__device__ float g_k  [B_*S_*E_];
__device__ float g_v  [B_*S_*E_];            // V stored [B,H,DK,S] (d-major)
__device__ hf    g_ao [B_*S_*E_];            // flash out, flat [M][E] fp16
__device__ float g_p  [B_*S_*E_];
__device__ float g_y  [B_*S_*E_];
__device__ hf    g_yr [B_*S_*E_];            // fp16 copy of y
__device__ hf    g_ffn[B_*S_*FF_];           // FFN hidden, fp16
__device__ float g_part[16*B_*E_];
__device__ float g_mean[B_*E_];
// folded quantum weights + transposed fp16 weights [N][K]
__device__ float g_wc  [3*NB_*H_*DK_*DK_];
__device__ hf    g_weff[3*NB_*E_*E_];        // QKV eff weights, [N][K]
__device__ float g_beff[3*NB_*E_];
__device__ hf    g_w1t [NB_*FF_*E_];         // f_w1^T  [FF][E]
__device__ hf    g_w2t [NB_*E_*FF_];         // f_w2^T  [E][FF]
__device__ hf    g_wot [NB_*E_*E_];          // Wo^T    [E][E]

// ---------------------------------------------------------------------------
// Helpers
// ---------------------------------------------------------------------------
__device__ __forceinline__ void cpa16(void* dst, const void* src) {
    unsigned d = (unsigned)__cvta_generic_to_shared(dst);
    asm volatile("cp.async.cg.shared.global [%0], [%1], 16;" :: "r"(d), "l"(src));
}
__device__ __forceinline__ void cp_commit() { asm volatile("cp.async.commit_group;"); }
__device__ __forceinline__ void cp_wait0()  { asm volatile("cp.async.wait_group 0;"); }

__device__ __forceinline__ unsigned f2tf(float x) {
    unsigned r;
    asm("cvt.rna.tf32.f32 %0, %1;" : "=r"(r) : "f"(x));
    return r;
}
__device__ __forceinline__ float f2tff(float x) { return __uint_as_float(f2tf(x)); }

// tf32 mma (flash attention)
__device__ __forceinline__ void mma1688(float* c, const unsigned* a, unsigned b0, unsigned b1) {
    asm volatile(
        "mma.sync.aligned.m16n8k8.row.col.f32.tf32.tf32.f32 "
        "{%0,%1,%2,%3}, {%4,%5,%6,%7}, {%8,%9}, {%0,%1,%2,%3};"
        : "+f"(c[0]), "+f"(c[1]), "+f"(c[2]), "+f"(c[3])
        : "r"(a[0]), "r"(a[1]), "r"(a[2]), "r"(a[3]), "r"(b0), "r"(b1));
}
// fp16 mma (GEMMs): K=16 per instruction, fp32 accumulate
__device__ __forceinline__ void mma16816h(float* c, const unsigned* a, unsigned b0, unsigned b1) {
    asm volatile(
        "mma.sync.aligned.m16n8k16.row.col.f32.f16.f16.f32 "
        "{%0,%1,%2,%3}, {%4,%5,%6,%7}, {%8,%9}, {%0,%1,%2,%3};"
        : "+f"(c[0]), "+f"(c[1]), "+f"(c[2]), "+f"(c[3])
        : "r"(a[0]), "r"(a[1]), "r"(a[2]), "r"(a[3]), "r"(b0), "r"(b1));
}

__device__ __forceinline__ void ldsm4(unsigned& a, unsigned& b, unsigned& c, unsigned& d,
                                      unsigned addr) {
    asm volatile("ldmatrix.sync.aligned.m8n8.x4.shared.b16 {%0,%1,%2,%3}, [%4];"
        : "=r"(a), "=r"(b), "=r"(c), "=r"(d) : "r"(addr));
}

__device__ __forceinline__ __half2 h2(float a, float b) {
    return __halves2half2(__float2half_rn(a), __float2half_rn(b));
}

// ---------------------------------------------------------------------------
// Embedding + positional encoding (fp32 + fp16 copies)
// ---------------------------------------------------------------------------
__global__ void embed_kernel(const int* __restrict__ tok,
                             const float* __restrict__ emb,
                             float* __restrict__ x, hf* __restrict__ xr)
{
    int row = blockIdx.x;
    int s   = row & (S_-1);
    int t   = tok[row];
    int e   = threadIdx.x * 4;
    float4 ev = *(const float4*)(emb + (long)t*E_ + e);
    float r[4] = {ev.x, ev.y, ev.z, ev.w};
#pragma unroll
    for (int c = 0; c < 4; c++) {
        int ee = e + c;
        int i2 = ee & ~1;
        float div = __expf((float)i2 * (-9.210340371976184f / (float)E_));
        float arg = (float)s * div;
        r[c] += (ee & 1) ? cosf(arg) : sinf(arg);
    }
    *(float4*)(x + (long)row*E_ + e) = make_float4(r[0], r[1], r[2], r[3]);
    hf* xo = xr + (long)row*E_ + e;
    *(__half2*)(xo)     = h2(r[0], r[1]);
    *(__half2*)(xo + 2) = h2(r[2], r[3]);
}

// ---------------------------------------------------------------------------
// Fold quantum linears: Wc[h] = W1[h]@W2[h], beff = b1@W2 + b2   (fp32)
// ---------------------------------------------------------------------------
__global__ __launch_bounds__(256)
void qcombine_kernel(const float* __restrict__ qw, const float* __restrict__ qb,
                     const float* __restrict__ kw, const float* __restrict__ kb,
                     const float* __restrict__ vw, const float* __restrict__ vb,
                     float* __restrict__ wc, float* __restrict__ beff)
{
    __shared__ float s1[64*65], s2[64*65];
    int blk = blockIdx.x;
    int t  = blk / (NB_*H_);
    int ih = blk % (NB_*H_);
    int i  = ih / H_, h = ih % H_;
    const float* w = t==0 ? qw : (t==1 ? kw : vw);
    const float* b = t==0 ? qb : (t==1 ? kb : vb);
    const float* W1 = w + ((long)(i*L_+0)*H_ + h)*DK_*DK_;
    const float* W2 = w + ((long)(i*L_+1)*H_ + h)*DK_*DK_;
    const float* b1 = b + ((long)(i*L_+0)*H_ + h)*DK_;
    const float* b2 = b + ((long)(i*L_+1)*H_ + h)*DK_;
    int tid = threadIdx.x;
    for (int idx = tid; idx < 4096; idx += 256) {
        int r = idx >> 6, c = idx & 63;
        s1[r*65+c] = W1[idx];
        s2[r*65+c] = W2[idx];
    }
    __syncthreads();
    float* wcp = wc + (long)blk*DK_*DK_;
    for (int idx = tid; idx < 4096; idx += 256) {
        int r = idx >> 6, c = idx & 63;
        float sum = 0.f;
#pragma unroll 8
        for (int d = 0; d < 64; d++) sum += s1[r*65+d]*s2[d*65+c];
        wcp[idx] = sum;
    }
    if (tid < 64) {
        float sum = b2[tid];
#pragma unroll 8
        for (int d = 0; d < 64; d++) sum += b1[d]*s2[d*65+tid];
        beff[((long)t*NB_ + i)*E_ + h*DK_ + tid] = sum;
    }
}

// ---------------------------------------------------------------------------
// Effective QKV weights, TRANSPOSED [N][K], fp16
// ---------------------------------------------------------------------------
__global__ __launch_bounds__(256)
void qweff_kernel(const float* __restrict__ Wq, const float* __restrict__ Wk,
                  const float* __restrict__ Wv,
                  const float* __restrict__ wc, hf* __restrict__ weff)
{
    __shared__ float wq_s[64*65];   // [k_local][d]
    __shared__ float wc_s[64*65];   // [d][n]
    int t = blockIdx.z / NB_, i = blockIdx.z % NB_;
    int h = blockIdx.y;
    int rb = blockIdx.x;            // 64-row block of K
    const float* Wsrc = (t==0 ? Wq : (t==1 ? Wk : Wv)) + (long)i*E_*E_;
    const float* Wcp  = wc + (long)((t*NB_ + i)*H_ + h)*DK_*DK_;
    hf* out = weff + (long)(t*NB_ + i)*E_*E_;
    int tid = threadIdx.x;
    for (int idx = tid; idx < 64*64; idx += 256) {
        int r = idx >> 6, c = idx & 63;
        wq_s[r*65+c] = Wsrc[(long)(rb*64 + r)*E_ + h*64 + c];
        wc_s[r*65+c] = Wcp[idx];
    }
    __syncthreads();
    int kl = tid & 63;
    for (int nl = tid >> 6; nl < 64; nl += 4) {
        float sum = 0.f;
#pragma unroll 8
        for (int d = 0; d < 64; d++) sum += wq_s[kl*65+d]*wc_s[d*65+nl];
        out[(long)(h*64 + nl)*E_ + rb*64 + kl] = __float2half_rn(sum);
    }
}

// ---------------------------------------------------------------------------
// Transpose + fp16 round: in [K][N] (per batch z) -> out [N][K] fp16
// ---------------------------------------------------------------------------
__global__ void tr_f16_kernel(const float* __restrict__ in, hf* __restrict__ out,
                              int K, int N)
{
    __shared__ float t[32][33];
    int kb = blockIdx.x*32, nb = blockIdx.y*32;
    const float* inp = in  + (long)blockIdx.z*K*N;
    hf*          oup = out + (long)blockIdx.z*K*N;
    int x = threadIdx.x, y0 = threadIdx.y;   // 32 x 8
#pragma unroll
    for (int dy = 0; dy < 32; dy += 8)
        t[y0+dy][x] = inp[(long)(kb+y0+dy)*N + nb + x];
    __syncthreads();
#pragma unroll
    for (int dy = 0; dy < 32; dy += 8)
        oup[(long)(nb+y0+dy)*K + kb + x] = __float2half_rn(t[x][y0+dy]);
}

// ---------------------------------------------------------------------------
// FP16 GEMM: C[M,N] = A[M,K] @ BT[N,K]^T (+bias)(+relu)(+residual)
// mma.m16n8k16.f16, ldmatrix operands, single-barrier cp.async, 2 CTAs/SM.
// A: fp16 [M][K]; BT: fp16 [N][K]. Output fp32 (optionally tf32-rounded,
// optionally +residual, optionally head-permuted w/ V transpose) or fp16 flat.
// ---------------------------------------------------------------------------
#define AH 40                                  // fp16 smem stride (80B = 5*16B)
#define HBUF (128*AH)                          // fp16 units per tile buffer
#define GEMM_SMEM (4*HBUF*2)                   // 2 stages x (A+B): 40960 B

template<bool OUT_HEADT, bool BIAS, bool RELU, bool CVT_OUT, bool OUT_F16, bool ADD_RES>
__global__ __launch_bounds__(256, 2)
void sgemm_hf(const hf* __restrict__ A,
              const hf* __restrict__ Bp0, const hf* __restrict__ Bp1,
              const hf* __restrict__ Bp2,
              const float* __restrict__ bi0, const float* __restrict__ bi1,
              const float* __restrict__ bi2,
              void* __restrict__ Cp0, void* __restrict__ Cp1,
              void* __restrict__ Cp2,
              const float* __restrict__ Rm,
              int M, int N, int K)
{
    extern __shared__ hf smh[];
    int z = blockIdx.z;
    const hf*    Bm   = z==0 ? Bp0 : (z==1 ? Bp1 : Bp2);
    const float* bias = z==0 ? bi0 : (z==1 ? bi1 : bi2);
    void*        C    = z==0 ? Cp0 : (z==1 ? Cp1 : Cp2);

    hf* Asb[2] = { smh,            smh + 2*HBUF };
    hf* Bsb[2] = { smh + HBUF,     smh + 3*HBUF };

    int tid  = threadIdx.x;
    int lane = tid & 31;
    int w    = tid >> 5;
    int wm   = w & 1;
    int wn   = w >> 1;
    int n0 = blockIdx.x * 128;
    int m0 = blockIdx.y * 128;
    int r0 = lane >> 2;
    int kc = lane & 3;

    auto copyA = [&](int k0, hf* as) {
#pragma unroll
        for (int t = 0; t < 2; t++) {
            int c = tid*2 + t;
            int r = c >> 2;
            int col = (c & 3) * 8;
            cpa16(as + r*AH + col, A + (long)(m0 + r)*K + k0 + col);
        }
    };
    auto copyB = [&](int k0, hf* bs) {
#pragma unroll
        for (int t = 0; t < 2; t++) {
            int c = tid*2 + t;
            int r = c >> 2;
            int col = (c & 3) * 8;
            cpa16(bs + r*AH + col, Bm + (long)(n0 + r)*K + k0 + col);
        }
    };

    float acc[4][4][4];
#pragma unroll
    for (int i = 0; i < 4; i++)
#pragma unroll
        for (int j = 0; j < 4; j++)
#pragma unroll
            for (int q = 0; q < 4; q++) acc[i][j][q] = 0.f;

    int niter = K >> 5;                        // BK=32
    copyA(0, Asb[0]); copyB(0, Bsb[0]); cp_commit();

    int arow = lane & 15, asel = lane >> 4;
    int g = lane >> 3;

    for (int it = 0; it < niter; it++) {
        cp_wait0();
        __syncthreads();
        if (it + 1 < niter) {
            copyA((it+1) << 5, Asb[(it+1)&1]);
            copyB((it+1) << 5, Bsb[(it+1)&1]);
            cp_commit();
        }
        unsigned as_b = (unsigned)__cvta_generic_to_shared(Asb[it&1]);
        unsigned bs_b = (unsigned)__cvta_generic_to_shared(Bsb[it&1]);
        // A: 16x16 tiles; rows lane%16, +16B for k8-15 half
        unsigned aoff = as_b + 2u*((wm*64 + arow)*AH) + asel*16u;
        // B: two n-octets per ldsm4; groups (oct, khalf)
        unsigned boff = bs_b + 2u*((wn*32 + (g>>1)*8 + (lane&7))*AH) + (g&1)*16u;
#pragma unroll
        for (int ks = 0; ks < 2; ks++) {       // two k16 steps per BK=32
            unsigned af[4][4], bf2[4][2];
#pragma unroll
            for (int mt = 0; mt < 4; mt++)
                ldsm4(af[mt][0], af[mt][1], af[mt][2], af[mt][3],
                      aoff + 2u*(mt*16*AH) + ks*32u);
#pragma unroll
            for (int ntp = 0; ntp < 4; ntp += 2)
                ldsm4(bf2[ntp][0], bf2[ntp][1], bf2[ntp+1][0], bf2[ntp+1][1],
                      boff + 2u*(ntp*8*AH) + ks*32u);
#pragma unroll
            for (int mt = 0; mt < 4; mt++)
#pragma unroll
                for (int nt = 0; nt < 4; nt++)
                    mma16816h(acc[mt][nt], af[mt], bf2[nt][0], bf2[nt][1]);
        }
    }

    // epilogue
#pragma unroll
    for (int mt = 0; mt < 4; mt++) {
#pragma unroll
        for (int nt = 0; nt < 4; nt++) {
            int c = n0 + wn*32 + nt*8 + kc*2;
            float bx = 0.f, by = 0.f;
            if (BIAS) { bx = bias[c]; by = bias[c+1]; }
#pragma unroll
            for (int half = 0; half < 2; half++) {
                int r = m0 + wm*64 + mt*16 + r0 + half*8;
                float vx = acc[mt][nt][half*2]   + bx;
                float vy = acc[mt][nt][half*2+1] + by;
                if (RELU) { vx = fmaxf(vx, 0.f); vy = fmaxf(vy, 0.f); }
                if (ADD_RES) {
                    float2 rr = *(const float2*)(Rm + (long)r*N + c);
                    vx += rr.x; vy += rr.y;
                }
                if (CVT_OUT) { vx = f2tff(vx); vy = f2tff(vy); }
                if (OUT_F16) {
                    hf* dst = (hf*)C + (long)r*N + c;
                    *(__half2*)dst = h2(vx, vy);
                } else if (OUT_HEADT) {
                    int b = r >> 11, s = r & (S_-1);
                    int h = c >> 6,  d = c & (DK_-1);
                    if (z == 2) {   // V: store [B,H,DK,S]
                        float* dst = (float*)C + (((long)(b*H_ + h)*DK_ + d)*S_ + s);
                        dst[0]  = vx;
                        dst[S_] = vy;
                    } else {
                        *(float2*)((float*)C + (((long)(b*H_ + h)*S_ + s)*DK_ + d)) =
                            make_float2(vx, vy);
                    }
                } else {
                    *(float2*)((float*)C + (long)r*N + c) = make_float2(vx, vy);
                }
            }
        }
    }
}

// ---------------------------------------------------------------------------
// Flash attention, tf32 mma + ldmatrix, single-barrier cp.async, 2 CTA/SM.
// Q,K: [B,H,S,DK] fp32 (tf32-rounded); V: [B,H,DK,S]. Output: flat [M][E] fp16.
// ---------------------------------------------------------------------------
#define KSTR 68
#define VTSTR 68
#define PSTR 68
#define KBUF (64*KSTR)
#define VBUF (64*VTSTR)
#define FLASH_SMEM (((KBUF+VBUF)*2 + 128*PSTR) * 4)   // 104448 B

__global__ __launch_bounds__(256, 2)
void flash_cp(const float* __restrict__ Q, const float* __restrict__ K,
              const float* __restrict__ V, hf* __restrict__ O)
{
    extern __shared__ float sm[];
    float* Ksb[2] = { sm,                      sm + KBUF + VBUF };
    float* Vsb[2] = { sm + KBUF,               sm + 2*KBUF + VBUF };
    float* Psh    = sm + 2*(KBUF + VBUF);      // [128][PSTR]

    int tid  = threadIdx.x;
    int lane = tid & 31;
    int w    = tid >> 5;
    int bh = blockIdx.y;
    int q0 = blockIdx.x * 128;
    int r0 = lane >> 2;
    int kc = lane & 3;
    int mrow = lane & 7, msel = lane >> 3;

    auto copyKV = [&](int k0, float* ks, float* vs) {
        const float* Kb = K + ((long)bh*S_ + k0)*DK_;
        const float* Vb = V + (long)bh*DK_*S_ + k0;
#pragma unroll
        for (int t = 0; t < 4; t++) {
            int idx = tid + t*256;
            int r = idx >> 4;
            int c = (idx & 15) * 4;
            cpa16(ks + r*KSTR  + c, Kb + r*DK_ + c);
            cpa16(vs + r*VTSTR + c, Vb + (long)r*S_ + c);
        }
    };

    // persistent Q fragments (pre-rounded; *0.125 exact)
    unsigned qa[8][4];
    const float* qbase = Q + ((long)bh*S_ + q0 + w*16)*DK_;
#pragma unroll
    for (int kt = 0; kt < 8; kt++) {
        qa[kt][0] = __float_as_uint(qbase[(r0    )*DK_ + kt*8 + kc    ] * 0.125f);
        qa[kt][1] = __float_as_uint(qbase[(r0 + 8)*DK_ + kt*8 + kc    ] * 0.125f);
        qa[kt][2] = __float_as_uint(qbase[(r0    )*DK_ + kt*8 + kc + 4] * 0.125f);
        qa[kt][3] = __float_as_uint(qbase[(r0 + 8)*DK_ + kt*8 + kc + 4] * 0.125f);
    }

    float o[8][4];
#pragma unroll
    for (int nt = 0; nt < 8; nt++)
#pragma unroll
        for (int q = 0; q < 4; q++) o[nt][q] = 0.f;
    float m0 = -1e30f, m1 = -1e30f, l0 = 0.f, l1 = 0.f;

    unsigned p_base = (unsigned)__cvta_generic_to_shared(Psh);
    unsigned poff = p_base + 4u*((w*16 + mrow + (msel&1)*8)*PSTR + (msel>>1)*4);

    const int niter = S_ / 64;
    copyKV(0, Ksb[0], Vsb[0]); cp_commit();

    for (int it = 0; it < niter; it++) {
        cp_wait0();
        __syncthreads();
        if (it + 1 < niter) {
            copyKV((it+1)*64, Ksb[(it+1)&1], Vsb[(it+1)&1]);
            cp_commit();
        }
        unsigned ks_b = (unsigned)__cvta_generic_to_shared(Ksb[it&1]);
        unsigned vs_b = (unsigned)__cvta_generic_to_shared(Vsb[it&1]);
        unsigned koff = ks_b + 4u*((mrow + (msel>>1)*8)*KSTR  + (msel&1)*4);
        unsigned voff = vs_b + 4u*((mrow + (msel>>1)*8)*VTSTR + (msel&1)*4);

        // S = Q K^T (warp: 16x64)
        float sc[8][4];
#pragma unroll
        for (int nt = 0; nt < 8; nt++)
#pragma unroll
            for (int q = 0; q < 4; q++) sc[nt][q] = 0.f;

#pragma unroll
        for (int kt = 0; kt < 8; kt++) {
            unsigned b0[8], b1[8];
#pragma unroll
            for (int ntp = 0; ntp < 8; ntp += 2)
                ldsm4(b0[ntp], b1[ntp], b0[ntp+1], b1[ntp+1],
                      koff + 4u*(ntp*8*KSTR + kt*8));
#pragma unroll
            for (int nt = 0; nt < 8; nt++)
                mma1688(sc[nt], qa[kt], b0[nt], b1[nt]);
        }

        // online softmax (rows r0 and r0+8)
        float tm0 = -1e30f, tm1 = -1e30f;
#pragma unroll
        for (int nt = 0; nt < 8; nt++) {
            tm0 = fmaxf(tm0, fmaxf(sc[nt][0], sc[nt][1]));
            tm1 = fmaxf(tm1, fmaxf(sc[nt][2], sc[nt][3]));
        }
        tm0 = fmaxf(tm0, __shfl_xor_sync(0xffffffffu, tm0, 1));
        tm0 = fmaxf(tm0, __shfl_xor_sync(0xffffffffu, tm0, 2));
        tm1 = fmaxf(tm1, __shfl_xor_sync(0xffffffffu, tm1, 1));
        tm1 = fmaxf(tm1, __shfl_xor_sync(0xffffffffu, tm1, 2));

        float mn0 = fmaxf(m0, tm0), mn1 = fmaxf(m1, tm1);
        float c0 = __expf(m0 - mn0), c1 = __expf(m1 - mn1);
        l0 *= c0; l1 *= c1;

        float s0 = 0.f, s1 = 0.f;
#pragma unroll
        for (int nt = 0; nt < 8; nt++) {
            float p0 = __expf(sc[nt][0] - mn0);
            float p1 = __expf(sc[nt][1] - mn0);
            float p2 = __expf(sc[nt][2] - mn1);
            float p3 = __expf(sc[nt][3] - mn1);
            s0 += p0 + p1; s1 += p2 + p3;
            o[nt][0] *= c0; o[nt][1] *= c0; o[nt][2] *= c1; o[nt][3] *= c1;
            *(float2*)&Psh[(w*16 + r0    )*PSTR + nt*8 + kc*2] =
                make_float2(f2tff(p0), f2tff(p1));
            *(float2*)&Psh[(w*16 + r0 + 8)*PSTR + nt*8 + kc*2] =
                make_float2(f2tff(p2), f2tff(p3));
        }
        s0 += __shfl_xor_sync(0xffffffffu, s0, 1);
        s0 += __shfl_xor_sync(0xffffffffu, s0, 2);
        s1 += __shfl_xor_sync(0xffffffffu, s1, 1);
        s1 += __shfl_xor_sync(0xffffffffu, s1, 2);
        l0 += s0; l1 += s1;
        m0 = mn0; m1 = mn1;

        __syncwarp();   // P stripe is warp-private

        // O += P V
#pragma unroll
        for (int kt = 0; kt < 8; kt++) {
            unsigned pa[4];
            ldsm4(pa[0], pa[1], pa[2], pa[3], poff + 4u*(kt*8));
            unsigned v0[8], v1[8];
#pragma unroll
            for (int ntp = 0; ntp < 8; ntp += 2)
                ldsm4(v0[ntp], v1[ntp], v0[ntp+1], v1[ntp+1],
                      voff + 4u*(ntp*8*VTSTR + kt*8));
#pragma unroll
            for (int nt = 0; nt < 8; nt++)
                mma1688(o[nt], pa, v0[nt], v1[nt]);
        }
    }

    // write flat [M][E] fp16 (row = b*S+s, col = h*64+d)
    float i0 = 1.f / l0, i1 = 1.f / l1;
    int bb = bh >> 3, hh = bh & 7;
    hf* ob = O + ((long)bb*S_ + q0 + w*16)*E_ + hh*64;
#pragma unroll
    for (int nt = 0; nt < 8; nt++) {
        *(__half2*)&ob[(long)(r0    )*E_ + nt*8 + kc*2] = h2(o[nt][0]*i0, o[nt][1]*i0);
        *(__half2*)&ob[(long)(r0 + 8)*E_ + nt*8 + kc*2] = h2(o[nt][2]*i1, o[nt][3]*i1);
    }
}

// ---------------------------------------------------------------------------
// out = LayerNorm(in) * g + b  — dual output (fp32 + fp16)
// ---------------------------------------------------------------------------
__global__ __launch_bounds__(128)
void ln_dual_kernel(const float* __restrict__ in,
                    const float* __restrict__ g, const float* __restrict__ bta,
                    float* __restrict__ out, hf* __restrict__ outr)
{
    __shared__ float red[4];
    int row = blockIdx.x;
    int tid = threadIdx.x;
    int e = tid * 4;
    const float4 xv = *(const float4*)(in + (long)row*E_ + e);
    float t0 = xv.x, t1 = xv.y, t2 = xv.z, t3 = xv.w;

    float s = t0 + t1 + t2 + t3;
#pragma unroll
    for (int off = 16; off; off >>= 1) s += __shfl_xor_sync(0xffffffffu, s, off);
    if ((tid & 31) == 0) red[tid >> 5] = s;
    __syncthreads();
    float mean = (red[0]+red[1]+red[2]+red[3]) * (1.f/E_);
    __syncthreads();

    float d0 = t0-mean, d1 = t1-mean, d2 = t2-mean, d3 = t3-mean;
    float vs = d0*d0 + d1*d1 + d2*d2 + d3*d3;
#pragma unroll
    for (int off = 16; off; off >>= 1) vs += __shfl_xor_sync(0xffffffffu, vs, off);
    if ((tid & 31) == 0) red[tid >> 5] = vs;
    __syncthreads();
    float var = (red[0]+red[1]+red[2]+red[3]) * (1.f/E_);
    float rstd = rsqrtf(var + 1e-5f);

    float4 gg = *(const float4*)(g + e);
    float4 bb = *(const float4*)(bta + e);
    float v0 = d0*rstd*gg.x + bb.x, v1 = d1*rstd*gg.y + bb.y;
    float v2 = d2*rstd*gg.z + bb.z, v3 = d3*rstd*gg.w + bb.w;
    *(float4*)(out + (long)row*E_ + e) = make_float4(v0, v1, v2, v3);
    hf* ro = outr + (long)row*E_ + e;
    *(__half2*)(ro)     = h2(v0, v1);
    *(__half2*)(ro + 2) = h2(v2, v3);
}

// ---------------------------------------------------------------------------
// Mean over S (two-stage) + classifier
// ---------------------------------------------------------------------------
__global__ void mean_part_kernel(const float* __restrict__ x, float* __restrict__ part)
{
    int idx = blockIdx.x*256 + threadIdx.x;
    int b = idx >> 9;
    int e = idx & (E_-1);
    int c = blockIdx.y;
    const float* p = x + ((long)b*S_ + c*128)*E_ + e;
    float s = 0.f;
#pragma unroll 8
    for (int i = 0; i < 128; i++) s += p[(long)i*E_];
    part[c*(B_*E_) + idx] = s;
}

__global__ void mean_final_kernel(const float* __restrict__ part, float* __restrict__ mean)
{
    int idx = blockIdx.x*256 + threadIdx.x;
    float s = 0.f;
#pragma unroll
    for (int c = 0; c < 16; c++) s += part[c*(B_*E_) + idx];
    mean[idx] = s * (1.f/(float)S_);
}

__global__ __launch_bounds__(128)
void classify_kernel(const float* __restrict__ mean, const float* __restrict__ w,
                     const float* __restrict__ bias, float* __restrict__ out)
{
    __shared__ float red[4];
    int b = blockIdx.x >> 2;
    int c = blockIdx.x & 3;
    int tid = threadIdx.x;
    float s = 0.f;
    for (int e = tid; e < E_; e += 128) s += mean[b*E_ + e] * w[e*C_ + c];
#pragma unroll
    for (int off = 16; off; off >>= 1) s += __shfl_xor_sync(0xffffffffu, s, off);
    if ((tid & 31) == 0) red[tid >> 5] = s;
    __syncthreads();
    if (tid == 0) out[b*C_ + c] = red[0]+red[1]+red[2]+red[3] + bias[c];
}

// ---------------------------------------------------------------------------
// Launch
// ---------------------------------------------------------------------------
extern "C" void kernel_launch(void* const* d_in, const int* in_sizes, int n_in,
                              void* d_out, int out_size)
{
    const int*   tokens = (const int*)  d_in[0];
    const float* emb    = (const float*)d_in[1];
    const float* Wq     = (const float*)d_in[2];
    const float* Wk     = (const float*)d_in[3];
    const float* Wv     = (const float*)d_in[4];
    const float* Wo     = (const float*)d_in[5];
    const float* qh_w   = (const float*)d_in[6];
    const float* qh_b   = (const float*)d_in[7];
    const float* kh_w   = (const float*)d_in[8];
    const float* kh_b   = (const float*)d_in[9];
    const float* vh_w   = (const float*)d_in[10];
    const float* vh_b   = (const float*)d_in[11];
    const float* ln1_g  = (const float*)d_in[12];
    const float* ln1_b  = (const float*)d_in[13];
    const float* ln2_g  = (const float*)d_in[14];
    const float* ln2_b  = (const float*)d_in[15];
    const float* f_w1   = (const float*)d_in[16];
    const float* f_b1   = (const float*)d_in[17];
    const float* f_w2   = (const float*)d_in[18];
    const float* f_b2   = (const float*)d_in[19];
    const float* cls_w  = (const float*)d_in[20];
    const float* cls_b  = (const float*)d_in[21];

    float *x,*q,*k,*v,*p,*y,*part,*mean,*wc,*beff;
    hf *xr,*yr,*ao,*ffn,*weff,*w1t,*w2t,*wot;
    cudaGetSymbolAddress((void**)&x,    g_x);
    cudaGetSymbolAddress((void**)&xr,   g_xr);
    cudaGetSymbolAddress((void**)&q,    g_q);
    cudaGetSymbolAddress((void**)&k,    g_k);
    cudaGetSymbolAddress((void**)&v,    g_v);
    cudaGetSymbolAddress((void**)&ao,   g_ao);
    cudaGetSymbolAddress((void**)&p,    g_p);
    cudaGetSymbolAddress((void**)&y,    g_y);
    cudaGetSymbolAddress((void**)&yr,   g_yr);
    cudaGetSymbolAddress((void**)&ffn,  g_ffn);
    cudaGetSymbolAddress((void**)&part, g_part);
    cudaGetSymbolAddress((void**)&mean, g_mean);
    cudaGetSymbolAddress((void**)&wc,   g_wc);
    cudaGetSymbolAddress((void**)&weff, g_weff);
    cudaGetSymbolAddress((void**)&beff, g_beff);
    cudaGetSymbolAddress((void**)&w1t,  g_w1t);
    cudaGetSymbolAddress((void**)&w2t,  g_w2t);
    cudaGetSymbolAddress((void**)&wot,  g_wot);

    cudaFuncSetAttribute((const void*)flash_cp,
                         cudaFuncAttributeMaxDynamicSharedMemorySize, FLASH_SMEM);

    const int M = B_*S_;               // 8192
    const long ESQ = (long)E_*E_;
    dim3 gQKV(E_/128, M/128, 3);
    dim3 gProj(E_/128, M/128, 1);
    dim3 gFfn1(FF_/128, M/128, 1);
    dim3 gFlash(S_/128, B_*H_);

    // Precompute
    embed_kernel<<<M, 128>>>(tokens, emb, x, xr);
    qcombine_kernel<<<3*NB_*H_, 256>>>(qh_w, qh_b, kh_w, kh_b, vh_w, vh_b, wc, beff);
    qweff_kernel<<<dim3(8, H_, 3*NB_), 256>>>(Wq, Wk, Wv, wc, weff);
    tr_f16_kernel<<<dim3(E_/32,  FF_/32, NB_), dim3(32,8)>>>(f_w1, w1t, E_,  FF_);
    tr_f16_kernel<<<dim3(FF_/32, E_/32,  NB_), dim3(32,8)>>>(f_w2, w2t, FF_, E_);
    tr_f16_kernel<<<dim3(E_/32,  E_/32,  NB_), dim3(32,8)>>>(Wo,   wot, E_,  E_);

    for (int i = 0; i < NB_; i++) {
        const hf* Wo_i = wot + (long)i*ESQ;

        // fused QKV projection (quantum folded); fp32 tf32-rounded out; V [B,H,DK,S]
        sgemm_hf<true,true,false,true,false,false><<<gQKV, 256, GEMM_SMEM>>>(
            xr,
            weff + (0*NB_ + i)*ESQ, weff + (1*NB_ + i)*ESQ, weff + (2*NB_ + i)*ESQ,
            beff + (0*NB_ + i)*E_,  beff + (1*NB_ + i)*E_,  beff + (2*NB_ + i)*E_,
            q, k, v, nullptr, M, E_, E_);

        // attention (writes ao flat [M][E] fp16)
        flash_cp<<<gFlash, 256, FLASH_SMEM>>>(q, k, v, ao);

        // output projection + residual(x) fused; then LN1
        sgemm_hf<false,false,false,false,false,true><<<gProj, 256, GEMM_SMEM>>>(
            ao, Wo_i, Wo_i, Wo_i, nullptr, nullptr, nullptr, p, p, p, x, M, E_, E_);
        ln_dual_kernel<<<M, 128>>>(p, ln1_g + i*E_, ln1_b + i*E_, y, yr);

        // FFN (hidden fp16) + residual(y) fused + LN2
        sgemm_hf<false,true,true,false,true,false><<<gFfn1, 256, GEMM_SMEM>>>(
            yr, w1t + (long)i*E_*FF_, w1t + (long)i*E_*FF_, w1t + (long)i*E_*FF_,
            f_b1 + i*FF_, f_b1 + i*FF_, f_b1 + i*FF_,
            ffn, ffn, ffn, nullptr, M, FF_, E_);
        sgemm_hf<false,true,false,false,false,true><<<gProj, 256, GEMM_SMEM>>>(
            ffn, w2t + (long)i*FF_*E_, w2t + (long)i*FF_*E_, w2t + (long)i*FF_*E_,
            f_b2 + i*E_, f_b2 + i*E_, f_b2 + i*E_,
            p, p, p, y, M, E_, FF_);
        ln_dual_kernel<<<M, 128>>>(p, ln2_g + i*E_, ln2_b + i*E_, x, xr);
    }

    mean_part_kernel<<<dim3((B_*E_)/256, 16), 256>>>(x, part);
    mean_final_kernel<<<(B_*E_)/256, 256>>>(part, mean);
    classify_kernel<<<B_*C_, 128>>>(mean, cls_w, cls_b, (float*)d_out);
}